// round 2
// baseline (speedup 1.0000x reference)
#include <cuda_runtime.h>
#include <math.h>

#define B_    4096
#define S_    30
#define FIN_  80
#define D_    320
#define H_    5
#define DH_   64
#define L_    4
#define DFF_  1280
#define NTOK  (B_ * S_)

#define FLAG_RELU 1
#define FLAG_PE   2

// ---------------- scratch (device globals; no allocations allowed) ----------
__device__ float g_h[NTOK * D_];
__device__ float g_heads[NTOK * D_];
__device__ float g_tmp[NTOK * D_];
__device__ float g_ffn[NTOK * DFF_];

// ---------------- generic tiled SGEMM: C = A(MxK) @ B(KxN) + bias ----------
// Block computes 64x64 tile; 256 threads, 4x4 per thread. All problem dims
// divide the tile sizes exactly, so no bounds checks anywhere.
__global__ __launch_bounds__(256) void gemm64(
    const float* __restrict__ A, int lda,
    const float* __restrict__ Bw, int ldb,
    const float* __restrict__ bias,
    float* __restrict__ C, int ldc,
    int K, int flags)
{
    __shared__ __align__(16) float As[16][65];  // pad: conflict-free transpose store
    __shared__ __align__(16) float Bs[16][64];

    int tid = threadIdx.x;
    int ty = tid >> 4, tx = tid & 15;
    size_t rowBase = (size_t)blockIdx.y * 64;
    int colBase = blockIdx.x * 64;
    const float* Ab = A + rowBase * (size_t)lda;
    const float* Bb = Bw + colBase;

    float acc[4][4];
#pragma unroll
    for (int i = 0; i < 4; i++)
#pragma unroll
        for (int j = 0; j < 4; j++) acc[i][j] = 0.f;

    for (int k0 = 0; k0 < K; k0 += 16) {
#pragma unroll
        for (int i = 0; i < 4; i++) {           // A tile 64x16 -> As[c][r]
            int e = tid + i * 256;
            int r = e >> 4, c = e & 15;
            As[c][r] = Ab[(size_t)r * lda + (k0 + c)];
        }
#pragma unroll
        for (int i = 0; i < 4; i++) {           // B tile 16x64
            int e = tid + i * 256;
            int r = e >> 6, c = e & 63;
            Bs[r][c] = Bb[(size_t)(k0 + r) * ldb + c];
        }
        __syncthreads();
#pragma unroll
        for (int k = 0; k < 16; k++) {
            float a0 = As[k][ty * 4 + 0];
            float a1 = As[k][ty * 4 + 1];
            float a2 = As[k][ty * 4 + 2];
            float a3 = As[k][ty * 4 + 3];
            float4 b = *(const float4*)&Bs[k][tx * 4];
            acc[0][0] += a0 * b.x; acc[0][1] += a0 * b.y; acc[0][2] += a0 * b.z; acc[0][3] += a0 * b.w;
            acc[1][0] += a1 * b.x; acc[1][1] += a1 * b.y; acc[1][2] += a1 * b.z; acc[1][3] += a1 * b.w;
            acc[2][0] += a2 * b.x; acc[2][1] += a2 * b.y; acc[2][2] += a2 * b.z; acc[2][3] += a2 * b.w;
            acc[3][0] += a3 * b.x; acc[3][1] += a3 * b.y; acc[3][2] += a3 * b.z; acc[3][3] += a3 * b.w;
        }
        __syncthreads();
    }

    int row0 = (int)rowBase + ty * 4;
    int col0 = colBase + tx * 4;
#pragma unroll
    for (int i = 0; i < 4; i++) {
        int row = row0 + i;
#pragma unroll
        for (int j = 0; j < 4; j++) {
            int col = col0 + j;
            float v = acc[i][j] + bias[col];
            if (flags & FLAG_PE) {
                int s = row % S_;
                int half = col >> 1;
                float div = expf((float)(2 * half) * (-9.210340371976184f / (float)D_));
                float arg = (float)s * div;
                v += (col & 1) ? cosf(arg) : sinf(arg);
            }
            if (flags & FLAG_RELU) v = fmaxf(v, 0.f);
            C[(size_t)row * ldc + col] = v;
        }
    }
}

// ---------------- fused QKV projection + attention: block per (b, h) -------
// Computes q,k,v from the h-state slice in shared memory (block-diagonal
// per-head weights), then scores/softmax/AV, writes head outputs.
__global__ __launch_bounds__(256) void attn_fused(
    const float* __restrict__ hsrc,
    const float* __restrict__ Wq, const float* __restrict__ bq,
    const float* __restrict__ Wk, const float* __restrict__ bk,
    const float* __restrict__ Wv, const float* __restrict__ bv,
    int l, float* __restrict__ heads)
{
    __shared__ float sh[S_][DH_ + 1];
    __shared__ float sq[S_][DH_ + 1];
    __shared__ float sk[S_][DH_ + 1];
    __shared__ float sv[S_][DH_ + 1];
    __shared__ float sc[S_][S_ + 1];

    int bh = blockIdx.x;
    int b = bh / H_, h = bh % H_;
    size_t base = ((size_t)b * S_) * D_ + (size_t)h * DH_;
    int tid = threadIdx.x;

    for (int e = tid; e < S_ * DH_; e += 256) {
        int s = e >> 6, d = e & 63;
        sh[s][d] = hsrc[base + (size_t)s * D_ + d];
    }
    __syncthreads();

    size_t woff = ((size_t)l * H_ + h) * DH_ * DH_;
    size_t boff = ((size_t)l * H_ + h) * DH_;
    const float* Wqh = Wq + woff;
    const float* Wkh = Wk + woff;
    const float* Wvh = Wv + woff;

    // q,k,v projections: 3*S_ rows of DH_ outputs; thread-group of 64 per row
    {
        int e = tid & 63;
        for (int r = tid >> 6; r < 3 * S_; r += 4) {
            int m = r / S_, s = r % S_;
            const float* Wm = (m == 0) ? Wqh : (m == 1) ? Wkh : Wvh;
            const float* bm = (m == 0) ? (bq + boff) : (m == 1) ? (bk + boff) : (bv + boff);
            float acc = bm[e];
#pragma unroll 16
            for (int d = 0; d < DH_; d++) acc += sh[s][d] * Wm[d * DH_ + e];
            if (m == 0) sq[s][e] = acc;
            else if (m == 1) sk[s][e] = acc;
            else sv[s][e] = acc;
        }
    }
    __syncthreads();

    // scores
    for (int e = tid; e < S_ * S_; e += 256) {
        int i = e / S_, j = e % S_;
        float acc = 0.f;
#pragma unroll
        for (int d = 0; d < DH_; d++) acc += sq[i][d] * sk[j][d];
        sc[i][j] = acc * 0.125f;  // 1/sqrt(64)
    }
    __syncthreads();

    // softmax rows
    if (tid < S_) {
        float m = -1e30f;
        for (int j = 0; j < S_; j++) m = fmaxf(m, sc[tid][j]);
        float sum = 0.f;
        for (int j = 0; j < S_; j++) {
            float e2 = expf(sc[tid][j] - m);
            sc[tid][j] = e2;
            sum += e2;
        }
        float inv = 1.f / sum;
        for (int j = 0; j < S_; j++) sc[tid][j] *= inv;
    }
    __syncthreads();

    // A @ V
    for (int e = tid; e < S_ * DH_; e += 256) {
        int s = e >> 6, d = e & 63;
        float acc = 0.f;
#pragma unroll
        for (int j = 0; j < S_; j++) acc += sc[s][j] * sv[j][d];
        heads[base + (size_t)s * D_ + d] = acc;
    }
}

// ---------------- residual add + LayerNorm (block per token, 320 threads) --
__global__ __launch_bounds__(320) void add_ln_kernel(
    float* __restrict__ hb, const float* __restrict__ add,
    const float* __restrict__ gamma, const float* __restrict__ beta)
{
    __shared__ float red[10];
    __shared__ float s_mean, s_rstd;
    int t = threadIdx.x;
    size_t off = (size_t)blockIdx.x * D_ + t;
    float v = hb[off] + add[off];

    float x = v;
#pragma unroll
    for (int o = 16; o; o >>= 1) x += __shfl_down_sync(0xffffffffu, x, o);
    if ((t & 31) == 0) red[t >> 5] = x;
    __syncthreads();
    if (t == 0) {
        float tot = 0.f;
        for (int i = 0; i < 10; i++) tot += red[i];
        s_mean = tot / (float)D_;
    }
    __syncthreads();

    float d = v - s_mean;
    float sq = d * d;
#pragma unroll
    for (int o = 16; o; o >>= 1) sq += __shfl_down_sync(0xffffffffu, sq, o);
    if ((t & 31) == 0) red[t >> 5] = sq;
    __syncthreads();
    if (t == 0) {
        float tot = 0.f;
        for (int i = 0; i < 10; i++) tot += red[i];
        s_rstd = rsqrtf(tot / (float)D_ + 1e-5f);
    }
    __syncthreads();

    hb[off] = d * s_rstd * gamma[t] + beta[t];
}

// ---------------- attention pooling + classifier (block per batch row) -----
__global__ __launch_bounds__(320) void pool_cls_kernel(
    const float* __restrict__ hb,
    const float* __restrict__ pool_W, const float* __restrict__ pool_b,
    const float* __restrict__ W1, const float* __restrict__ b1,
    const float* __restrict__ W2, const float* __restrict__ b2,
    float* __restrict__ out)
{
    __shared__ float sscore[S_];
    __shared__ float sz[D_];
    __shared__ float shid[D_ / 2];
    __shared__ float sred[10];

    int b = blockIdx.x;
    int t = threadIdx.x, warp = t >> 5, lane = t & 31;
    const float* hrow = hb + (size_t)b * S_ * D_;

    for (int s = warp; s < S_; s += 10) {
        float acc = 0.f;
        for (int d = lane; d < D_; d += 32) acc += hrow[s * D_ + d] * pool_W[d];
#pragma unroll
        for (int o = 16; o; o >>= 1) acc += __shfl_down_sync(0xffffffffu, acc, o);
        if (lane == 0) sscore[s] = acc + pool_b[0];
    }
    __syncthreads();

    if (t == 0) {
        float m = -1e30f;
        for (int s = 0; s < S_; s++) m = fmaxf(m, sscore[s]);
        float sum = 0.f;
        for (int s = 0; s < S_; s++) {
            float e = expf(sscore[s] - m);
            sscore[s] = e;
            sum += e;
        }
        float inv = 1.f / sum;
        for (int s = 0; s < S_; s++) sscore[s] *= inv;
    }
    __syncthreads();

    {
        float acc = 0.f;
        for (int s = 0; s < S_; s++) acc += sscore[s] * hrow[s * D_ + t];
        sz[t] = acc;
    }
    __syncthreads();

    if (t < D_ / 2) {
        float acc = b1[t];
        for (int d = 0; d < D_; d++) acc += sz[d] * W1[d * (D_ / 2) + t];
        shid[t] = fmaxf(acc, 0.f);
    }
    __syncthreads();

    float p = (t < D_ / 2) ? shid[t] * W2[t] : 0.f;
#pragma unroll
    for (int o = 16; o; o >>= 1) p += __shfl_down_sync(0xffffffffu, p, o);
    if (lane == 0) sred[warp] = p;
    __syncthreads();
    if (t == 0) {
        float tot = 0.f;
        for (int i = 0; i < 10; i++) tot += sred[i];
        float logit = tot + b2[0];
        out[b] = logit;                           // logits
        out[B_ + b] = 1.f / (1.f + expf(-logit)); // probs
    }
}

// ---------------- host launcher -------------------------------------------
extern "C" void kernel_launch(void* const* d_in, const int* in_sizes, int n_in,
                              void* d_out, int out_size)
{
    const float* x      = (const float*)d_in[0];
    const float* in_W   = (const float*)d_in[1];
    const float* in_b   = (const float*)d_in[2];
    const float* Wq     = (const float*)d_in[3];
    const float* bq     = (const float*)d_in[4];
    const float* Wk     = (const float*)d_in[5];
    const float* bk     = (const float*)d_in[6];
    const float* Wv     = (const float*)d_in[7];
    const float* bv     = (const float*)d_in[8];
    const float* Wo     = (const float*)d_in[9];
    const float* bo     = (const float*)d_in[10];
    const float* ln1_g  = (const float*)d_in[11];
    const float* ln1_b  = (const float*)d_in[12];
    const float* W1     = (const float*)d_in[13];
    const float* b1     = (const float*)d_in[14];
    const float* W2     = (const float*)d_in[15];
    const float* b2     = (const float*)d_in[16];
    const float* ln2_g  = (const float*)d_in[17];
    const float* ln2_b  = (const float*)d_in[18];
    const float* pool_W = (const float*)d_in[19];
    const float* pool_b = (const float*)d_in[20];
    const float* cW1    = (const float*)d_in[21];
    const float* cb1    = (const float*)d_in[22];
    const float* cW2    = (const float*)d_in[23];
    const float* cb2    = (const float*)d_in[24];

    float *ph, *pheads, *ptmp, *pffn;
    cudaGetSymbolAddress((void**)&ph, g_h);
    cudaGetSymbolAddress((void**)&pheads, g_heads);
    cudaGetSymbolAddress((void**)&ptmp, g_tmp);
    cudaGetSymbolAddress((void**)&pffn, g_ffn);

    const dim3 gridD(D_ / 64, NTOK / 64);      // N=320
    const dim3 gridF(DFF_ / 64, NTOK / 64);    // N=1280

    // input projection + bias + positional encoding
    gemm64<<<gridD, 256>>>(x, FIN_, in_W, D_, in_b, ph, D_, FIN_, FLAG_PE);

    for (int l = 0; l < L_; l++) {
        // fused per-head QKV projection + attention
        attn_fused<<<B_ * H_, 256>>>(ph, Wq, bq, Wk, bk, Wv, bv, l, pheads);
        // output projection
        gemm64<<<gridD, 256>>>(pheads, D_, Wo + (size_t)l * D_ * D_, D_,
                               bo + l * D_, ptmp, D_, D_, 0);
        add_ln_kernel<<<NTOK, 320>>>(ph, ptmp, ln1_g + l * D_, ln1_b + l * D_);
        // FFN
        gemm64<<<gridF, 256>>>(ph, D_, W1 + (size_t)l * D_ * DFF_, DFF_,
                               b1 + l * DFF_, pffn, DFF_, D_, FLAG_RELU);
        gemm64<<<gridD, 256>>>(pffn, DFF_, W2 + (size_t)l * DFF_ * D_, D_,
                               b2 + l * D_, ptmp, D_, DFF_, 0);
        add_ln_kernel<<<NTOK, 320>>>(ph, ptmp, ln2_g + l * D_, ln2_b + l * D_);
    }

    pool_cls_kernel<<<B_, 320>>>(ph, pool_W, pool_b, cW1, cb1, cW2, cb2,
                                 (float*)d_out);
}

// round 4
// speedup vs baseline: 1.1255x; 1.1255x over previous
#include <cuda_runtime.h>
#include <math.h>

#define B_    4096
#define S_    30
#define FIN_  80
#define D_    320
#define H_    5
#define DH_   64
#define L_    4
#define DFF_  1280
#define NTOK  (B_ * S_)

#define FLAG_RELU 1
#define FLAG_PE   2

// ---------------- scratch (device globals; no allocations allowed) ----------
__device__ float g_h[NTOK * D_];
__device__ float g_heads[NTOK * D_];
__device__ float g_tmp[NTOK * D_];
__device__ float g_ffn[NTOK * DFF_];

// ======================================================================
// 3xTF32 tensor-core GEMM: C = A(MxK) @ B(KxN) + bias [+relu]
// BM=128, BN=64, BK=16. 256 threads = 8 warps in 4x2, warp tile 32x32.
// mma.sync.m16n8k8.tf32; A,B split hi/lo for ~fp32 accuracy.
// A smem [128][20] (stride 20 -> conflict-free frag loads)
// B smem [16][72]  (stride 72 -> conflict-free frag loads)
// Requires: M%128==0, N%64==0, K%16==0.
// ======================================================================
__device__ __forceinline__ unsigned f2tf32(float v) {
    unsigned r;
    asm("cvt.rna.tf32.f32 %0, %1;\n" : "=r"(r) : "f"(v));
    return r;
}

__device__ __forceinline__ void mma_tf32(float* c, const unsigned* a, const unsigned* b) {
    asm volatile(
        "mma.sync.aligned.m16n8k8.row.col.f32.tf32.tf32.f32 "
        "{%0,%1,%2,%3}, {%4,%5,%6,%7}, {%8,%9}, {%0,%1,%2,%3};\n"
        : "+f"(c[0]), "+f"(c[1]), "+f"(c[2]), "+f"(c[3])
        : "r"(a[0]), "r"(a[1]), "r"(a[2]), "r"(a[3]), "r"(b[0]), "r"(b[1]));
}

__global__ __launch_bounds__(256, 2) void gemm_tf32(
    const float* __restrict__ A, int lda,
    const float* __restrict__ Bw, int ldb,
    const float* __restrict__ bias,
    float* __restrict__ C, int ldc,
    int K, int flags)
{
    __shared__ float sAh[128][20], sAl[128][20];
    __shared__ float sBh[16][72],  sBl[16][72];

    const int tid  = threadIdx.x;
    const int lane = tid & 31;
    const int w    = tid >> 5;
    const int g    = lane >> 2;      // group id 0..7
    const int t4   = lane & 3;       // thread-in-group
    const int wm   = (w >> 1) * 32;  // warp row offset (4 warps)
    const int wn   = (w & 1) * 32;   // warp col offset (2 warps)

    const size_t rowBase = (size_t)blockIdx.y * 128;
    const int    colBase = blockIdx.x * 64;

    // gmem staging indices
    const int arow = tid >> 2;         // A: thread t covers rows t>>2 and (t+256)>>2
    const int akq  = tid & 3;          //    float4 index within 16-wide k slab
    const int brow = tid >> 4;         // B: 16 k-rows
    const int bc4  = (tid & 15) * 4;   //    4 cols per thread

    const float* Ag = A + rowBase * (size_t)lda;
    const float* Bg = Bw + colBase;

    float4 rA0, rA1, rB;
    rA0 = *(const float4*)&Ag[(size_t)arow * lda + akq * 4];
    rA1 = *(const float4*)&Ag[(size_t)(arow + 64) * lda + akq * 4];
    rB  = *(const float4*)&Bg[(size_t)brow * ldb + bc4];

    float acc[2][4][4];
#pragma unroll
    for (int mt = 0; mt < 2; mt++)
#pragma unroll
        for (int nt = 0; nt < 4; nt++)
#pragma unroll
            for (int i = 0; i < 4; i++) acc[mt][nt][i] = 0.f;

    for (int k0 = 0; k0 < K; k0 += 16) {
        // stage current tile to smem with hi/lo split
        {
            const float* pv = (const float*)&rA0;
#pragma unroll
            for (int j = 0; j < 4; j++) {
                float v = pv[j];
                unsigned hi = f2tf32(v);
                float lo = v - __uint_as_float(hi);
                sAh[arow][akq * 4 + j] = __uint_as_float(hi);
                sAl[arow][akq * 4 + j] = __uint_as_float(f2tf32(lo));
            }
            pv = (const float*)&rA1;
#pragma unroll
            for (int j = 0; j < 4; j++) {
                float v = pv[j];
                unsigned hi = f2tf32(v);
                float lo = v - __uint_as_float(hi);
                sAh[arow + 64][akq * 4 + j] = __uint_as_float(hi);
                sAl[arow + 64][akq * 4 + j] = __uint_as_float(f2tf32(lo));
            }
            pv = (const float*)&rB;
#pragma unroll
            for (int j = 0; j < 4; j++) {
                float v = pv[j];
                unsigned hi = f2tf32(v);
                float lo = v - __uint_as_float(hi);
                sBh[brow][bc4 + j] = __uint_as_float(hi);
                sBl[brow][bc4 + j] = __uint_as_float(f2tf32(lo));
            }
        }
        __syncthreads();

        // prefetch next tile
        if (k0 + 16 < K) {
            rA0 = *(const float4*)&Ag[(size_t)arow * lda + (k0 + 16) + akq * 4];
            rA1 = *(const float4*)&Ag[(size_t)(arow + 64) * lda + (k0 + 16) + akq * 4];
            rB  = *(const float4*)&Bg[(size_t)(k0 + 16 + brow) * ldb + bc4];
        }

        // two k8 steps
#pragma unroll
        for (int ks = 0; ks < 2; ks++) {
            const int kb = ks * 8;
            unsigned ah[2][4], al[2][4], bh[4][2], bl[4][2];
#pragma unroll
            for (int mt = 0; mt < 2; mt++) {
                int r = wm + mt * 16 + g;
                ah[mt][0] = __float_as_uint(sAh[r][kb + t4]);
                ah[mt][1] = __float_as_uint(sAh[r + 8][kb + t4]);
                ah[mt][2] = __float_as_uint(sAh[r][kb + t4 + 4]);
                ah[mt][3] = __float_as_uint(sAh[r + 8][kb + t4 + 4]);
                al[mt][0] = __float_as_uint(sAl[r][kb + t4]);
                al[mt][1] = __float_as_uint(sAl[r + 8][kb + t4]);
                al[mt][2] = __float_as_uint(sAl[r][kb + t4 + 4]);
                al[mt][3] = __float_as_uint(sAl[r + 8][kb + t4 + 4]);
            }
#pragma unroll
            for (int nt = 0; nt < 4; nt++) {
                int c = wn + nt * 8 + g;
                bh[nt][0] = __float_as_uint(sBh[kb + t4][c]);
                bh[nt][1] = __float_as_uint(sBh[kb + t4 + 4][c]);
                bl[nt][0] = __float_as_uint(sBl[kb + t4][c]);
                bl[nt][1] = __float_as_uint(sBl[kb + t4 + 4][c]);
            }
#pragma unroll
            for (int mt = 0; mt < 2; mt++)
#pragma unroll
                for (int nt = 0; nt < 4; nt++) {
                    mma_tf32(acc[mt][nt], ah[mt], bl[nt]);
                    mma_tf32(acc[mt][nt], al[mt], bh[nt]);
                    mma_tf32(acc[mt][nt], ah[mt], bh[nt]);
                }
        }
        __syncthreads();
    }

    // epilogue: bias [+relu], write fragments as float2
#pragma unroll
    for (int mt = 0; mt < 2; mt++) {
        size_t r0 = rowBase + wm + mt * 16 + g;
#pragma unroll
        for (int nt = 0; nt < 4; nt++) {
            int c = colBase + wn + nt * 8 + t4 * 2;
            float2 bs = *(const float2*)&bias[c];
            float v0 = acc[mt][nt][0] + bs.x;
            float v1 = acc[mt][nt][1] + bs.y;
            float v2 = acc[mt][nt][2] + bs.x;
            float v3 = acc[mt][nt][3] + bs.y;
            if (flags & FLAG_RELU) {
                v0 = fmaxf(v0, 0.f); v1 = fmaxf(v1, 0.f);
                v2 = fmaxf(v2, 0.f); v3 = fmaxf(v3, 0.f);
            }
            *(float2*)&C[r0 * ldc + c]       = make_float2(v0, v1);
            *(float2*)&C[(r0 + 8) * ldc + c] = make_float2(v2, v3);
        }
    }
}

// ---------------- fp32 tiled SGEMM (input projection only; PE epilogue) ----
__global__ __launch_bounds__(256) void gemm64(
    const float* __restrict__ A, int lda,
    const float* __restrict__ Bw, int ldb,
    const float* __restrict__ bias,
    float* __restrict__ C, int ldc,
    int K, int flags)
{
    __shared__ __align__(16) float As[16][65];
    __shared__ __align__(16) float Bs[16][64];

    int tid = threadIdx.x;
    int ty = tid >> 4, tx = tid & 15;
    size_t rowBase = (size_t)blockIdx.y * 64;
    int colBase = blockIdx.x * 64;
    const float* Ab = A + rowBase * (size_t)lda;
    const float* Bb = Bw + colBase;

    float acc[4][4];
#pragma unroll
    for (int i = 0; i < 4; i++)
#pragma unroll
        for (int j = 0; j < 4; j++) acc[i][j] = 0.f;

    for (int k0 = 0; k0 < K; k0 += 16) {
#pragma unroll
        for (int i = 0; i < 4; i++) {
            int e = tid + i * 256;
            int r = e >> 4, c = e & 15;
            As[c][r] = Ab[(size_t)r * lda + (k0 + c)];
        }
#pragma unroll
        for (int i = 0; i < 4; i++) {
            int e = tid + i * 256;
            int r = e >> 6, c = e & 63;
            Bs[r][c] = Bb[(size_t)(k0 + r) * ldb + c];
        }
        __syncthreads();
#pragma unroll
        for (int k = 0; k < 16; k++) {
            float a0 = As[k][ty * 4 + 0];
            float a1 = As[k][ty * 4 + 1];
            float a2 = As[k][ty * 4 + 2];
            float a3 = As[k][ty * 4 + 3];
            float4 b = *(const float4*)&Bs[k][tx * 4];
            acc[0][0] += a0 * b.x; acc[0][1] += a0 * b.y; acc[0][2] += a0 * b.z; acc[0][3] += a0 * b.w;
            acc[1][0] += a1 * b.x; acc[1][1] += a1 * b.y; acc[1][2] += a1 * b.z; acc[1][3] += a1 * b.w;
            acc[2][0] += a2 * b.x; acc[2][1] += a2 * b.y; acc[2][2] += a2 * b.z; acc[2][3] += a2 * b.w;
            acc[3][0] += a3 * b.x; acc[3][1] += a3 * b.y; acc[3][2] += a3 * b.z; acc[3][3] += a3 * b.w;
        }
        __syncthreads();
    }

    int row0 = (int)rowBase + ty * 4;
    int col0 = colBase + tx * 4;
#pragma unroll
    for (int i = 0; i < 4; i++) {
        int row = row0 + i;
#pragma unroll
        for (int j = 0; j < 4; j++) {
            int col = col0 + j;
            float v = acc[i][j] + bias[col];
            if (flags & FLAG_PE) {
                int s = row % S_;
                int half = col >> 1;
                float div = expf((float)(2 * half) * (-9.210340371976184f / (float)D_));
                float arg = (float)s * div;
                v += (col & 1) ? cosf(arg) : sinf(arg);
            }
            if (flags & FLAG_RELU) v = fmaxf(v, 0.f);
            C[(size_t)row * ldc + col] = v;
        }
    }
}

// ---------------- fused QKV projection + attention: block per (b, h) -------
__global__ __launch_bounds__(256) void attn_fused(
    const float* __restrict__ hsrc,
    const float* __restrict__ Wq, const float* __restrict__ bq,
    const float* __restrict__ Wk, const float* __restrict__ bk,
    const float* __restrict__ Wv, const float* __restrict__ bv,
    int l, float* __restrict__ heads)
{
    __shared__ float sh[S_][DH_ + 1];
    __shared__ float sq[S_][DH_ + 1];
    __shared__ float sk[S_][DH_ + 1];
    __shared__ float sv[S_][DH_ + 1];
    __shared__ float sc[S_][S_ + 1];

    int bh = blockIdx.x;
    int b = bh / H_, h = bh % H_;
    size_t base = ((size_t)b * S_) * D_ + (size_t)h * DH_;
    int tid = threadIdx.x;

    for (int e = tid; e < S_ * DH_; e += 256) {
        int s = e >> 6, d = e & 63;
        sh[s][d] = hsrc[base + (size_t)s * D_ + d];
    }
    __syncthreads();

    size_t woff = ((size_t)l * H_ + h) * DH_ * DH_;
    size_t boff = ((size_t)l * H_ + h) * DH_;
    const float* Wqh = Wq + woff;
    const float* Wkh = Wk + woff;
    const float* Wvh = Wv + woff;

    {
        int e = tid & 63;
        for (int r = tid >> 6; r < 3 * S_; r += 4) {
            int m = r / S_, s = r % S_;
            const float* Wm = (m == 0) ? Wqh : (m == 1) ? Wkh : Wvh;
            const float* bm = (m == 0) ? (bq + boff) : (m == 1) ? (bk + boff) : (bv + boff);
            float acc = bm[e];
#pragma unroll 16
            for (int d = 0; d < DH_; d++) acc += sh[s][d] * Wm[d * DH_ + e];
            if (m == 0) sq[s][e] = acc;
            else if (m == 1) sk[s][e] = acc;
            else sv[s][e] = acc;
        }
    }
    __syncthreads();

    for (int e = tid; e < S_ * S_; e += 256) {
        int i = e / S_, j = e % S_;
        float acc = 0.f;
#pragma unroll
        for (int d = 0; d < DH_; d++) acc += sq[i][d] * sk[j][d];
        sc[i][j] = acc * 0.125f;
    }
    __syncthreads();

    if (tid < S_) {
        float m = -1e30f;
        for (int j = 0; j < S_; j++) m = fmaxf(m, sc[tid][j]);
        float sum = 0.f;
        for (int j = 0; j < S_; j++) {
            float e2 = expf(sc[tid][j] - m);
            sc[tid][j] = e2;
            sum += e2;
        }
        float inv = 1.f / sum;
        for (int j = 0; j < S_; j++) sc[tid][j] *= inv;
    }
    __syncthreads();

    for (int e = tid; e < S_ * DH_; e += 256) {
        int s = e >> 6, d = e & 63;
        float acc = 0.f;
#pragma unroll
        for (int j = 0; j < S_; j++) acc += sc[s][j] * sv[j][d];
        heads[base + (size_t)s * D_ + d] = acc;
    }
}

// ---------------- residual add + LayerNorm: warp per token -----------------
__global__ __launch_bounds__(256) void add_ln_warp(
    float* __restrict__ hb, const float* __restrict__ add,
    const float* __restrict__ gamma, const float* __restrict__ beta)
{
    int w = threadIdx.x >> 5, lane = threadIdx.x & 31;
    size_t base = ((size_t)blockIdx.x * 8 + w) * D_;

    float v[10];
    float s = 0.f;
#pragma unroll
    for (int i = 0; i < 10; i++) {
        v[i] = hb[base + lane + i * 32] + add[base + lane + i * 32];
        s += v[i];
    }
#pragma unroll
    for (int o = 16; o; o >>= 1) s += __shfl_xor_sync(0xffffffffu, s, o);
    float mean = s * (1.f / (float)D_);

    float s2 = 0.f;
#pragma unroll
    for (int i = 0; i < 10; i++) {
        float d = v[i] - mean;
        s2 += d * d;
    }
#pragma unroll
    for (int o = 16; o; o >>= 1) s2 += __shfl_xor_sync(0xffffffffu, s2, o);
    float rstd = rsqrtf(s2 * (1.f / (float)D_) + 1e-5f);

#pragma unroll
    for (int i = 0; i < 10; i++) {
        int d = lane + i * 32;
        hb[base + d] = (v[i] - mean) * rstd * gamma[d] + beta[d];
    }
}

// ---------------- attention pooling + classifier (block per batch row) -----
__global__ __launch_bounds__(320) void pool_cls_kernel(
    const float* __restrict__ hb,
    const float* __restrict__ pool_W, const float* __restrict__ pool_b,
    const float* __restrict__ W1, const float* __restrict__ b1,
    const float* __restrict__ W2, const float* __restrict__ b2,
    float* __restrict__ out)
{
    __shared__ float sscore[S_];
    __shared__ float sz[D_];
    __shared__ float shid[D_ / 2];
    __shared__ float sred[10];

    int b = blockIdx.x;
    int t = threadIdx.x, warp = t >> 5, lane = t & 31;
    const float* hrow = hb + (size_t)b * S_ * D_;

    for (int s = warp; s < S_; s += 10) {
        float acc = 0.f;
        for (int d = lane; d < D_; d += 32) acc += hrow[s * D_ + d] * pool_W[d];
#pragma unroll
        for (int o = 16; o; o >>= 1) acc += __shfl_down_sync(0xffffffffu, acc, o);
        if (lane == 0) sscore[s] = acc + pool_b[0];
    }
    __syncthreads();

    if (t == 0) {
        float m = -1e30f;
        for (int s = 0; s < S_; s++) m = fmaxf(m, sscore[s]);
        float sum = 0.f;
        for (int s = 0; s < S_; s++) {
            float e = expf(sscore[s] - m);
            sscore[s] = e;
            sum += e;
        }
        float inv = 1.f / sum;
        for (int s = 0; s < S_; s++) sscore[s] *= inv;
    }
    __syncthreads();

    {
        float acc = 0.f;
        for (int s = 0; s < S_; s++) acc += sscore[s] * hrow[s * D_ + t];
        sz[t] = acc;
    }
    __syncthreads();

    if (t < D_ / 2) {
        float acc = b1[t];
        for (int d = 0; d < D_; d++) acc += sz[d] * W1[d * (D_ / 2) + t];
        shid[t] = fmaxf(acc, 0.f);
    }
    __syncthreads();

    float p = (t < D_ / 2) ? shid[t] * W2[t] : 0.f;
#pragma unroll
    for (int o = 16; o; o >>= 1) p += __shfl_down_sync(0xffffffffu, p, o);
    if (lane == 0) sred[warp] = p;
    __syncthreads();
    if (t == 0) {
        float tot = 0.f;
        for (int i = 0; i < 10; i++) tot += sred[i];
        float logit = tot + b2[0];
        out[b] = logit;
        out[B_ + b] = 1.f / (1.f + expf(-logit));
    }
}

// ---------------- host launcher -------------------------------------------
extern "C" void kernel_launch(void* const* d_in, const int* in_sizes, int n_in,
                              void* d_out, int out_size)
{
    const float* x      = (const float*)d_in[0];
    const float* in_W   = (const float*)d_in[1];
    const float* in_b   = (const float*)d_in[2];
    const float* Wq     = (const float*)d_in[3];
    const float* bq     = (const float*)d_in[4];
    const float* Wk     = (const float*)d_in[5];
    const float* bk     = (const float*)d_in[6];
    const float* Wv     = (const float*)d_in[7];
    const float* bv     = (const float*)d_in[8];
    const float* Wo     = (const float*)d_in[9];
    const float* bo     = (const float*)d_in[10];
    const float* ln1_g  = (const float*)d_in[11];
    const float* ln1_b  = (const float*)d_in[12];
    const float* W1     = (const float*)d_in[13];
    const float* b1     = (const float*)d_in[14];
    const float* W2     = (const float*)d_in[15];
    const float* b2     = (const float*)d_in[16];
    const float* ln2_g  = (const float*)d_in[17];
    const float* ln2_b  = (const float*)d_in[18];
    const float* pool_W = (const float*)d_in[19];
    const float* pool_b = (const float*)d_in[20];
    const float* cW1    = (const float*)d_in[21];
    const float* cb1    = (const float*)d_in[22];
    const float* cW2    = (const float*)d_in[23];
    const float* cb2    = (const float*)d_in[24];

    float *ph, *pheads, *ptmp, *pffn;
    cudaGetSymbolAddress((void**)&ph, g_h);
    cudaGetSymbolAddress((void**)&pheads, g_heads);
    cudaGetSymbolAddress((void**)&ptmp, g_tmp);
    cudaGetSymbolAddress((void**)&pffn, g_ffn);

    const dim3 gridIn(D_ / 64, NTOK / 64);          // fp32 input proj
    const dim3 gridD_tc(D_ / 64, NTOK / 128);       // tf32, N=320
    const dim3 gridF_tc(DFF_ / 64, NTOK / 128);     // tf32, N=1280

    // input projection + bias + positional encoding (fp32)
    gemm64<<<gridIn, 256>>>(x, FIN_, in_W, D_, in_b, ph, D_, FIN_, FLAG_PE);

    for (int l = 0; l < L_; l++) {
        attn_fused<<<B_ * H_, 256>>>(ph, Wq, bq, Wk, bk, Wv, bv, l, pheads);
        gemm_tf32<<<gridD_tc, 256>>>(pheads, D_, Wo + (size_t)l * D_ * D_, D_,
                                     bo + l * D_, ptmp, D_, D_, 0);
        add_ln_warp<<<NTOK / 8, 256>>>(ph, ptmp, ln1_g + l * D_, ln1_b + l * D_);
        gemm_tf32<<<gridF_tc, 256>>>(ph, D_, W1 + (size_t)l * D_ * DFF_, DFF_,
                                     b1 + l * DFF_, pffn, DFF_, D_, FLAG_RELU);
        gemm_tf32<<<gridD_tc, 256>>>(pffn, DFF_, W2 + (size_t)l * DFF_ * D_, D_,
                                     b2 + l * D_, ptmp, D_, DFF_, 0);
        add_ln_warp<<<NTOK / 8, 256>>>(ph, ptmp, ln2_g + l * D_, ln2_b + l * D_);
    }

    pool_cls_kernel<<<B_, 320>>>(ph, pool_W, pool_b, cW1, cb1, cW2, cb2,
                                 (float*)d_out);
}

// round 5
// speedup vs baseline: 1.6533x; 1.4689x over previous
#include <cuda_runtime.h>
#include <cuda_bf16.h>
#include <math.h>

#define B_    4096
#define S_    30
#define FIN_  80
#define D_    320
#define H_    5
#define DH_   64
#define L_    4
#define DFF_  1280
#define NTOK  (B_ * S_)

#define FLAG_RELU 1
#define FLAG_PE   2

// ---------------- scratch (device globals; no allocations allowed) ----------
__device__ float g_h[NTOK * D_];
__device__ float g_heads[NTOK * D_];
__device__ float g_tmp[NTOK * D_];
__device__ float g_ffn[NTOK * DFF_];

// ======================================================================
// 3xBF16 tensor-core GEMM: C = A(MxK) @ B(KxN) + bias [+relu]
// BM=128, BN=64, BK=16. 256 threads = 8 warps in 4x2, warp tile 32x32.
// mma.sync.m16n8k16.bf16; A,B split hi/lo (drop lo*lo) for ~fp32 accuracy.
// smem rows stride 12 u32 (48B): frag LDS conflict-free (banks 12g+t4).
// Requires: M%128==0, N%64==0, K%16==0.
// ======================================================================
__device__ __forceinline__ void split2(float v0, float v1, unsigned& hi, unsigned& lo) {
    __nv_bfloat16 h0 = __float2bfloat16(v0), h1 = __float2bfloat16(v1);
    float l0f = v0 - __bfloat162float(h0);
    float l1f = v1 - __bfloat162float(h1);
    __nv_bfloat16 l0 = __float2bfloat16(l0f), l1 = __float2bfloat16(l1f);
    hi = ((unsigned)__bfloat16_as_ushort(h1) << 16) | __bfloat16_as_ushort(h0);
    lo = ((unsigned)__bfloat16_as_ushort(l1) << 16) | __bfloat16_as_ushort(l0);
}

__device__ __forceinline__ void mma_bf16(float* c, const unsigned* a, const unsigned* b) {
    asm volatile(
        "mma.sync.aligned.m16n8k16.row.col.f32.bf16.bf16.f32 "
        "{%0,%1,%2,%3}, {%4,%5,%6,%7}, {%8,%9}, {%0,%1,%2,%3};\n"
        : "+f"(c[0]), "+f"(c[1]), "+f"(c[2]), "+f"(c[3])
        : "r"(a[0]), "r"(a[1]), "r"(a[2]), "r"(a[3]), "r"(b[0]), "r"(b[1]));
}

#define ASTRIDE 12  // u32 per smem row (8 data + 4 pad)

__global__ __launch_bounds__(256, 2) void gemm_bf16s(
    const float* __restrict__ A, int lda,
    const float* __restrict__ Bw, int ldb,
    const float* __restrict__ bias,
    float* __restrict__ C, int ldc,
    int K, int flags)
{
    __shared__ unsigned sAh[128 * ASTRIDE], sAl[128 * ASTRIDE];
    __shared__ unsigned sBh[64 * ASTRIDE],  sBl[64 * ASTRIDE];

    const int tid  = threadIdx.x;
    const int lane = tid & 31;
    const int w    = tid >> 5;
    const int g    = lane >> 2;      // group 0..7
    const int t4   = lane & 3;
    const int wm   = (w >> 1) * 32;  // warp row offset
    const int wn   = (w & 1) * 32;   // warp col offset

    const size_t rowBase = (size_t)blockIdx.y * 128;
    const int    colBase = blockIdx.x * 64;

    // A staging: thread covers rows (tid>>2) and +64, k-quad (tid&3)*4
    const int arow = tid >> 2;
    const int akq  = tid & 3;
    // B staging: thread covers col bn=tid>>2 (0..63), k-quad (tid&3)*4
    const int bn   = tid >> 2;
    const int bkq  = tid & 3;

    const float* Ag = A + rowBase * (size_t)lda;
    const float* Bg = Bw + colBase;

    float4 rA0, rA1;
    float  rB[4];
    rA0 = *(const float4*)&Ag[(size_t)arow * lda + akq * 4];
    rA1 = *(const float4*)&Ag[(size_t)(arow + 64) * lda + akq * 4];
#pragma unroll
    for (int i = 0; i < 4; i++)
        rB[i] = Bg[(size_t)(bkq * 4 + i) * ldb + bn];

    float acc[2][4][4];
#pragma unroll
    for (int mt = 0; mt < 2; mt++)
#pragma unroll
        for (int nt = 0; nt < 4; nt++)
#pragma unroll
            for (int i = 0; i < 4; i++) acc[mt][nt][i] = 0.f;

    for (int k0 = 0; k0 < K; k0 += 16) {
        // stage current tile with hi/lo split (bf16-pair packed)
        {
            unsigned h, l;
            split2(rA0.x, rA0.y, h, l);
            sAh[arow * ASTRIDE + akq * 2]     = h; sAl[arow * ASTRIDE + akq * 2]     = l;
            split2(rA0.z, rA0.w, h, l);
            sAh[arow * ASTRIDE + akq * 2 + 1] = h; sAl[arow * ASTRIDE + akq * 2 + 1] = l;
            split2(rA1.x, rA1.y, h, l);
            sAh[(arow + 64) * ASTRIDE + akq * 2]     = h; sAl[(arow + 64) * ASTRIDE + akq * 2]     = l;
            split2(rA1.z, rA1.w, h, l);
            sAh[(arow + 64) * ASTRIDE + akq * 2 + 1] = h; sAl[(arow + 64) * ASTRIDE + akq * 2 + 1] = l;
            // B transposed to [n][k]
            split2(rB[0], rB[1], h, l);
            sBh[bn * ASTRIDE + bkq * 2]     = h; sBl[bn * ASTRIDE + bkq * 2]     = l;
            split2(rB[2], rB[3], h, l);
            sBh[bn * ASTRIDE + bkq * 2 + 1] = h; sBl[bn * ASTRIDE + bkq * 2 + 1] = l;
        }
        __syncthreads();

        // prefetch next tile
        if (k0 + 16 < K) {
            rA0 = *(const float4*)&Ag[(size_t)arow * lda + (k0 + 16) + akq * 4];
            rA1 = *(const float4*)&Ag[(size_t)(arow + 64) * lda + (k0 + 16) + akq * 4];
#pragma unroll
            for (int i = 0; i < 4; i++)
                rB[i] = Bg[(size_t)(k0 + 16 + bkq * 4 + i) * ldb + bn];
        }

        // fragments: one k16 step per tile
        unsigned ah[2][4], al[2][4], bh[4][2], bl[4][2];
#pragma unroll
        for (int mt = 0; mt < 2; mt++) {
            int r = wm + mt * 16 + g;
            ah[mt][0] = sAh[r * ASTRIDE + t4];
            ah[mt][1] = sAh[(r + 8) * ASTRIDE + t4];
            ah[mt][2] = sAh[r * ASTRIDE + t4 + 4];
            ah[mt][3] = sAh[(r + 8) * ASTRIDE + t4 + 4];
            al[mt][0] = sAl[r * ASTRIDE + t4];
            al[mt][1] = sAl[(r + 8) * ASTRIDE + t4];
            al[mt][2] = sAl[r * ASTRIDE + t4 + 4];
            al[mt][3] = sAl[(r + 8) * ASTRIDE + t4 + 4];
        }
#pragma unroll
        for (int nt = 0; nt < 4; nt++) {
            int c = wn + nt * 8 + g;
            bh[nt][0] = sBh[c * ASTRIDE + t4];
            bh[nt][1] = sBh[c * ASTRIDE + t4 + 4];
            bl[nt][0] = sBl[c * ASTRIDE + t4];
            bl[nt][1] = sBl[c * ASTRIDE + t4 + 4];
        }
#pragma unroll
        for (int mt = 0; mt < 2; mt++)
#pragma unroll
            for (int nt = 0; nt < 4; nt++) {
                mma_bf16(acc[mt][nt], ah[mt], bl[nt]);
                mma_bf16(acc[mt][nt], al[mt], bh[nt]);
                mma_bf16(acc[mt][nt], ah[mt], bh[nt]);
            }
        __syncthreads();
    }

    // epilogue: bias [+relu]
#pragma unroll
    for (int mt = 0; mt < 2; mt++) {
        size_t r0 = rowBase + wm + mt * 16 + g;
#pragma unroll
        for (int nt = 0; nt < 4; nt++) {
            int c = colBase + wn + nt * 8 + t4 * 2;
            float2 bs = *(const float2*)&bias[c];
            float v0 = acc[mt][nt][0] + bs.x;
            float v1 = acc[mt][nt][1] + bs.y;
            float v2 = acc[mt][nt][2] + bs.x;
            float v3 = acc[mt][nt][3] + bs.y;
            if (flags & FLAG_RELU) {
                v0 = fmaxf(v0, 0.f); v1 = fmaxf(v1, 0.f);
                v2 = fmaxf(v2, 0.f); v3 = fmaxf(v3, 0.f);
            }
            *(float2*)&C[r0 * ldc + c]       = make_float2(v0, v1);
            *(float2*)&C[(r0 + 8) * ldc + c] = make_float2(v2, v3);
        }
    }
}

// ---------------- fp32 tiled SGEMM (input projection only; PE epilogue) ----
__global__ __launch_bounds__(256) void gemm64(
    const float* __restrict__ A, int lda,
    const float* __restrict__ Bw, int ldb,
    const float* __restrict__ bias,
    float* __restrict__ C, int ldc,
    int K, int flags)
{
    __shared__ __align__(16) float As[16][65];
    __shared__ __align__(16) float Bs[16][64];

    int tid = threadIdx.x;
    int ty = tid >> 4, tx = tid & 15;
    size_t rowBase = (size_t)blockIdx.y * 64;
    int colBase = blockIdx.x * 64;
    const float* Ab = A + rowBase * (size_t)lda;
    const float* Bb = Bw + colBase;

    float acc[4][4];
#pragma unroll
    for (int i = 0; i < 4; i++)
#pragma unroll
        for (int j = 0; j < 4; j++) acc[i][j] = 0.f;

    for (int k0 = 0; k0 < K; k0 += 16) {
#pragma unroll
        for (int i = 0; i < 4; i++) {
            int e = tid + i * 256;
            int r = e >> 4, c = e & 15;
            As[c][r] = Ab[(size_t)r * lda + (k0 + c)];
        }
#pragma unroll
        for (int i = 0; i < 4; i++) {
            int e = tid + i * 256;
            int r = e >> 6, c = e & 63;
            Bs[r][c] = Bb[(size_t)(k0 + r) * ldb + c];
        }
        __syncthreads();
#pragma unroll
        for (int k = 0; k < 16; k++) {
            float a0 = As[k][ty * 4 + 0];
            float a1 = As[k][ty * 4 + 1];
            float a2 = As[k][ty * 4 + 2];
            float a3 = As[k][ty * 4 + 3];
            float4 b = *(const float4*)&Bs[k][tx * 4];
            acc[0][0] += a0 * b.x; acc[0][1] += a0 * b.y; acc[0][2] += a0 * b.z; acc[0][3] += a0 * b.w;
            acc[1][0] += a1 * b.x; acc[1][1] += a1 * b.y; acc[1][2] += a1 * b.z; acc[1][3] += a1 * b.w;
            acc[2][0] += a2 * b.x; acc[2][1] += a2 * b.y; acc[2][2] += a2 * b.z; acc[2][3] += a2 * b.w;
            acc[3][0] += a3 * b.x; acc[3][1] += a3 * b.y; acc[3][2] += a3 * b.z; acc[3][3] += a3 * b.w;
        }
        __syncthreads();
    }

    int row0 = (int)rowBase + ty * 4;
    int col0 = colBase + tx * 4;
#pragma unroll
    for (int i = 0; i < 4; i++) {
        int row = row0 + i;
#pragma unroll
        for (int j = 0; j < 4; j++) {
            int col = col0 + j;
            float v = acc[i][j] + bias[col];
            if (flags & FLAG_PE) {
                int s = row % S_;
                int half = col >> 1;
                float div = expf((float)(2 * half) * (-9.210340371976184f / (float)D_));
                float arg = (float)s * div;
                v += (col & 1) ? cosf(arg) : sinf(arg);
            }
            if (flags & FLAG_RELU) v = fmaxf(v, 0.f);
            C[(size_t)row * ldc + col] = v;
        }
    }
}

// ---------------- fused QKV projection + attention: block per (b, h) -------
__global__ __launch_bounds__(256) void attn_fused(
    const float* __restrict__ hsrc,
    const float* __restrict__ Wq, const float* __restrict__ bq,
    const float* __restrict__ Wk, const float* __restrict__ bk,
    const float* __restrict__ Wv, const float* __restrict__ bv,
    int l, float* __restrict__ heads)
{
    __shared__ float sh[S_][DH_ + 1];
    __shared__ float sq[S_][DH_ + 1];
    __shared__ float sk[S_][DH_ + 1];
    __shared__ float sv[S_][DH_ + 1];
    __shared__ float sc[S_][S_ + 1];

    int bh = blockIdx.x;
    int b = bh / H_, h = bh % H_;
    size_t base = ((size_t)b * S_) * D_ + (size_t)h * DH_;
    int tid = threadIdx.x;

    for (int e = tid; e < S_ * DH_; e += 256) {
        int s = e >> 6, d = e & 63;
        sh[s][d] = hsrc[base + (size_t)s * D_ + d];
    }
    __syncthreads();

    size_t woff = ((size_t)l * H_ + h) * DH_ * DH_;
    size_t boff = ((size_t)l * H_ + h) * DH_;
    const float* Wqh = Wq + woff;
    const float* Wkh = Wk + woff;
    const float* Wvh = Wv + woff;

    {
        int e = tid & 63;
        for (int r = tid >> 6; r < 3 * S_; r += 4) {
            int m = r / S_, s = r % S_;
            const float* Wm = (m == 0) ? Wqh : (m == 1) ? Wkh : Wvh;
            const float* bm = (m == 0) ? (bq + boff) : (m == 1) ? (bk + boff) : (bv + boff);
            float acc = bm[e];
#pragma unroll 16
            for (int d = 0; d < DH_; d++) acc += sh[s][d] * Wm[d * DH_ + e];
            if (m == 0) sq[s][e] = acc;
            else if (m == 1) sk[s][e] = acc;
            else sv[s][e] = acc;
        }
    }
    __syncthreads();

    for (int e = tid; e < S_ * S_; e += 256) {
        int i = e / S_, j = e % S_;
        float acc = 0.f;
#pragma unroll
        for (int d = 0; d < DH_; d++) acc += sq[i][d] * sk[j][d];
        sc[i][j] = acc * 0.125f;
    }
    __syncthreads();

    if (tid < S_) {
        float m = -1e30f;
        for (int j = 0; j < S_; j++) m = fmaxf(m, sc[tid][j]);
        float sum = 0.f;
        for (int j = 0; j < S_; j++) {
            float e2 = expf(sc[tid][j] - m);
            sc[tid][j] = e2;
            sum += e2;
        }
        float inv = 1.f / sum;
        for (int j = 0; j < S_; j++) sc[tid][j] *= inv;
    }
    __syncthreads();

    for (int e = tid; e < S_ * DH_; e += 256) {
        int s = e >> 6, d = e & 63;
        float acc = 0.f;
#pragma unroll
        for (int j = 0; j < S_; j++) acc += sc[s][j] * sv[j][d];
        heads[base + (size_t)s * D_ + d] = acc;
    }
}

// ---------------- residual add + LayerNorm: warp per token -----------------
__global__ __launch_bounds__(256) void add_ln_warp(
    float* __restrict__ hb, const float* __restrict__ add,
    const float* __restrict__ gamma, const float* __restrict__ beta)
{
    int w = threadIdx.x >> 5, lane = threadIdx.x & 31;
    size_t base = ((size_t)blockIdx.x * 8 + w) * D_;

    float v[10];
    float s = 0.f;
#pragma unroll
    for (int i = 0; i < 10; i++) {
        v[i] = hb[base + lane + i * 32] + add[base + lane + i * 32];
        s += v[i];
    }
#pragma unroll
    for (int o = 16; o; o >>= 1) s += __shfl_xor_sync(0xffffffffu, s, o);
    float mean = s * (1.f / (float)D_);

    float s2 = 0.f;
#pragma unroll
    for (int i = 0; i < 10; i++) {
        float d = v[i] - mean;
        s2 += d * d;
    }
#pragma unroll
    for (int o = 16; o; o >>= 1) s2 += __shfl_xor_sync(0xffffffffu, s2, o);
    float rstd = rsqrtf(s2 * (1.f / (float)D_) + 1e-5f);

#pragma unroll
    for (int i = 0; i < 10; i++) {
        int d = lane + i * 32;
        hb[base + d] = (v[i] - mean) * rstd * gamma[d] + beta[d];
    }
}

// ---------------- attention pooling + classifier (block per batch row) -----
__global__ __launch_bounds__(320) void pool_cls_kernel(
    const float* __restrict__ hb,
    const float* __restrict__ pool_W, const float* __restrict__ pool_b,
    const float* __restrict__ W1, const float* __restrict__ b1,
    const float* __restrict__ W2, const float* __restrict__ b2,
    float* __restrict__ out)
{
    __shared__ float sscore[S_];
    __shared__ float sz[D_];
    __shared__ float shid[D_ / 2];
    __shared__ float sred[10];

    int b = blockIdx.x;
    int t = threadIdx.x, warp = t >> 5, lane = t & 31;
    const float* hrow = hb + (size_t)b * S_ * D_;

    for (int s = warp; s < S_; s += 10) {
        float acc = 0.f;
        for (int d = lane; d < D_; d += 32) acc += hrow[s * D_ + d] * pool_W[d];
#pragma unroll
        for (int o = 16; o; o >>= 1) acc += __shfl_down_sync(0xffffffffu, acc, o);
        if (lane == 0) sscore[s] = acc + pool_b[0];
    }
    __syncthreads();

    if (t == 0) {
        float m = -1e30f;
        for (int s = 0; s < S_; s++) m = fmaxf(m, sscore[s]);
        float sum = 0.f;
        for (int s = 0; s < S_; s++) {
            float e = expf(sscore[s] - m);
            sscore[s] = e;
            sum += e;
        }
        float inv = 1.f / sum;
        for (int s = 0; s < S_; s++) sscore[s] *= inv;
    }
    __syncthreads();

    {
        float acc = 0.f;
        for (int s = 0; s < S_; s++) acc += sscore[s] * hrow[s * D_ + t];
        sz[t] = acc;
    }
    __syncthreads();

    if (t < D_ / 2) {
        float acc = b1[t];
        for (int d = 0; d < D_; d++) acc += sz[d] * W1[d * (D_ / 2) + t];
        shid[t] = fmaxf(acc, 0.f);
    }
    __syncthreads();

    float p = (t < D_ / 2) ? shid[t] * W2[t] : 0.f;
#pragma unroll
    for (int o = 16; o; o >>= 1) p += __shfl_down_sync(0xffffffffu, p, o);
    if (lane == 0) sred[warp] = p;
    __syncthreads();
    if (t == 0) {
        float tot = 0.f;
        for (int i = 0; i < 10; i++) tot += sred[i];
        float logit = tot + b2[0];
        out[b] = logit;
        out[B_ + b] = 1.f / (1.f + expf(-logit));
    }
}

// ---------------- host launcher -------------------------------------------
extern "C" void kernel_launch(void* const* d_in, const int* in_sizes, int n_in,
                              void* d_out, int out_size)
{
    const float* x      = (const float*)d_in[0];
    const float* in_W   = (const float*)d_in[1];
    const float* in_b   = (const float*)d_in[2];
    const float* Wq     = (const float*)d_in[3];
    const float* bq     = (const float*)d_in[4];
    const float* Wk     = (const float*)d_in[5];
    const float* bk     = (const float*)d_in[6];
    const float* Wv     = (const float*)d_in[7];
    const float* bv     = (const float*)d_in[8];
    const float* Wo     = (const float*)d_in[9];
    const float* bo     = (const float*)d_in[10];
    const float* ln1_g  = (const float*)d_in[11];
    const float* ln1_b  = (const float*)d_in[12];
    const float* W1     = (const float*)d_in[13];
    const float* b1     = (const float*)d_in[14];
    const float* W2     = (const float*)d_in[15];
    const float* b2     = (const float*)d_in[16];
    const float* ln2_g  = (const float*)d_in[17];
    const float* ln2_b  = (const float*)d_in[18];
    const float* pool_W = (const float*)d_in[19];
    const float* pool_b = (const float*)d_in[20];
    const float* cW1    = (const float*)d_in[21];
    const float* cb1    = (const float*)d_in[22];
    const float* cW2    = (const float*)d_in[23];
    const float* cb2    = (const float*)d_in[24];

    float *ph, *pheads, *ptmp, *pffn;
    cudaGetSymbolAddress((void**)&ph, g_h);
    cudaGetSymbolAddress((void**)&pheads, g_heads);
    cudaGetSymbolAddress((void**)&ptmp, g_tmp);
    cudaGetSymbolAddress((void**)&pffn, g_ffn);

    const dim3 gridIn(D_ / 64, NTOK / 64);          // fp32 input proj
    const dim3 gridD_tc(D_ / 64, NTOK / 128);       // bf16s, N=320
    const dim3 gridF_tc(DFF_ / 64, NTOK / 128);     // bf16s, N=1280

    // input projection + bias + positional encoding (fp32)
    gemm64<<<gridIn, 256>>>(x, FIN_, in_W, D_, in_b, ph, D_, FIN_, FLAG_PE);

    for (int l = 0; l < L_; l++) {
        attn_fused<<<B_ * H_, 256>>>(ph, Wq, bq, Wk, bk, Wv, bv, l, pheads);
        gemm_bf16s<<<gridD_tc, 256>>>(pheads, D_, Wo + (size_t)l * D_ * D_, D_,
                                      bo + l * D_, ptmp, D_, D_, 0);
        add_ln_warp<<<NTOK / 8, 256>>>(ph, ptmp, ln1_g + l * D_, ln1_b + l * D_);
        gemm_bf16s<<<gridF_tc, 256>>>(ph, D_, W1 + (size_t)l * D_ * DFF_, DFF_,
                                      b1 + l * DFF_, pffn, DFF_, D_, FLAG_RELU);
        gemm_bf16s<<<gridD_tc, 256>>>(pffn, DFF_, W2 + (size_t)l * DFF_ * D_, D_,
                                      b2 + l * D_, ptmp, D_, DFF_, 0);
        add_ln_warp<<<NTOK / 8, 256>>>(ph, ptmp, ln2_g + l * D_, ln2_b + l * D_);
    }

    pool_cls_kernel<<<B_, 320>>>(ph, pool_W, pool_b, cW1, cb1, cW2, cb2,
                                 (float*)d_out);
}

// round 8
// speedup vs baseline: 1.9511x; 1.1801x over previous
#include <cuda_runtime.h>
#include <cuda_bf16.h>
#include <math.h>
#include <stdint.h>

#define B_    4096
#define S_    30
#define FIN_  80
#define D_    320
#define H_    5
#define DH_   64
#define L_    4
#define DFF_  1280
#define NTOK  (B_ * S_)

#define FLAG_RELU 1
#define FLAG_PE   2
#define FLAG_PACK 4

// ---------------- scratch (device globals; no allocations allowed) ----------
__device__ float g_h[NTOK * D_];
__device__ float g_tmp[NTOK * D_];
__device__ uint32_t g_h_hi[NTOK * D_ / 2],   g_h_lo[NTOK * D_ / 2];
__device__ uint32_t g_hd_hi[NTOK * D_ / 2],  g_hd_lo[NTOK * D_ / 2];
__device__ uint32_t g_ff_hi[NTOK * DFF_ / 2], g_ff_lo[NTOK * DFF_ / 2];
__device__ uint32_t g_wo_hi[L_ * D_ * D_ / 2],   g_wo_lo[L_ * D_ * D_ / 2];
__device__ uint32_t g_w1_hi[L_ * D_ * DFF_ / 2], g_w1_lo[L_ * D_ * DFF_ / 2];
__device__ uint32_t g_w2_hi[L_ * DFF_ * D_ / 2], g_w2_lo[L_ * DFF_ * D_ / 2];

// ---------------- helpers --------------------------------------------------
__device__ __forceinline__ uint32_t smem_u32(const void* p) {
    uint32_t a;
    asm("{ .reg .u64 t; cvta.to.shared.u64 t, %1; cvt.u32.u64 %0, t; }"
        : "=r"(a) : "l"(p));
    return a;
}

// bf16 hi/lo split, packed pairs (v0 low half, v1 high half)
__device__ __forceinline__ void split2(float v0, float v1, uint32_t& hi, uint32_t& lo) {
    asm("cvt.rn.bf16x2.f32 %0, %1, %2;" : "=r"(hi) : "f"(v1), "f"(v0));
    float h0 = __uint_as_float(hi << 16);
    float h1 = __uint_as_float(hi & 0xffff0000u);
    asm("cvt.rn.bf16x2.f32 %0, %1, %2;" : "=r"(lo) : "f"(v1 - h1), "f"(v0 - h0));
}

__device__ __forceinline__ void mma_bf16(float* c, const uint32_t* a, const uint32_t* b) {
    asm volatile(
        "mma.sync.aligned.m16n8k16.row.col.f32.bf16.bf16.f32 "
        "{%0,%1,%2,%3}, {%4,%5,%6,%7}, {%8,%9}, {%0,%1,%2,%3};\n"
        : "+f"(c[0]), "+f"(c[1]), "+f"(c[2]), "+f"(c[3])
        : "r"(a[0]), "r"(a[1]), "r"(a[2]), "r"(a[3]), "r"(b[0]), "r"(b[1]));
}

__device__ __forceinline__ void ldm_x4(uint32_t* r, uint32_t addr) {
    asm volatile("ldmatrix.sync.aligned.m8n8.x4.shared.b16 {%0,%1,%2,%3}, [%4];"
        : "=r"(r[0]), "=r"(r[1]), "=r"(r[2]), "=r"(r[3]) : "r"(addr));
}

__device__ __forceinline__ void cp16(uint32_t dst, const uint32_t* src) {
    asm volatile("cp.async.cg.shared.global [%0], [%1], 16;" :: "r"(dst), "l"(src));
}
#define CP_COMMIT() asm volatile("cp.async.commit_group;" ::: "memory")
#define CP_WAIT0()  asm volatile("cp.async.wait_group 0;" ::: "memory")
#define CP_WAIT1()  asm volatile("cp.async.wait_group 1;" ::: "memory")

// ---------------- weight conversion: W[K][N] -> Wt_hi/lo [N][K/2] ----------
__global__ void convert_w(const float* __restrict__ W,
                          uint32_t* __restrict__ hi, uint32_t* __restrict__ lo,
                          int K, int N)
{
    int idx = blockIdx.x * 256 + threadIdx.x;
    int K2 = K >> 1;
    if (idx >= N * K2) return;
    int n = idx / K2, k2 = idx % K2;
    float v0 = W[(size_t)(2 * k2) * N + n];
    float v1 = W[(size_t)(2 * k2 + 1) * N + n];
    uint32_t h, l;
    split2(v0, v1, h, l);
    hi[idx] = h; lo[idx] = l;
}

// ======================================================================
// Pre-split bf16 GEMM: C = A @ B + bias [+relu] [packed out]
// A: packed bf16-hi/lo [M][K/2] u32.  B: packed transposed [N][K/2] u32.
// BM=128 BN=64 BK=32, 256 thr (8 warps 4x2, warp tile 32x32), cp.async
// double buffer, ldmatrix frags, 3-term split (hh + hl + lh).
// smem/stage: Ah[128][20] Al Bh[64][20] Bl (u32, 4-pad rows) = 30720 B.
// ======================================================================
#define SA_H 0
#define SA_L 10240
#define SB_H 20480
#define SB_L 25600
#define STAGE_B 30720
#define GPS_SMEM (2 * STAGE_B)

__global__ __launch_bounds__(256, 2) void gemm_ps(
    const uint32_t* __restrict__ Ahi, const uint32_t* __restrict__ Alo, int K2,
    const uint32_t* __restrict__ Bhi, const uint32_t* __restrict__ Blo,
    const float* __restrict__ bias,
    float* __restrict__ C, uint32_t* __restrict__ Chi, uint32_t* __restrict__ Clo,
    int N, int flags)
{
    extern __shared__ __align__(1024) char smem[];
    const uint32_t sbase = smem_u32(smem);
    const int tid = threadIdx.x;
    const int lane = tid & 31;
    const int w = tid >> 5;
    const int g = lane >> 2, t4 = lane & 3;
    const int wm = (w >> 1) * 32, wn = (w & 1) * 32;

    const size_t rowBase = (size_t)blockIdx.y * 128;
    const int    colBase = blockIdx.x * 64;

    const uint32_t* Ah_g = Ahi + rowBase * K2;
    const uint32_t* Al_g = Alo + rowBase * K2;
    const uint32_t* Bh_g = Bhi + (size_t)colBase * K2;
    const uint32_t* Bl_g = Blo + (size_t)colBase * K2;

    const int ar0 = tid >> 2, ach = (tid & 3) * 4;   // A rows ar0, ar0+64
    const int br  = tid >> 2, bch = (tid & 3) * 4;   // B row (n)

    float acc[2][4][4];
#pragma unroll
    for (int mt = 0; mt < 2; mt++)
#pragma unroll
        for (int nt = 0; nt < 4; nt++)
#pragma unroll
            for (int i = 0; i < 4; i++) acc[mt][nt][i] = 0.f;

    auto stage = [&](int it, int buf) {
        uint32_t sb = sbase + buf * STAGE_B;
        int k2o = it * 16;
#pragma unroll
        for (int j = 0; j < 2; j++) {
            int row = ar0 + j * 64;
            uint32_t soff = (uint32_t)(row * 20 + ach) * 4;
            cp16(sb + SA_H + soff, Ah_g + (size_t)row * K2 + k2o + ach);
            cp16(sb + SA_L + soff, Al_g + (size_t)row * K2 + k2o + ach);
        }
        uint32_t soffb = (uint32_t)(br * 20 + bch) * 4;
        cp16(sb + SB_H + soffb, Bh_g + (size_t)br * K2 + k2o + bch);
        cp16(sb + SB_L + soffb, Bl_g + (size_t)br * K2 + k2o + bch);
    };

    auto compute = [&](int buf) {
        uint32_t sb = sbase + buf * STAGE_B;
#pragma unroll
        for (int s = 0; s < 2; s++) {
            const int s8 = s * 8;
            uint32_t ah[2][4], al[2][4], bh[4][2], bl[4][2];
#pragma unroll
            for (int mt = 0; mt < 2; mt++) {
                int row = wm + mt * 16 + (lane & 15);
                uint32_t off = (uint32_t)(row * 20 + s8 + ((lane >> 4) << 2)) * 4;
                ldm_x4(ah[mt], sb + SA_H + off);
                ldm_x4(al[mt], sb + SA_L + off);
            }
#pragma unroll
            for (int h2 = 0; h2 < 2; h2++) {
                int row = wn + h2 * 16 + (lane & 7) + ((lane >> 4) << 3);
                uint32_t off = (uint32_t)(row * 20 + s8 + ((lane & 8) >> 1)) * 4;
                uint32_t t[4];
                ldm_x4(t, sb + SB_H + off);
                bh[h2 * 2][0] = t[0]; bh[h2 * 2][1] = t[1];
                bh[h2 * 2 + 1][0] = t[2]; bh[h2 * 2 + 1][1] = t[3];
                ldm_x4(t, sb + SB_L + off);
                bl[h2 * 2][0] = t[0]; bl[h2 * 2][1] = t[1];
                bl[h2 * 2 + 1][0] = t[2]; bl[h2 * 2 + 1][1] = t[3];
            }
#pragma unroll
            for (int mt = 0; mt < 2; mt++)
#pragma unroll
                for (int nt = 0; nt < 4; nt++) {
                    mma_bf16(acc[mt][nt], ah[mt], bl[nt]);
                    mma_bf16(acc[mt][nt], al[mt], bh[nt]);
                    mma_bf16(acc[mt][nt], ah[mt], bh[nt]);
                }
        }
    };

    const int nIter = K2 >> 4;   // K/32
    stage(0, 0);
    CP_COMMIT();
    for (int it = 0; it < nIter; it++) {
        if (it + 1 < nIter) {
            stage(it + 1, (it + 1) & 1);
            CP_COMMIT();
            CP_WAIT1();
        } else {
            CP_WAIT0();
        }
        __syncthreads();
        compute(it & 1);
        __syncthreads();
    }

    // epilogue
#pragma unroll
    for (int mt = 0; mt < 2; mt++) {
        size_t r0 = rowBase + wm + mt * 16 + g;
#pragma unroll
        for (int nt = 0; nt < 4; nt++) {
            int col = colBase + wn + nt * 8 + t4 * 2;
            float2 bs = *(const float2*)&bias[col];
            float v0 = acc[mt][nt][0] + bs.x;
            float v1 = acc[mt][nt][1] + bs.y;
            float v2 = acc[mt][nt][2] + bs.x;
            float v3 = acc[mt][nt][3] + bs.y;
            if (flags & FLAG_RELU) {
                v0 = fmaxf(v0, 0.f); v1 = fmaxf(v1, 0.f);
                v2 = fmaxf(v2, 0.f); v3 = fmaxf(v3, 0.f);
            }
            if (flags & FLAG_PACK) {
                int N2 = N >> 1, c2 = col >> 1;
                uint32_t h, l;
                split2(v0, v1, h, l);
                Chi[r0 * N2 + c2] = h; Clo[r0 * N2 + c2] = l;
                split2(v2, v3, h, l);
                Chi[(r0 + 8) * N2 + c2] = h; Clo[(r0 + 8) * N2 + c2] = l;
            } else {
                *(float2*)&C[r0 * N + col]       = make_float2(v0, v1);
                *(float2*)&C[(r0 + 8) * N + col] = make_float2(v2, v3);
            }
        }
    }
}

// ---------------- fp32 tiled SGEMM (input projection only; PE epilogue) ----
__global__ __launch_bounds__(256) void gemm64(
    const float* __restrict__ A, int lda,
    const float* __restrict__ Bw, int ldb,
    const float* __restrict__ bias,
    float* __restrict__ C, int ldc,
    int K, int flags)
{
    __shared__ __align__(16) float As[16][65];
    __shared__ __align__(16) float Bs[16][64];

    int tid = threadIdx.x;
    int ty = tid >> 4, tx = tid & 15;
    size_t rowBase = (size_t)blockIdx.y * 64;
    int colBase = blockIdx.x * 64;
    const float* Ab = A + rowBase * (size_t)lda;
    const float* Bb = Bw + colBase;

    float acc[4][4];
#pragma unroll
    for (int i = 0; i < 4; i++)
#pragma unroll
        for (int j = 0; j < 4; j++) acc[i][j] = 0.f;

    for (int k0 = 0; k0 < K; k0 += 16) {
#pragma unroll
        for (int i = 0; i < 4; i++) {
            int e = tid + i * 256;
            int r = e >> 4, c = e & 15;
            As[c][r] = Ab[(size_t)r * lda + (k0 + c)];
        }
#pragma unroll
        for (int i = 0; i < 4; i++) {
            int e = tid + i * 256;
            int r = e >> 6, c = e & 63;
            Bs[r][c] = Bb[(size_t)(k0 + r) * ldb + c];
        }
        __syncthreads();
#pragma unroll
        for (int k = 0; k < 16; k++) {
            float a0 = As[k][ty * 4 + 0];
            float a1 = As[k][ty * 4 + 1];
            float a2 = As[k][ty * 4 + 2];
            float a3 = As[k][ty * 4 + 3];
            float4 b = *(const float4*)&Bs[k][tx * 4];
            acc[0][0] += a0 * b.x; acc[0][1] += a0 * b.y; acc[0][2] += a0 * b.z; acc[0][3] += a0 * b.w;
            acc[1][0] += a1 * b.x; acc[1][1] += a1 * b.y; acc[1][2] += a1 * b.z; acc[1][3] += a1 * b.w;
            acc[2][0] += a2 * b.x; acc[2][1] += a2 * b.y; acc[2][2] += a2 * b.z; acc[2][3] += a2 * b.w;
            acc[3][0] += a3 * b.x; acc[3][1] += a3 * b.y; acc[3][2] += a3 * b.z; acc[3][3] += a3 * b.w;
        }
        __syncthreads();
    }

    int row0 = (int)rowBase + ty * 4;
    int col0 = colBase + tx * 4;
#pragma unroll
    for (int i = 0; i < 4; i++) {
        int row = row0 + i;
#pragma unroll
        for (int j = 0; j < 4; j++) {
            int col = col0 + j;
            float v = acc[i][j] + bias[col];
            if (flags & FLAG_PE) {
                int s = row % S_;
                int half = col >> 1;
                float div = expf((float)(2 * half) * (-9.210340371976184f / (float)D_));
                float arg = (float)s * div;
                v += (col & 1) ? cosf(arg) : sinf(arg);
            }
            if (flags & FLAG_RELU) v = fmaxf(v, 0.f);
            C[(size_t)row * ldc + col] = v;
        }
    }
}

// ---------------- fused QKV projection + attention: block per (b, h) -------
// Writes packed bf16 hi/lo head outputs.
__global__ __launch_bounds__(256) void attn_fused(
    const float* __restrict__ hsrc,
    const float* __restrict__ Wq, const float* __restrict__ bq,
    const float* __restrict__ Wk, const float* __restrict__ bk,
    const float* __restrict__ Wv, const float* __restrict__ bv,
    int l, uint32_t* __restrict__ headsHi, uint32_t* __restrict__ headsLo)
{
    __shared__ float sh[S_][DH_ + 1];
    __shared__ float sq[S_][DH_ + 1];
    __shared__ float sk[S_][DH_ + 1];
    __shared__ float sv[S_][DH_ + 1];
    __shared__ float sc[S_][S_ + 1];

    int bh = blockIdx.x;
    int b = bh / H_, h = bh % H_;
    size_t base = ((size_t)b * S_) * D_ + (size_t)h * DH_;
    int tid = threadIdx.x;

    for (int e = tid; e < S_ * DH_; e += 256) {
        int s = e >> 6, d = e & 63;
        sh[s][d] = hsrc[base + (size_t)s * D_ + d];
    }
    __syncthreads();

    size_t woff = ((size_t)l * H_ + h) * DH_ * DH_;
    size_t boff = ((size_t)l * H_ + h) * DH_;
    const float* Wqh = Wq + woff;
    const float* Wkh = Wk + woff;
    const float* Wvh = Wv + woff;

    {
        int e = tid & 63;
        for (int r = tid >> 6; r < 3 * S_; r += 4) {
            int m = r / S_, s = r % S_;
            const float* Wm = (m == 0) ? Wqh : (m == 1) ? Wkh : Wvh;
            const float* bm = (m == 0) ? (bq + boff) : (m == 1) ? (bk + boff) : (bv + boff);
            float acc = bm[e];
#pragma unroll 16
            for (int d = 0; d < DH_; d++) acc += sh[s][d] * Wm[d * DH_ + e];
            if (m == 0) sq[s][e] = acc;
            else if (m == 1) sk[s][e] = acc;
            else sv[s][e] = acc;
        }
    }
    __syncthreads();

    for (int e = tid; e < S_ * S_; e += 256) {
        int i = e / S_, j = e % S_;
        float acc = 0.f;
#pragma unroll
        for (int d = 0; d < DH_; d++) acc += sq[i][d] * sk[j][d];
        sc[i][j] = acc * 0.125f;
    }
    __syncthreads();

    if (tid < S_) {
        float m = -1e30f;
        for (int j = 0; j < S_; j++) m = fmaxf(m, sc[tid][j]);
        float sum = 0.f;
        for (int j = 0; j < S_; j++) {
            float e2 = expf(sc[tid][j] - m);
            sc[tid][j] = e2;
            sum += e2;
        }
        float inv = 1.f / sum;
        for (int j = 0; j < S_; j++) sc[tid][j] *= inv;
    }
    __syncthreads();

    // A @ V -> packed bf16 hi/lo pairs
    size_t tokBase = (size_t)b * S_;
    for (int e = tid; e < S_ * 32; e += 256) {
        int s = e >> 5, p = e & 31;
        int d0 = p * 2;
        float a0 = 0.f, a1 = 0.f;
#pragma unroll
        for (int j = 0; j < S_; j++) {
            a0 += sc[s][j] * sv[j][d0];
            a1 += sc[s][j] * sv[j][d0 + 1];
        }
        uint32_t hh, ll;
        split2(a0, a1, hh, ll);
        size_t off = (tokBase + s) * (D_ / 2) + h * 32 + p;
        headsHi[off] = hh;
        headsLo[off] = ll;
    }
}

// ---------------- residual add + LayerNorm: warp per token -----------------
// Optionally also writes packed bf16 hi/lo of the normalized output.
__global__ __launch_bounds__(256) void add_ln_warp(
    float* __restrict__ hb, const float* __restrict__ add,
    const float* __restrict__ gamma, const float* __restrict__ beta,
    uint32_t* __restrict__ outHi, uint32_t* __restrict__ outLo, int pack)
{
    int w = threadIdx.x >> 5, lane = threadIdx.x & 31;
    size_t tok = (size_t)blockIdx.x * 8 + w;
    size_t base = tok * D_;

    float2 v[5];
    float s = 0.f;
#pragma unroll
    for (int i = 0; i < 5; i++) {
        int d = lane * 2 + i * 64;
        float2 a = *(const float2*)&hb[base + d];
        float2 r = *(const float2*)&add[base + d];
        v[i].x = a.x + r.x;
        v[i].y = a.y + r.y;
        s += v[i].x + v[i].y;
    }
#pragma unroll
    for (int o = 16; o; o >>= 1) s += __shfl_xor_sync(0xffffffffu, s, o);
    float mean = s * (1.f / (float)D_);

    float s2 = 0.f;
#pragma unroll
    for (int i = 0; i < 5; i++) {
        float dx = v[i].x - mean, dy = v[i].y - mean;
        s2 += dx * dx + dy * dy;
    }
#pragma unroll
    for (int o = 16; o; o >>= 1) s2 += __shfl_xor_sync(0xffffffffu, s2, o);
    float rstd = rsqrtf(s2 * (1.f / (float)D_) + 1e-5f);

#pragma unroll
    for (int i = 0; i < 5; i++) {
        int d = lane * 2 + i * 64;
        float o0 = (v[i].x - mean) * rstd * gamma[d] + beta[d];
        float o1 = (v[i].y - mean) * rstd * gamma[d + 1] + beta[d + 1];
        *(float2*)&hb[base + d] = make_float2(o0, o1);
        if (pack) {
            uint32_t hh, ll;
            split2(o0, o1, hh, ll);
            outHi[tok * (D_ / 2) + lane + i * 32] = hh;
            outLo[tok * (D_ / 2) + lane + i * 32] = ll;
        }
    }
}

// ---------------- attention pooling + classifier (block per batch row) -----
__global__ __launch_bounds__(320) void pool_cls_kernel(
    const float* __restrict__ hb,
    const float* __restrict__ pool_W, const float* __restrict__ pool_b,
    const float* __restrict__ W1, const float* __restrict__ b1,
    const float* __restrict__ W2, const float* __restrict__ b2,
    float* __restrict__ out)
{
    __shared__ float sscore[S_];
    __shared__ float sz[D_];
    __shared__ float shid[D_ / 2];
    __shared__ float sred[10];

    int b = blockIdx.x;
    int t = threadIdx.x, warp = t >> 5, lane = t & 31;
    const float* hrow = hb + (size_t)b * S_ * D_;

    for (int s = warp; s < S_; s += 10) {
        float acc = 0.f;
        for (int d = lane; d < D_; d += 32) acc += hrow[s * D_ + d] * pool_W[d];
#pragma unroll
        for (int o = 16; o; o >>= 1) acc += __shfl_down_sync(0xffffffffu, acc, o);
        if (lane == 0) sscore[s] = acc + pool_b[0];
    }
    __syncthreads();

    if (t == 0) {
        float m = -1e30f;
        for (int s = 0; s < S_; s++) m = fmaxf(m, sscore[s]);
        float sum = 0.f;
        for (int s = 0; s < S_; s++) {
            float e = expf(sscore[s] - m);
            sscore[s] = e;
            sum += e;
        }
        float inv = 1.f / sum;
        for (int s = 0; s < S_; s++) sscore[s] *= inv;
    }
    __syncthreads();

    {
        float acc = 0.f;
        for (int s = 0; s < S_; s++) acc += sscore[s] * hrow[s * D_ + t];
        sz[t] = acc;
    }
    __syncthreads();

    if (t < D_ / 2) {
        float acc = b1[t];
        for (int d = 0; d < D_; d++) acc += sz[d] * W1[d * (D_ / 2) + t];
        shid[t] = fmaxf(acc, 0.f);
    }
    __syncthreads();

    float p = (t < D_ / 2) ? shid[t] * W2[t] : 0.f;
#pragma unroll
    for (int o = 16; o; o >>= 1) p += __shfl_down_sync(0xffffffffu, p, o);
    if (lane == 0) sred[warp] = p;
    __syncthreads();
    if (t == 0) {
        float tot = 0.f;
        for (int i = 0; i < 10; i++) tot += sred[i];
        float logit = tot + b2[0];
        out[b] = logit;
        out[B_ + b] = 1.f / (1.f + expf(-logit));
    }
}

// ---------------- host launcher -------------------------------------------
extern "C" void kernel_launch(void* const* d_in, const int* in_sizes, int n_in,
                              void* d_out, int out_size)
{
    const float* x      = (const float*)d_in[0];
    const float* in_W   = (const float*)d_in[1];
    const float* in_b   = (const float*)d_in[2];
    const float* Wq     = (const float*)d_in[3];
    const float* bq     = (const float*)d_in[4];
    const float* Wk     = (const float*)d_in[5];
    const float* bk     = (const float*)d_in[6];
    const float* Wv     = (const float*)d_in[7];
    const float* bv     = (const float*)d_in[8];
    const float* Wo     = (const float*)d_in[9];
    const float* bo     = (const float*)d_in[10];
    const float* ln1_g  = (const float*)d_in[11];
    const float* ln1_b  = (const float*)d_in[12];
    const float* W1     = (const float*)d_in[13];
    const float* b1     = (const float*)d_in[14];
    const float* W2     = (const float*)d_in[15];
    const float* b2     = (const float*)d_in[16];
    const float* ln2_g  = (const float*)d_in[17];
    const float* ln2_b  = (const float*)d_in[18];
    const float* pool_W = (const float*)d_in[19];
    const float* pool_b = (const float*)d_in[20];
    const float* cW1    = (const float*)d_in[21];
    const float* cb1    = (const float*)d_in[22];
    const float* cW2    = (const float*)d_in[23];
    const float* cb2    = (const float*)d_in[24];

    float *ph, *ptmp;
    uint32_t *ph_hi, *ph_lo, *phd_hi, *phd_lo, *pff_hi, *pff_lo;
    uint32_t *pwo_hi, *pwo_lo, *pw1_hi, *pw1_lo, *pw2_hi, *pw2_lo;
    cudaGetSymbolAddress((void**)&ph, g_h);
    cudaGetSymbolAddress((void**)&ptmp, g_tmp);
    cudaGetSymbolAddress((void**)&ph_hi, g_h_hi);
    cudaGetSymbolAddress((void**)&ph_lo, g_h_lo);
    cudaGetSymbolAddress((void**)&phd_hi, g_hd_hi);
    cudaGetSymbolAddress((void**)&phd_lo, g_hd_lo);
    cudaGetSymbolAddress((void**)&pff_hi, g_ff_hi);
    cudaGetSymbolAddress((void**)&pff_lo, g_ff_lo);
    cudaGetSymbolAddress((void**)&pwo_hi, g_wo_hi);
    cudaGetSymbolAddress((void**)&pwo_lo, g_wo_lo);
    cudaGetSymbolAddress((void**)&pw1_hi, g_w1_hi);
    cudaGetSymbolAddress((void**)&pw1_lo, g_w1_lo);
    cudaGetSymbolAddress((void**)&pw2_hi, g_w2_hi);
    cudaGetSymbolAddress((void**)&pw2_lo, g_w2_lo);

    cudaFuncSetAttribute(gemm_ps, cudaFuncAttributeMaxDynamicSharedMemorySize, GPS_SMEM);

    // weight conversion (per layer)
    const int woN = D_ * D_ / 2, w1N = D_ * DFF_ / 2, w2N = DFF_ * D_ / 2;
    for (int l = 0; l < L_; l++) {
        convert_w<<<(woN + 255) / 256, 256>>>(Wo + (size_t)l * D_ * D_,
                                              pwo_hi + (size_t)l * woN, pwo_lo + (size_t)l * woN, D_, D_);
        convert_w<<<(w1N + 255) / 256, 256>>>(W1 + (size_t)l * D_ * DFF_,
                                              pw1_hi + (size_t)l * w1N, pw1_lo + (size_t)l * w1N, D_, DFF_);
        convert_w<<<(w2N + 255) / 256, 256>>>(W2 + (size_t)l * DFF_ * D_,
                                              pw2_hi + (size_t)l * w2N, pw2_lo + (size_t)l * w2N, DFF_, D_);
    }

    const dim3 gridIn(D_ / 64, NTOK / 64);
    const dim3 gridD(D_ / 64, NTOK / 128);     // N=320
    const dim3 gridF(DFF_ / 64, NTOK / 128);   // N=1280

    // input projection + bias + positional encoding (fp32)
    gemm64<<<gridIn, 256>>>(x, FIN_, in_W, D_, in_b, ph, D_, FIN_, FLAG_PE);

    for (int l = 0; l < L_; l++) {
        attn_fused<<<B_ * H_, 256>>>(ph, Wq, bq, Wk, bk, Wv, bv, l, phd_hi, phd_lo);
        // Wo: heads_packed @ Wo_t -> tmp fp32
        gemm_ps<<<gridD, 256, GPS_SMEM>>>(phd_hi, phd_lo, D_ / 2,
                                          pwo_hi + (size_t)l * woN, pwo_lo + (size_t)l * woN,
                                          bo + l * D_, ptmp, nullptr, nullptr, D_, 0);
        add_ln_warp<<<NTOK / 8, 256>>>(ph, ptmp, ln1_g + l * D_, ln1_b + l * D_,
                                       ph_hi, ph_lo, 1);
        // FFN1: h_packed @ W1_t -> ffn packed (relu)
        gemm_ps<<<gridF, 256, GPS_SMEM>>>(ph_hi, ph_lo, D_ / 2,
                                          pw1_hi + (size_t)l * w1N, pw1_lo + (size_t)l * w1N,
                                          b1 + l * DFF_, nullptr, pff_hi, pff_lo, DFF_,
                                          FLAG_RELU | FLAG_PACK);
        // FFN2: ffn_packed @ W2_t -> tmp fp32
        gemm_ps<<<gridD, 256, GPS_SMEM>>>(pff_hi, pff_lo, DFF_ / 2,
                                          pw2_hi + (size_t)l * w2N, pw2_lo + (size_t)l * w2N,
                                          b2 + l * D_, ptmp, nullptr, nullptr, D_, 0);
        add_ln_warp<<<NTOK / 8, 256>>>(ph, ptmp, ln2_g + l * D_, ln2_b + l * D_,
                                       nullptr, nullptr, 0);
    }

    pool_cls_kernel<<<B_, 320>>>(ph, pool_W, pool_b, cW1, cb1, cW2, cb2,
                                 (float*)d_out);
}

// round 10
// speedup vs baseline: 1.9683x; 1.0088x over previous
#include <cuda_runtime.h>
#include <cuda_bf16.h>
#include <math.h>
#include <stdint.h>

#define B_    4096
#define S_    30
#define FIN_  80
#define D_    320
#define H_    5
#define DH_   64
#define L_    4
#define DFF_  1280
#define NTOK  (B_ * S_)

#define FLAG_RELU 1
#define FLAG_PE   2
#define FLAG_PACK 4

// ---------------- scratch (device globals; no allocations allowed) ----------
__device__ float g_h[NTOK * D_];
__device__ float g_tmp[NTOK * D_];
__device__ uint32_t g_h_hi[NTOK * D_ / 2],   g_h_lo[NTOK * D_ / 2];
__device__ uint32_t g_hd_hi[NTOK * D_ / 2],  g_hd_lo[NTOK * D_ / 2];
__device__ uint32_t g_ff_hi[NTOK * DFF_ / 2], g_ff_lo[NTOK * DFF_ / 2];
__device__ uint32_t g_wo_hi[L_ * D_ * D_ / 2],   g_wo_lo[L_ * D_ * D_ / 2];
__device__ uint32_t g_w1_hi[L_ * D_ * DFF_ / 2], g_w1_lo[L_ * D_ * DFF_ / 2];
__device__ uint32_t g_w2_hi[L_ * DFF_ * D_ / 2], g_w2_lo[L_ * DFF_ * D_ / 2];

// ---------------- helpers --------------------------------------------------
__device__ __forceinline__ uint32_t smem_u32(const void* p) {
    uint32_t a;
    asm("{ .reg .u64 t; cvta.to.shared.u64 t, %1; cvt.u32.u64 %0, t; }"
        : "=r"(a) : "l"(p));
    return a;
}

__device__ __forceinline__ void split2(float v0, float v1, uint32_t& hi, uint32_t& lo) {
    asm("cvt.rn.bf16x2.f32 %0, %1, %2;" : "=r"(hi) : "f"(v1), "f"(v0));
    float h0 = __uint_as_float(hi << 16);
    float h1 = __uint_as_float(hi & 0xffff0000u);
    asm("cvt.rn.bf16x2.f32 %0, %1, %2;" : "=r"(lo) : "f"(v1 - h1), "f"(v0 - h0));
}

__device__ __forceinline__ void mma_bf16(float* c, const uint32_t* a, const uint32_t* b) {
    asm volatile(
        "mma.sync.aligned.m16n8k16.row.col.f32.bf16.bf16.f32 "
        "{%0,%1,%2,%3}, {%4,%5,%6,%7}, {%8,%9}, {%0,%1,%2,%3};\n"
        : "+f"(c[0]), "+f"(c[1]), "+f"(c[2]), "+f"(c[3])
        : "r"(a[0]), "r"(a[1]), "r"(a[2]), "r"(a[3]), "r"(b[0]), "r"(b[1]));
}

__device__ __forceinline__ void ldm_x4(uint32_t* r, uint32_t addr) {
    asm volatile("ldmatrix.sync.aligned.m8n8.x4.shared.b16 {%0,%1,%2,%3}, [%4];"
        : "=r"(r[0]), "=r"(r[1]), "=r"(r[2]), "=r"(r[3]) : "r"(addr));
}

__device__ __forceinline__ void cp16(uint32_t dst, const uint32_t* src) {
    asm volatile("cp.async.cg.shared.global [%0], [%1], 16;" :: "r"(dst), "l"(src));
}
#define CP_COMMIT() asm volatile("cp.async.commit_group;" ::: "memory")
#define CP_WAIT0()  asm volatile("cp.async.wait_group 0;" ::: "memory")
#define CP_WAIT1()  asm volatile("cp.async.wait_group 1;" ::: "memory")

// ---------------- weight conversion: W[K][N] -> Wt_hi/lo [N][K/2] ----------
__global__ void convert_w(const float* __restrict__ W,
                          uint32_t* __restrict__ hi, uint32_t* __restrict__ lo,
                          int K, int N)
{
    int idx = blockIdx.x * 256 + threadIdx.x;
    int K2 = K >> 1;
    if (idx >= N * K2) return;
    int n = idx / K2, k2 = idx % K2;
    float v0 = W[(size_t)(2 * k2) * N + n];
    float v1 = W[(size_t)(2 * k2 + 1) * N + n];
    uint32_t h, l;
    split2(v0, v1, h, l);
    hi[idx] = h; lo[idx] = l;
}

// ======================================================================
// Pre-split bf16 GEMM, single-sync 3-stage cp.async pipeline.
// A packed hi/lo [M][K2] u32; B packed transposed [N][K2] u32.
// BM=128, BK=32 (16 u32), 256 thr.
//   BN=64:  8 warps 4x2, warp tile 32x32 (MT=2)
//   BN=128: 8 warps 2x4, warp tile 64x32 (MT=4)
// smem row stride 20 u32 (80B = 5x16: cp.async-aligned, ldmatrix
// conflict-free). Stage = 20480 + BN*160 bytes; 3 stages.
// ======================================================================
template<int BN, int MT>
__global__ __launch_bounds__(256) void gemm_ps(
    const uint32_t* __restrict__ Ahi, const uint32_t* __restrict__ Alo, int K2,
    const uint32_t* __restrict__ Bhi, const uint32_t* __restrict__ Blo,
    const float* __restrict__ bias,
    float* __restrict__ C, uint32_t* __restrict__ Chi, uint32_t* __restrict__ Clo,
    int N, int flags)
{
    constexpr int ST   = 20;                 // u32 per smem row (80B, 16B-mult)
    constexpr int SAH  = 0;
    constexpr int SAL  = 128 * ST * 4;       // 10240
    constexpr int SBH  = 2 * SAL;            // 20480
    constexpr int SBL  = SBH + BN * ST * 4;
    constexpr int STAGE = SBH + 2 * BN * ST * 4;

    extern __shared__ __align__(1024) char smem[];
    const uint32_t sbase = smem_u32(smem);
    const int tid = threadIdx.x;
    const int lane = tid & 31;
    const int w = tid >> 5;
    const int g = lane >> 2, t4 = lane & 3;
    const int wm = (BN == 64) ? (w >> 1) * 32 : (w >> 2) * 64;
    const int wn = (BN == 64) ? (w & 1) * 32 : (w & 3) * 32;

    const size_t rowBase = (size_t)blockIdx.y * 128;
    const int    colBase = blockIdx.x * BN;

    const uint32_t* Ah_g = Ahi + rowBase * K2;
    const uint32_t* Al_g = Alo + rowBase * K2;
    const uint32_t* Bh_g = Bhi + (size_t)colBase * K2;
    const uint32_t* Bl_g = Blo + (size_t)colBase * K2;

    float acc[MT][4][4];
#pragma unroll
    for (int mt = 0; mt < MT; mt++)
#pragma unroll
        for (int nt = 0; nt < 4; nt++)
#pragma unroll
            for (int i = 0; i < 4; i++) acc[mt][nt][i] = 0.f;

    auto stage = [&](int it, int slot) {
        uint32_t sb = sbase + slot * STAGE;
        int k2o = it * 16;
#pragma unroll
        for (int j = 0; j < 2; j++) {
            int idx = tid + j * 256;
            int row = idx >> 2, ch = (idx & 3) * 4;
            uint32_t so = (uint32_t)(row * ST + ch) * 4;
            const size_t go = (size_t)row * K2 + k2o + ch;
            cp16(sb + SAH + so, Ah_g + go);
            cp16(sb + SAL + so, Al_g + go);
        }
#pragma unroll
        for (int j = 0; j < BN / 64; j++) {
            int idx = tid + j * 256;
            int row = idx >> 2, ch = (idx & 3) * 4;
            uint32_t so = (uint32_t)(row * ST + ch) * 4;
            const size_t go = (size_t)row * K2 + k2o + ch;
            cp16(sb + SBH + so, Bh_g + go);
            cp16(sb + SBL + so, Bl_g + go);
        }
    };

    auto compute = [&](int slot) {
        uint32_t sb = sbase + slot * STAGE;
#pragma unroll
        for (int s = 0; s < 2; s++) {
            const int s8 = s * 8;
            uint32_t ah[MT][4], al[MT][4], bh[4][2], bl[4][2];
#pragma unroll
            for (int mt = 0; mt < MT; mt++) {
                int row = wm + mt * 16 + (lane & 15);
                uint32_t off = (uint32_t)(row * ST + s8 + ((lane >> 4) << 2)) * 4;
                ldm_x4(ah[mt], sb + SAH + off);
                ldm_x4(al[mt], sb + SAL + off);
            }
#pragma unroll
            for (int h2 = 0; h2 < 2; h2++) {
                int row = wn + h2 * 16 + (lane & 7) + ((lane >> 4) << 3);
                uint32_t off = (uint32_t)(row * ST + s8 + ((lane & 8) >> 1)) * 4;
                uint32_t t[4];
                ldm_x4(t, sb + SBH + off);
                bh[h2 * 2][0] = t[0]; bh[h2 * 2][1] = t[1];
                bh[h2 * 2 + 1][0] = t[2]; bh[h2 * 2 + 1][1] = t[3];
                ldm_x4(t, sb + SBL + off);
                bl[h2 * 2][0] = t[0]; bl[h2 * 2][1] = t[1];
                bl[h2 * 2 + 1][0] = t[2]; bl[h2 * 2 + 1][1] = t[3];
            }
#pragma unroll
            for (int mt = 0; mt < MT; mt++)
#pragma unroll
                for (int nt = 0; nt < 4; nt++) {
                    mma_bf16(acc[mt][nt], ah[mt], bl[nt]);
                    mma_bf16(acc[mt][nt], al[mt], bh[nt]);
                    mma_bf16(acc[mt][nt], ah[mt], bh[nt]);
                }
        }
    };

    const int nIter = K2 >> 4;   // K/32  (>= 10 always)
    stage(0, 0); CP_COMMIT();
    stage(1, 1); CP_COMMIT();
    for (int it = 0; it < nIter; it++) {
        if (it + 1 < nIter) { CP_WAIT1(); } else { CP_WAIT0(); }
        __syncthreads();
        compute(it % 3);
        if (it + 2 < nIter) {
            stage(it + 2, (it + 2) % 3);
            CP_COMMIT();
        }
    }

    // epilogue
#pragma unroll
    for (int mt = 0; mt < MT; mt++) {
        size_t r0 = rowBase + wm + mt * 16 + g;
#pragma unroll
        for (int nt = 0; nt < 4; nt++) {
            int col = colBase + wn + nt * 8 + t4 * 2;
            float2 bs = *(const float2*)&bias[col];
            float v0 = acc[mt][nt][0] + bs.x;
            float v1 = acc[mt][nt][1] + bs.y;
            float v2 = acc[mt][nt][2] + bs.x;
            float v3 = acc[mt][nt][3] + bs.y;
            if (flags & FLAG_RELU) {
                v0 = fmaxf(v0, 0.f); v1 = fmaxf(v1, 0.f);
                v2 = fmaxf(v2, 0.f); v3 = fmaxf(v3, 0.f);
            }
            if (flags & FLAG_PACK) {
                int N2 = N >> 1, c2 = col >> 1;
                uint32_t h, l;
                split2(v0, v1, h, l);
                Chi[r0 * N2 + c2] = h; Clo[r0 * N2 + c2] = l;
                split2(v2, v3, h, l);
                Chi[(r0 + 8) * N2 + c2] = h; Clo[(r0 + 8) * N2 + c2] = l;
            } else {
                *(float2*)&C[r0 * N + col]       = make_float2(v0, v1);
                *(float2*)&C[(r0 + 8) * N + col] = make_float2(v2, v3);
            }
        }
    }
}

#define GPS_SMEM64  (3 * (20480 + 64 * 160))    // 92160
#define GPS_SMEM128 (3 * (20480 + 128 * 160))   // 122880

// ---------------- fp32 tiled SGEMM (input projection only; PE epilogue) ----
__global__ __launch_bounds__(256) void gemm64(
    const float* __restrict__ A, int lda,
    const float* __restrict__ Bw, int ldb,
    const float* __restrict__ bias,
    float* __restrict__ C, int ldc,
    int K, int flags)
{
    __shared__ __align__(16) float As[16][65];
    __shared__ __align__(16) float Bs[16][64];

    int tid = threadIdx.x;
    int ty = tid >> 4, tx = tid & 15;
    size_t rowBase = (size_t)blockIdx.y * 64;
    int colBase = blockIdx.x * 64;
    const float* Ab = A + rowBase * (size_t)lda;
    const float* Bb = Bw + colBase;

    float acc[4][4];
#pragma unroll
    for (int i = 0; i < 4; i++)
#pragma unroll
        for (int j = 0; j < 4; j++) acc[i][j] = 0.f;

    for (int k0 = 0; k0 < K; k0 += 16) {
#pragma unroll
        for (int i = 0; i < 4; i++) {
            int e = tid + i * 256;
            int r = e >> 4, c = e & 15;
            As[c][r] = Ab[(size_t)r * lda + (k0 + c)];
        }
#pragma unroll
        for (int i = 0; i < 4; i++) {
            int e = tid + i * 256;
            int r = e >> 6, c = e & 63;
            Bs[r][c] = Bb[(size_t)(k0 + r) * ldb + c];
        }
        __syncthreads();
#pragma unroll
        for (int k = 0; k < 16; k++) {
            float a0 = As[k][ty * 4 + 0];
            float a1 = As[k][ty * 4 + 1];
            float a2 = As[k][ty * 4 + 2];
            float a3 = As[k][ty * 4 + 3];
            float4 b = *(const float4*)&Bs[k][tx * 4];
            acc[0][0] += a0 * b.x; acc[0][1] += a0 * b.y; acc[0][2] += a0 * b.z; acc[0][3] += a0 * b.w;
            acc[1][0] += a1 * b.x; acc[1][1] += a1 * b.y; acc[1][2] += a1 * b.z; acc[1][3] += a1 * b.w;
            acc[2][0] += a2 * b.x; acc[2][1] += a2 * b.y; acc[2][2] += a2 * b.z; acc[2][3] += a2 * b.w;
            acc[3][0] += a3 * b.x; acc[3][1] += a3 * b.y; acc[3][2] += a3 * b.z; acc[3][3] += a3 * b.w;
        }
        __syncthreads();
    }

    int row0 = (int)rowBase + ty * 4;
    int col0 = colBase + tx * 4;
#pragma unroll
    for (int i = 0; i < 4; i++) {
        int row = row0 + i;
#pragma unroll
        for (int j = 0; j < 4; j++) {
            int col = col0 + j;
            float v = acc[i][j] + bias[col];
            if (flags & FLAG_PE) {
                int s = row % S_;
                int half = col >> 1;
                float div = expf((float)(2 * half) * (-9.210340371976184f / (float)D_));
                float arg = (float)s * div;
                v += (col & 1) ? cosf(arg) : sinf(arg);
            }
            if (flags & FLAG_RELU) v = fmaxf(v, 0.f);
            C[(size_t)row * ldc + col] = v;
        }
    }
}

// ---------------- fused QKV projection + attention: block per (b, h) -------
__global__ __launch_bounds__(256) void attn_fused(
    const float* __restrict__ hsrc,
    const float* __restrict__ Wq, const float* __restrict__ bq,
    const float* __restrict__ Wk, const float* __restrict__ bk,
    const float* __restrict__ Wv, const float* __restrict__ bv,
    int l, uint32_t* __restrict__ headsHi, uint32_t* __restrict__ headsLo)
{
    __shared__ float sh[S_][DH_ + 1];
    __shared__ float sq[S_][DH_ + 1];
    __shared__ float sk[S_][DH_ + 1];
    __shared__ float sv[S_][DH_ + 1];
    __shared__ float sc[S_][S_ + 1];

    int bh = blockIdx.x;
    int b = bh / H_, h = bh % H_;
    size_t base = ((size_t)b * S_) * D_ + (size_t)h * DH_;
    int tid = threadIdx.x;

    for (int e = tid; e < S_ * DH_; e += 256) {
        int s = e >> 6, d = e & 63;
        sh[s][d] = hsrc[base + (size_t)s * D_ + d];
    }
    __syncthreads();

    size_t woff = ((size_t)l * H_ + h) * DH_ * DH_;
    size_t boff = ((size_t)l * H_ + h) * DH_;
    const float* Wqh = Wq + woff;
    const float* Wkh = Wk + woff;
    const float* Wvh = Wv + woff;

    {
        int e = tid & 63;
        for (int r = tid >> 6; r < 3 * S_; r += 4) {
            int m = r / S_, s = r % S_;
            const float* Wm = (m == 0) ? Wqh : (m == 1) ? Wkh : Wvh;
            const float* bm = (m == 0) ? (bq + boff) : (m == 1) ? (bk + boff) : (bv + boff);
            float acc = bm[e];
#pragma unroll 16
            for (int d = 0; d < DH_; d++) acc += sh[s][d] * Wm[d * DH_ + e];
            if (m == 0) sq[s][e] = acc;
            else if (m == 1) sk[s][e] = acc;
            else sv[s][e] = acc;
        }
    }
    __syncthreads();

    for (int e = tid; e < S_ * S_; e += 256) {
        int i = e / S_, j = e % S_;
        float acc = 0.f;
#pragma unroll
        for (int d = 0; d < DH_; d++) acc += sq[i][d] * sk[j][d];
        sc[i][j] = acc * 0.125f;
    }
    __syncthreads();

    if (tid < S_) {
        float m = -1e30f;
        for (int j = 0; j < S_; j++) m = fmaxf(m, sc[tid][j]);
        float sum = 0.f;
        for (int j = 0; j < S_; j++) {
            float e2 = expf(sc[tid][j] - m);
            sc[tid][j] = e2;
            sum += e2;
        }
        float inv = 1.f / sum;
        for (int j = 0; j < S_; j++) sc[tid][j] *= inv;
    }
    __syncthreads();

    // A @ V -> packed bf16 hi/lo pairs
    size_t tokBase = (size_t)b * S_;
    for (int e = tid; e < S_ * 32; e += 256) {
        int s = e >> 5, p = e & 31;
        int d0 = p * 2;
        float a0 = 0.f, a1 = 0.f;
#pragma unroll
        for (int j = 0; j < S_; j++) {
            a0 += sc[s][j] * sv[j][d0];
            a1 += sc[s][j] * sv[j][d0 + 1];
        }
        uint32_t hh, ll;
        split2(a0, a1, hh, ll);
        size_t off = (tokBase + s) * (D_ / 2) + h * 32 + p;
        headsHi[off] = hh;
        headsLo[off] = ll;
    }
}

// ---------------- residual add + LayerNorm: warp per token -----------------
__global__ __launch_bounds__(256) void add_ln_warp(
    float* __restrict__ hb, const float* __restrict__ add,
    const float* __restrict__ gamma, const float* __restrict__ beta,
    uint32_t* __restrict__ outHi, uint32_t* __restrict__ outLo, int pack)
{
    int w = threadIdx.x >> 5, lane = threadIdx.x & 31;
    size_t tok = (size_t)blockIdx.x * 8 + w;
    size_t base = tok * D_;

    float2 v[5];
    float s = 0.f;
#pragma unroll
    for (int i = 0; i < 5; i++) {
        int d = lane * 2 + i * 64;
        float2 a = *(const float2*)&hb[base + d];
        float2 r = *(const float2*)&add[base + d];
        v[i].x = a.x + r.x;
        v[i].y = a.y + r.y;
        s += v[i].x + v[i].y;
    }
#pragma unroll
    for (int o = 16; o; o >>= 1) s += __shfl_xor_sync(0xffffffffu, s, o);
    float mean = s * (1.f / (float)D_);

    float s2 = 0.f;
#pragma unroll
    for (int i = 0; i < 5; i++) {
        float dx = v[i].x - mean, dy = v[i].y - mean;
        s2 += dx * dx + dy * dy;
    }
#pragma unroll
    for (int o = 16; o; o >>= 1) s2 += __shfl_xor_sync(0xffffffffu, s2, o);
    float rstd = rsqrtf(s2 * (1.f / (float)D_) + 1e-5f);

#pragma unroll
    for (int i = 0; i < 5; i++) {
        int d = lane * 2 + i * 64;
        float o0 = (v[i].x - mean) * rstd * gamma[d] + beta[d];
        float o1 = (v[i].y - mean) * rstd * gamma[d + 1] + beta[d + 1];
        *(float2*)&hb[base + d] = make_float2(o0, o1);
        if (pack) {
            uint32_t hh, ll;
            split2(o0, o1, hh, ll);
            outHi[tok * (D_ / 2) + lane + i * 32] = hh;
            outLo[tok * (D_ / 2) + lane + i * 32] = ll;
        }
    }
}

// ---------------- attention pooling + classifier (block per batch row) -----
__global__ __launch_bounds__(320) void pool_cls_kernel(
    const float* __restrict__ hb,
    const float* __restrict__ pool_W, const float* __restrict__ pool_b,
    const float* __restrict__ W1, const float* __restrict__ b1,
    const float* __restrict__ W2, const float* __restrict__ b2,
    float* __restrict__ out)
{
    __shared__ float sscore[S_];
    __shared__ float sz[D_];
    __shared__ float shid[D_ / 2];
    __shared__ float sred[10];

    int b = blockIdx.x;
    int t = threadIdx.x, warp = t >> 5, lane = t & 31;
    const float* hrow = hb + (size_t)b * S_ * D_;

    for (int s = warp; s < S_; s += 10) {
        float acc = 0.f;
        for (int d = lane; d < D_; d += 32) acc += hrow[s * D_ + d] * pool_W[d];
#pragma unroll
        for (int o = 16; o; o >>= 1) acc += __shfl_down_sync(0xffffffffu, acc, o);
        if (lane == 0) sscore[s] = acc + pool_b[0];
    }
    __syncthreads();

    if (t == 0) {
        float m = -1e30f;
        for (int s = 0; s < S_; s++) m = fmaxf(m, sscore[s]);
        float sum = 0.f;
        for (int s = 0; s < S_; s++) {
            float e = expf(sscore[s] - m);
            sscore[s] = e;
            sum += e;
        }
        float inv = 1.f / sum;
        for (int s = 0; s < S_; s++) sscore[s] *= inv;
    }
    __syncthreads();

    {
        float acc = 0.f;
        for (int s = 0; s < S_; s++) acc += sscore[s] * hrow[s * D_ + t];
        sz[t] = acc;
    }
    __syncthreads();

    if (t < D_ / 2) {
        float acc = b1[t];
        for (int d = 0; d < D_; d++) acc += sz[d] * W1[d * (D_ / 2) + t];
        shid[t] = fmaxf(acc, 0.f);
    }
    __syncthreads();

    float p = (t < D_ / 2) ? shid[t] * W2[t] : 0.f;
#pragma unroll
    for (int o = 16; o; o >>= 1) p += __shfl_down_sync(0xffffffffu, p, o);
    if (lane == 0) sred[warp] = p;
    __syncthreads();
    if (t == 0) {
        float tot = 0.f;
        for (int i = 0; i < 10; i++) tot += sred[i];
        float logit = tot + b2[0];
        out[b] = logit;
        out[B_ + b] = 1.f / (1.f + expf(-logit));
    }
}

// ---------------- host launcher -------------------------------------------
extern "C" void kernel_launch(void* const* d_in, const int* in_sizes, int n_in,
                              void* d_out, int out_size)
{
    const float* x      = (const float*)d_in[0];
    const float* in_W   = (const float*)d_in[1];
    const float* in_b   = (const float*)d_in[2];
    const float* Wq     = (const float*)d_in[3];
    const float* bq     = (const float*)d_in[4];
    const float* Wk     = (const float*)d_in[5];
    const float* bk     = (const float*)d_in[6];
    const float* Wv     = (const float*)d_in[7];
    const float* bv     = (const float*)d_in[8];
    const float* Wo     = (const float*)d_in[9];
    const float* bo     = (const float*)d_in[10];
    const float* ln1_g  = (const float*)d_in[11];
    const float* ln1_b  = (const float*)d_in[12];
    const float* W1     = (const float*)d_in[13];
    const float* b1     = (const float*)d_in[14];
    const float* W2     = (const float*)d_in[15];
    const float* b2     = (const float*)d_in[16];
    const float* ln2_g  = (const float*)d_in[17];
    const float* ln2_b  = (const float*)d_in[18];
    const float* pool_W = (const float*)d_in[19];
    const float* pool_b = (const float*)d_in[20];
    const float* cW1    = (const float*)d_in[21];
    const float* cb1    = (const float*)d_in[22];
    const float* cW2    = (const float*)d_in[23];
    const float* cb2    = (const float*)d_in[24];

    float *ph, *ptmp;
    uint32_t *ph_hi, *ph_lo, *phd_hi, *phd_lo, *pff_hi, *pff_lo;
    uint32_t *pwo_hi, *pwo_lo, *pw1_hi, *pw1_lo, *pw2_hi, *pw2_lo;
    cudaGetSymbolAddress((void**)&ph, g_h);
    cudaGetSymbolAddress((void**)&ptmp, g_tmp);
    cudaGetSymbolAddress((void**)&ph_hi, g_h_hi);
    cudaGetSymbolAddress((void**)&ph_lo, g_h_lo);
    cudaGetSymbolAddress((void**)&phd_hi, g_hd_hi);
    cudaGetSymbolAddress((void**)&phd_lo, g_hd_lo);
    cudaGetSymbolAddress((void**)&pff_hi, g_ff_hi);
    cudaGetSymbolAddress((void**)&pff_lo, g_ff_lo);
    cudaGetSymbolAddress((void**)&pwo_hi, g_wo_hi);
    cudaGetSymbolAddress((void**)&pwo_lo, g_wo_lo);
    cudaGetSymbolAddress((void**)&pw1_hi, g_w1_hi);
    cudaGetSymbolAddress((void**)&pw1_lo, g_w1_lo);
    cudaGetSymbolAddress((void**)&pw2_hi, g_w2_hi);
    cudaGetSymbolAddress((void**)&pw2_lo, g_w2_lo);

    cudaFuncSetAttribute(gemm_ps<64, 2>,
                         cudaFuncAttributeMaxDynamicSharedMemorySize, GPS_SMEM64);
    cudaFuncSetAttribute(gemm_ps<128, 4>,
                         cudaFuncAttributeMaxDynamicSharedMemorySize, GPS_SMEM128);

    // weight conversion (per layer)
    const int woN = D_ * D_ / 2, w1N = D_ * DFF_ / 2, w2N = DFF_ * D_ / 2;
    for (int l = 0; l < L_; l++) {
        convert_w<<<(woN + 255) / 256, 256>>>(Wo + (size_t)l * D_ * D_,
                                              pwo_hi + (size_t)l * woN, pwo_lo + (size_t)l * woN, D_, D_);
        convert_w<<<(w1N + 255) / 256, 256>>>(W1 + (size_t)l * D_ * DFF_,
                                              pw1_hi + (size_t)l * w1N, pw1_lo + (size_t)l * w1N, D_, DFF_);
        convert_w<<<(w2N + 255) / 256, 256>>>(W2 + (size_t)l * DFF_ * D_,
                                              pw2_hi + (size_t)l * w2N, pw2_lo + (size_t)l * w2N, DFF_, D_);
    }

    const dim3 gridIn(D_ / 64, NTOK / 64);
    const dim3 gridD(D_ / 64, NTOK / 128);       // BN=64, N=320
    const dim3 gridF(DFF_ / 128, NTOK / 128);    // BN=128, N=1280

    // input projection + bias + positional encoding (fp32)
    gemm64<<<gridIn, 256>>>(x, FIN_, in_W, D_, in_b, ph, D_, FIN_, FLAG_PE);

    for (int l = 0; l < L_; l++) {
        attn_fused<<<B_ * H_, 256>>>(ph, Wq, bq, Wk, bk, Wv, bv, l, phd_hi, phd_lo);
        // Wo: heads_packed @ Wo_t -> tmp fp32   (BN=64)
        gemm_ps<64, 2><<<gridD, 256, GPS_SMEM64>>>(phd_hi, phd_lo, D_ / 2,
                                          pwo_hi + (size_t)l * woN, pwo_lo + (size_t)l * woN,
                                          bo + l * D_, ptmp, nullptr, nullptr, D_, 0);
        add_ln_warp<<<NTOK / 8, 256>>>(ph, ptmp, ln1_g + l * D_, ln1_b + l * D_,
                                       ph_hi, ph_lo, 1);
        // FFN1: h_packed @ W1_t -> ffn packed (relu)   (BN=128)
        gemm_ps<128, 4><<<gridF, 256, GPS_SMEM128>>>(ph_hi, ph_lo, D_ / 2,
                                          pw1_hi + (size_t)l * w1N, pw1_lo + (size_t)l * w1N,
                                          b1 + l * DFF_, nullptr, pff_hi, pff_lo, DFF_,
                                          FLAG_RELU | FLAG_PACK);
        // FFN2: ffn_packed @ W2_t -> tmp fp32   (BN=64)
        gemm_ps<64, 2><<<gridD, 256, GPS_SMEM64>>>(pff_hi, pff_lo, DFF_ / 2,
                                          pw2_hi + (size_t)l * w2N, pw2_lo + (size_t)l * w2N,
                                          b2 + l * D_, ptmp, nullptr, nullptr, D_, 0);
        add_ln_warp<<<NTOK / 8, 256>>>(ph, ptmp, ln2_g + l * D_, ln2_b + l * D_,
                                       nullptr, nullptr, 0);
    }

    pool_cls_kernel<<<B_, 320>>>(ph, pool_W, pool_b, cW1, cb1, cW2, cb2,
                                 (float*)d_out);
}

// round 11
// speedup vs baseline: 2.5289x; 1.2848x over previous
#include <cuda_runtime.h>
#include <cuda_fp16.h>
#include <math.h>
#include <stdint.h>

#define B_    4096
#define S_    30
#define FIN_  80
#define D_    320
#define H_    5
#define DH_   64
#define L_    4
#define DFF_  1280
#define NTOK  (B_ * S_)

#define FLAG_RELU 1
#define FLAG_PE   2
#define FLAG_PACK 4

// ---------------- scratch (device globals; no allocations allowed) ----------
__device__ float g_h[NTOK * D_];
__device__ float g_tmp[NTOK * D_];
__device__ uint32_t g_ha[NTOK * D_ / 2];      // h packed fp16x2 (FFN1 A)
__device__ uint32_t g_hd[NTOK * D_ / 2];      // heads packed fp16x2 (Wo A)
__device__ uint32_t g_ff[NTOK * DFF_ / 2];    // ffn packed fp16x2 (FFN2 A)
__device__ uint32_t g_wo_hi[L_ * D_ * D_ / 2],   g_wo_lo[L_ * D_ * D_ / 2];
__device__ uint32_t g_w1_hi[L_ * D_ * DFF_ / 2], g_w1_lo[L_ * D_ * DFF_ / 2];
__device__ uint32_t g_w2_hi[L_ * DFF_ * D_ / 2], g_w2_lo[L_ * DFF_ * D_ / 2];

// ---------------- helpers --------------------------------------------------
__device__ __forceinline__ uint32_t smem_u32(const void* p) {
    uint32_t a;
    asm("{ .reg .u64 t; cvta.to.shared.u64 t, %1; cvt.u32.u64 %0, t; }"
        : "=r"(a) : "l"(p));
    return a;
}

__device__ __forceinline__ uint32_t pack2h(float v0, float v1) {
    __half2 h = __floats2half2_rn(v0, v1);
    return *reinterpret_cast<uint32_t*>(&h);
}

// fp16 hi/lo split, packed pairs (v0 low half, v1 high half)
__device__ __forceinline__ void split2h(float v0, float v1, uint32_t& hi, uint32_t& lo) {
    __half2 h = __floats2half2_rn(v0, v1);
    float2 hf = __half22float2(h);
    __half2 l = __floats2half2_rn(v0 - hf.x, v1 - hf.y);
    hi = *reinterpret_cast<uint32_t*>(&h);
    lo = *reinterpret_cast<uint32_t*>(&l);
}

__device__ __forceinline__ void mma_f16(float* c, const uint32_t* a, const uint32_t* b) {
    asm volatile(
        "mma.sync.aligned.m16n8k16.row.col.f32.f16.f16.f32 "
        "{%0,%1,%2,%3}, {%4,%5,%6,%7}, {%8,%9}, {%0,%1,%2,%3};\n"
        : "+f"(c[0]), "+f"(c[1]), "+f"(c[2]), "+f"(c[3])
        : "r"(a[0]), "r"(a[1]), "r"(a[2]), "r"(a[3]), "r"(b[0]), "r"(b[1]));
}

__device__ __forceinline__ void ldm_x4(uint32_t* r, uint32_t addr) {
    asm volatile("ldmatrix.sync.aligned.m8n8.x4.shared.b16 {%0,%1,%2,%3}, [%4];"
        : "=r"(r[0]), "=r"(r[1]), "=r"(r[2]), "=r"(r[3]) : "r"(addr));
}

__device__ __forceinline__ void cp16(uint32_t dst, const uint32_t* src) {
    asm volatile("cp.async.cg.shared.global [%0], [%1], 16;" :: "r"(dst), "l"(src));
}
#define CP_COMMIT() asm volatile("cp.async.commit_group;" ::: "memory")
#define CP_WAIT0()  asm volatile("cp.async.wait_group 0;" ::: "memory")
#define CP_WAIT1()  asm volatile("cp.async.wait_group 1;" ::: "memory")

// ---------------- weight conversion: W[K][N] -> fp16 hi/lo [N][K/2] --------
__global__ void convert_w(const float* __restrict__ W,
                          uint32_t* __restrict__ hi, uint32_t* __restrict__ lo,
                          int K, int N)
{
    int idx = blockIdx.x * 256 + threadIdx.x;
    int K2 = K >> 1;
    if (idx >= N * K2) return;
    int n = idx / K2, k2 = idx % K2;
    float v0 = W[(size_t)(2 * k2) * N + n];
    float v1 = W[(size_t)(2 * k2 + 1) * N + n];
    uint32_t h, l;
    split2h(v0, v1, h, l);
    hi[idx] = h; lo[idx] = l;
}

// ======================================================================
// 2-term fp16 GEMM: C = A @ (Bh + Bl) + bias [+relu] [packed out]
// A single fp16x2 [M][K2]; B hi/lo fp16x2 transposed [N][K2].
// BM=128, BK=32 (16 u32), 256 thr; single-sync 3-stage cp.async pipe.
//   BN=64:  8 warps 4x2, warp tile 32x32 (MT=2)
//   BN=128: 8 warps 2x4, warp tile 64x32 (MT=4)
// smem row stride 20 u32 (80B, 16B-aligned, ldmatrix conflict-free).
// Stage = 10240 + BN*160 bytes; 3 stages.
// ======================================================================
template<int BN, int MT>
__global__ __launch_bounds__(256) void gemm_ps(
    const uint32_t* __restrict__ Apk, int K2,
    const uint32_t* __restrict__ Bhi, const uint32_t* __restrict__ Blo,
    const float* __restrict__ bias,
    float* __restrict__ C, uint32_t* __restrict__ Cpk,
    int N, int flags)
{
    constexpr int ST   = 20;
    constexpr int SA   = 0;
    constexpr int SBH  = 128 * ST * 4;       // 10240
    constexpr int SBL  = SBH + BN * ST * 4;
    constexpr int STAGE = SBH + 2 * BN * ST * 4;

    extern __shared__ __align__(1024) char smem[];
    const uint32_t sbase = smem_u32(smem);
    const int tid = threadIdx.x;
    const int lane = tid & 31;
    const int w = tid >> 5;
    const int g = lane >> 2, t4 = lane & 3;
    const int wm = (BN == 64) ? (w >> 1) * 32 : (w >> 2) * 64;
    const int wn = (BN == 64) ? (w & 1) * 32 : (w & 3) * 32;

    const size_t rowBase = (size_t)blockIdx.y * 128;
    const int    colBase = blockIdx.x * BN;

    const uint32_t* A_g  = Apk + rowBase * K2;
    const uint32_t* Bh_g = Bhi + (size_t)colBase * K2;
    const uint32_t* Bl_g = Blo + (size_t)colBase * K2;

    float acc[MT][4][4];
#pragma unroll
    for (int mt = 0; mt < MT; mt++)
#pragma unroll
        for (int nt = 0; nt < 4; nt++)
#pragma unroll
            for (int i = 0; i < 4; i++) acc[mt][nt][i] = 0.f;

    auto stage = [&](int it, int slot) {
        uint32_t sb = sbase + slot * STAGE;
        int k2o = it * 16;
#pragma unroll
        for (int j = 0; j < 2; j++) {       // A: 128 rows x 4 chunks
            int idx = tid + j * 256;
            int row = idx >> 2, ch = (idx & 3) * 4;
            uint32_t so = (uint32_t)(row * ST + ch) * 4;
            cp16(sb + SA + so, A_g + (size_t)row * K2 + k2o + ch);
        }
#pragma unroll
        for (int j = 0; j < BN / 64; j++) { // B: BN rows x 4 chunks, hi+lo
            int idx = tid + j * 256;
            int row = idx >> 2, ch = (idx & 3) * 4;
            uint32_t so = (uint32_t)(row * ST + ch) * 4;
            const size_t go = (size_t)row * K2 + k2o + ch;
            cp16(sb + SBH + so, Bh_g + go);
            cp16(sb + SBL + so, Bl_g + go);
        }
    };

    auto compute = [&](int slot) {
        uint32_t sb = sbase + slot * STAGE;
#pragma unroll
        for (int s = 0; s < 2; s++) {
            const int s8 = s * 8;
            uint32_t ah[MT][4], bh[4][2], bl[4][2];
#pragma unroll
            for (int mt = 0; mt < MT; mt++) {
                int row = wm + mt * 16 + (lane & 15);
                uint32_t off = (uint32_t)(row * ST + s8 + ((lane >> 4) << 2)) * 4;
                ldm_x4(ah[mt], sb + SA + off);
            }
#pragma unroll
            for (int h2 = 0; h2 < 2; h2++) {
                int row = wn + h2 * 16 + (lane & 7) + ((lane >> 4) << 3);
                uint32_t off = (uint32_t)(row * ST + s8 + ((lane & 8) >> 1)) * 4;
                uint32_t t[4];
                ldm_x4(t, sb + SBH + off);
                bh[h2 * 2][0] = t[0]; bh[h2 * 2][1] = t[1];
                bh[h2 * 2 + 1][0] = t[2]; bh[h2 * 2 + 1][1] = t[3];
                ldm_x4(t, sb + SBL + off);
                bl[h2 * 2][0] = t[0]; bl[h2 * 2][1] = t[1];
                bl[h2 * 2 + 1][0] = t[2]; bl[h2 * 2 + 1][1] = t[3];
            }
#pragma unroll
            for (int mt = 0; mt < MT; mt++)
#pragma unroll
                for (int nt = 0; nt < 4; nt++) {
                    mma_f16(acc[mt][nt], ah[mt], bl[nt]);
                    mma_f16(acc[mt][nt], ah[mt], bh[nt]);
                }
        }
    };

    const int nIter = K2 >> 4;   // K/32 (>= 10 always)
    stage(0, 0); CP_COMMIT();
    stage(1, 1); CP_COMMIT();
    for (int it = 0; it < nIter; it++) {
        if (it + 1 < nIter) { CP_WAIT1(); } else { CP_WAIT0(); }
        __syncthreads();
        compute(it % 3);
        if (it + 2 < nIter) {
            stage(it + 2, (it + 2) % 3);
            CP_COMMIT();
        }
    }

    // epilogue
#pragma unroll
    for (int mt = 0; mt < MT; mt++) {
        size_t r0 = rowBase + wm + mt * 16 + g;
#pragma unroll
        for (int nt = 0; nt < 4; nt++) {
            int col = colBase + wn + nt * 8 + t4 * 2;
            float2 bs = *(const float2*)&bias[col];
            float v0 = acc[mt][nt][0] + bs.x;
            float v1 = acc[mt][nt][1] + bs.y;
            float v2 = acc[mt][nt][2] + bs.x;
            float v3 = acc[mt][nt][3] + bs.y;
            if (flags & FLAG_RELU) {
                v0 = fmaxf(v0, 0.f); v1 = fmaxf(v1, 0.f);
                v2 = fmaxf(v2, 0.f); v3 = fmaxf(v3, 0.f);
            }
            if (flags & FLAG_PACK) {
                int N2 = N >> 1, c2 = col >> 1;
                Cpk[r0 * N2 + c2]       = pack2h(v0, v1);
                Cpk[(r0 + 8) * N2 + c2] = pack2h(v2, v3);
            } else {
                *(float2*)&C[r0 * N + col]       = make_float2(v0, v1);
                *(float2*)&C[(r0 + 8) * N + col] = make_float2(v2, v3);
            }
        }
    }
}

#define GPS_SMEM64  (3 * (10240 + 64 * 160))    // 61440
#define GPS_SMEM128 (3 * (10240 + 128 * 160))   // 92160

// ---------------- fp32 tiled SGEMM (input projection only; PE epilogue) ----
__global__ __launch_bounds__(256) void gemm64(
    const float* __restrict__ A, int lda,
    const float* __restrict__ Bw, int ldb,
    const float* __restrict__ bias,
    float* __restrict__ C, int ldc,
    int K, int flags)
{
    __shared__ __align__(16) float As[16][65];
    __shared__ __align__(16) float Bs[16][64];

    int tid = threadIdx.x;
    int ty = tid >> 4, tx = tid & 15;
    size_t rowBase = (size_t)blockIdx.y * 64;
    int colBase = blockIdx.x * 64;
    const float* Ab = A + rowBase * (size_t)lda;
    const float* Bb = Bw + colBase;

    float acc[4][4];
#pragma unroll
    for (int i = 0; i < 4; i++)
#pragma unroll
        for (int j = 0; j < 4; j++) acc[i][j] = 0.f;

    for (int k0 = 0; k0 < K; k0 += 16) {
#pragma unroll
        for (int i = 0; i < 4; i++) {
            int e = tid + i * 256;
            int r = e >> 4, c = e & 15;
            As[c][r] = Ab[(size_t)r * lda + (k0 + c)];
        }
#pragma unroll
        for (int i = 0; i < 4; i++) {
            int e = tid + i * 256;
            int r = e >> 6, c = e & 63;
            Bs[r][c] = Bb[(size_t)(k0 + r) * ldb + c];
        }
        __syncthreads();
#pragma unroll
        for (int k = 0; k < 16; k++) {
            float a0 = As[k][ty * 4 + 0];
            float a1 = As[k][ty * 4 + 1];
            float a2 = As[k][ty * 4 + 2];
            float a3 = As[k][ty * 4 + 3];
            float4 b = *(const float4*)&Bs[k][tx * 4];
            acc[0][0] += a0 * b.x; acc[0][1] += a0 * b.y; acc[0][2] += a0 * b.z; acc[0][3] += a0 * b.w;
            acc[1][0] += a1 * b.x; acc[1][1] += a1 * b.y; acc[1][2] += a1 * b.z; acc[1][3] += a1 * b.w;
            acc[2][0] += a2 * b.x; acc[2][1] += a2 * b.y; acc[2][2] += a2 * b.z; acc[2][3] += a2 * b.w;
            acc[3][0] += a3 * b.x; acc[3][1] += a3 * b.y; acc[3][2] += a3 * b.z; acc[3][3] += a3 * b.w;
        }
        __syncthreads();
    }

    int row0 = (int)rowBase + ty * 4;
    int col0 = colBase + tx * 4;
#pragma unroll
    for (int i = 0; i < 4; i++) {
        int row = row0 + i;
#pragma unroll
        for (int j = 0; j < 4; j++) {
            int col = col0 + j;
            float v = acc[i][j] + bias[col];
            if (flags & FLAG_PE) {
                int s = row % S_;
                int half = col >> 1;
                float div = expf((float)(2 * half) * (-9.210340371976184f / (float)D_));
                float arg = (float)s * div;
                v += (col & 1) ? cosf(arg) : sinf(arg);
            }
            if (flags & FLAG_RELU) v = fmaxf(v, 0.f);
            C[(size_t)row * ldc + col] = v;
        }
    }
}

// ---------------- fused QKV projection + attention: block per (b, h) -------
// Writes heads as single packed fp16x2.
__global__ __launch_bounds__(256) void attn_fused(
    const float* __restrict__ hsrc,
    const float* __restrict__ Wq, const float* __restrict__ bq,
    const float* __restrict__ Wk, const float* __restrict__ bk,
    const float* __restrict__ Wv, const float* __restrict__ bv,
    int l, uint32_t* __restrict__ headsPk)
{
    __shared__ float sh[S_][DH_ + 1];
    __shared__ float sq[S_][DH_ + 1];
    __shared__ float sk[S_][DH_ + 1];
    __shared__ float sv[S_][DH_ + 1];
    __shared__ float sc[S_][S_ + 1];

    int bh = blockIdx.x;
    int b = bh / H_, h = bh % H_;
    size_t base = ((size_t)b * S_) * D_ + (size_t)h * DH_;
    int tid = threadIdx.x;

    for (int e = tid; e < S_ * DH_; e += 256) {
        int s = e >> 6, d = e & 63;
        sh[s][d] = hsrc[base + (size_t)s * D_ + d];
    }
    __syncthreads();

    size_t woff = ((size_t)l * H_ + h) * DH_ * DH_;
    size_t boff = ((size_t)l * H_ + h) * DH_;
    const float* Wqh = Wq + woff;
    const float* Wkh = Wk + woff;
    const float* Wvh = Wv + woff;

    {
        int e = tid & 63;
        for (int r = tid >> 6; r < 3 * S_; r += 4) {
            int m = r / S_, s = r % S_;
            const float* Wm = (m == 0) ? Wqh : (m == 1) ? Wkh : Wvh;
            const float* bm = (m == 0) ? (bq + boff) : (m == 1) ? (bk + boff) : (bv + boff);
            float acc = bm[e];
#pragma unroll 16
            for (int d = 0; d < DH_; d++) acc += sh[s][d] * Wm[d * DH_ + e];
            if (m == 0) sq[s][e] = acc;
            else if (m == 1) sk[s][e] = acc;
            else sv[s][e] = acc;
        }
    }
    __syncthreads();

    for (int e = tid; e < S_ * S_; e += 256) {
        int i = e / S_, j = e % S_;
        float acc = 0.f;
#pragma unroll
        for (int d = 0; d < DH_; d++) acc += sq[i][d] * sk[j][d];
        sc[i][j] = acc * 0.125f;
    }
    __syncthreads();

    if (tid < S_) {
        float m = -1e30f;
        for (int j = 0; j < S_; j++) m = fmaxf(m, sc[tid][j]);
        float sum = 0.f;
        for (int j = 0; j < S_; j++) {
            float e2 = expf(sc[tid][j] - m);
            sc[tid][j] = e2;
            sum += e2;
        }
        float inv = 1.f / sum;
        for (int j = 0; j < S_; j++) sc[tid][j] *= inv;
    }
    __syncthreads();

    // A @ V -> packed fp16 pairs
    size_t tokBase = (size_t)b * S_;
    for (int e = tid; e < S_ * 32; e += 256) {
        int s = e >> 5, p = e & 31;
        int d0 = p * 2;
        float a0 = 0.f, a1 = 0.f;
#pragma unroll
        for (int j = 0; j < S_; j++) {
            a0 += sc[s][j] * sv[j][d0];
            a1 += sc[s][j] * sv[j][d0 + 1];
        }
        headsPk[(tokBase + s) * (D_ / 2) + h * 32 + p] = pack2h(a0, a1);
    }
}

// ---------------- residual add + LayerNorm: warp per token -----------------
__global__ __launch_bounds__(256) void add_ln_warp(
    float* __restrict__ hb, const float* __restrict__ add,
    const float* __restrict__ gamma, const float* __restrict__ beta,
    uint32_t* __restrict__ outPk, int pack)
{
    int w = threadIdx.x >> 5, lane = threadIdx.x & 31;
    size_t tok = (size_t)blockIdx.x * 8 + w;
    size_t base = tok * D_;

    float2 v[5];
    float s = 0.f;
#pragma unroll
    for (int i = 0; i < 5; i++) {
        int d = lane * 2 + i * 64;
        float2 a = *(const float2*)&hb[base + d];
        float2 r = *(const float2*)&add[base + d];
        v[i].x = a.x + r.x;
        v[i].y = a.y + r.y;
        s += v[i].x + v[i].y;
    }
#pragma unroll
    for (int o = 16; o; o >>= 1) s += __shfl_xor_sync(0xffffffffu, s, o);
    float mean = s * (1.f / (float)D_);

    float s2 = 0.f;
#pragma unroll
    for (int i = 0; i < 5; i++) {
        float dx = v[i].x - mean, dy = v[i].y - mean;
        s2 += dx * dx + dy * dy;
    }
#pragma unroll
    for (int o = 16; o; o >>= 1) s2 += __shfl_xor_sync(0xffffffffu, s2, o);
    float rstd = rsqrtf(s2 * (1.f / (float)D_) + 1e-5f);

#pragma unroll
    for (int i = 0; i < 5; i++) {
        int d = lane * 2 + i * 64;
        float o0 = (v[i].x - mean) * rstd * gamma[d] + beta[d];
        float o1 = (v[i].y - mean) * rstd * gamma[d + 1] + beta[d + 1];
        *(float2*)&hb[base + d] = make_float2(o0, o1);
        if (pack)
            outPk[tok * (D_ / 2) + lane + i * 32] = pack2h(o0, o1);
    }
}

// ---------------- attention pooling + classifier (block per batch row) -----
__global__ __launch_bounds__(320) void pool_cls_kernel(
    const float* __restrict__ hb,
    const float* __restrict__ pool_W, const float* __restrict__ pool_b,
    const float* __restrict__ W1, const float* __restrict__ b1,
    const float* __restrict__ W2, const float* __restrict__ b2,
    float* __restrict__ out)
{
    __shared__ float sscore[S_];
    __shared__ float sz[D_];
    __shared__ float shid[D_ / 2];
    __shared__ float sred[10];

    int b = blockIdx.x;
    int t = threadIdx.x, warp = t >> 5, lane = t & 31;
    const float* hrow = hb + (size_t)b * S_ * D_;

    for (int s = warp; s < S_; s += 10) {
        float acc = 0.f;
        for (int d = lane; d < D_; d += 32) acc += hrow[s * D_ + d] * pool_W[d];
#pragma unroll
        for (int o = 16; o; o >>= 1) acc += __shfl_down_sync(0xffffffffu, acc, o);
        if (lane == 0) sscore[s] = acc + pool_b[0];
    }
    __syncthreads();

    if (t == 0) {
        float m = -1e30f;
        for (int s = 0; s < S_; s++) m = fmaxf(m, sscore[s]);
        float sum = 0.f;
        for (int s = 0; s < S_; s++) {
            float e = expf(sscore[s] - m);
            sscore[s] = e;
            sum += e;
        }
        float inv = 1.f / sum;
        for (int s = 0; s < S_; s++) sscore[s] *= inv;
    }
    __syncthreads();

    {
        float acc = 0.f;
        for (int s = 0; s < S_; s++) acc += sscore[s] * hrow[s * D_ + t];
        sz[t] = acc;
    }
    __syncthreads();

    if (t < D_ / 2) {
        float acc = b1[t];
        for (int d = 0; d < D_; d++) acc += sz[d] * W1[d * (D_ / 2) + t];
        shid[t] = fmaxf(acc, 0.f);
    }
    __syncthreads();

    float p = (t < D_ / 2) ? shid[t] * W2[t] : 0.f;
#pragma unroll
    for (int o = 16; o; o >>= 1) p += __shfl_down_sync(0xffffffffu, p, o);
    if (lane == 0) sred[warp] = p;
    __syncthreads();
    if (t == 0) {
        float tot = 0.f;
        for (int i = 0; i < 10; i++) tot += sred[i];
        float logit = tot + b2[0];
        out[b] = logit;
        out[B_ + b] = 1.f / (1.f + expf(-logit));
    }
}

// ---------------- host launcher -------------------------------------------
extern "C" void kernel_launch(void* const* d_in, const int* in_sizes, int n_in,
                              void* d_out, int out_size)
{
    const float* x      = (const float*)d_in[0];
    const float* in_W   = (const float*)d_in[1];
    const float* in_b   = (const float*)d_in[2];
    const float* Wq     = (const float*)d_in[3];
    const float* bq     = (const float*)d_in[4];
    const float* Wk     = (const float*)d_in[5];
    const float* bk     = (const float*)d_in[6];
    const float* Wv     = (const float*)d_in[7];
    const float* bv     = (const float*)d_in[8];
    const float* Wo     = (const float*)d_in[9];
    const float* bo     = (const float*)d_in[10];
    const float* ln1_g  = (const float*)d_in[11];
    const float* ln1_b  = (const float*)d_in[12];
    const float* W1     = (const float*)d_in[13];
    const float* b1     = (const float*)d_in[14];
    const float* W2     = (const float*)d_in[15];
    const float* b2     = (const float*)d_in[16];
    const float* ln2_g  = (const float*)d_in[17];
    const float* ln2_b  = (const float*)d_in[18];
    const float* pool_W = (const float*)d_in[19];
    const float* pool_b = (const float*)d_in[20];
    const float* cW1    = (const float*)d_in[21];
    const float* cb1    = (const float*)d_in[22];
    const float* cW2    = (const float*)d_in[23];
    const float* cb2    = (const float*)d_in[24];

    float *ph, *ptmp;
    uint32_t *pha, *phd, *pff;
    uint32_t *pwo_hi, *pwo_lo, *pw1_hi, *pw1_lo, *pw2_hi, *pw2_lo;
    cudaGetSymbolAddress((void**)&ph, g_h);
    cudaGetSymbolAddress((void**)&ptmp, g_tmp);
    cudaGetSymbolAddress((void**)&pha, g_ha);
    cudaGetSymbolAddress((void**)&phd, g_hd);
    cudaGetSymbolAddress((void**)&pff, g_ff);
    cudaGetSymbolAddress((void**)&pwo_hi, g_wo_hi);
    cudaGetSymbolAddress((void**)&pwo_lo, g_wo_lo);
    cudaGetSymbolAddress((void**)&pw1_hi, g_w1_hi);
    cudaGetSymbolAddress((void**)&pw1_lo, g_w1_lo);
    cudaGetSymbolAddress((void**)&pw2_hi, g_w2_hi);
    cudaGetSymbolAddress((void**)&pw2_lo, g_w2_lo);

    cudaFuncSetAttribute(gemm_ps<64, 2>,
                         cudaFuncAttributeMaxDynamicSharedMemorySize, GPS_SMEM64);
    cudaFuncSetAttribute(gemm_ps<128, 4>,
                         cudaFuncAttributeMaxDynamicSharedMemorySize, GPS_SMEM128);

    // weight conversion (per layer)
    const int woN = D_ * D_ / 2, w1N = D_ * DFF_ / 2, w2N = DFF_ * D_ / 2;
    for (int l = 0; l < L_; l++) {
        convert_w<<<(woN + 255) / 256, 256>>>(Wo + (size_t)l * D_ * D_,
                                              pwo_hi + (size_t)l * woN, pwo_lo + (size_t)l * woN, D_, D_);
        convert_w<<<(w1N + 255) / 256, 256>>>(W1 + (size_t)l * D_ * DFF_,
                                              pw1_hi + (size_t)l * w1N, pw1_lo + (size_t)l * w1N, D_, DFF_);
        convert_w<<<(w2N + 255) / 256, 256>>>(W2 + (size_t)l * DFF_ * D_,
                                              pw2_hi + (size_t)l * w2N, pw2_lo + (size_t)l * w2N, DFF_, D_);
    }

    const dim3 gridIn(D_ / 64, NTOK / 64);
    const dim3 gridD(D_ / 64, NTOK / 128);       // BN=64, N=320
    const dim3 gridF(DFF_ / 128, NTOK / 128);    // BN=128, N=1280

    // input projection + bias + positional encoding (fp32)
    gemm64<<<gridIn, 256>>>(x, FIN_, in_W, D_, in_b, ph, D_, FIN_, FLAG_PE);

    for (int l = 0; l < L_; l++) {
        attn_fused<<<B_ * H_, 256>>>(ph, Wq, bq, Wk, bk, Wv, bv, l, phd);
        // Wo: heads_packed @ Wo -> tmp fp32   (BN=64)
        gemm_ps<64, 2><<<gridD, 256, GPS_SMEM64>>>(phd, D_ / 2,
                                          pwo_hi + (size_t)l * woN, pwo_lo + (size_t)l * woN,
                                          bo + l * D_, ptmp, nullptr, D_, 0);
        add_ln_warp<<<NTOK / 8, 256>>>(ph, ptmp, ln1_g + l * D_, ln1_b + l * D_,
                                       pha, 1);
        // FFN1: h_packed @ W1 -> ffn packed (relu)   (BN=128)
        gemm_ps<128, 4><<<gridF, 256, GPS_SMEM128>>>(pha, D_ / 2,
                                          pw1_hi + (size_t)l * w1N, pw1_lo + (size_t)l * w1N,
                                          b1 + l * DFF_, nullptr, pff, DFF_,
                                          FLAG_RELU | FLAG_PACK);
        // FFN2: ffn_packed @ W2 -> tmp fp32   (BN=64)
        gemm_ps<64, 2><<<gridD, 256, GPS_SMEM64>>>(pff, DFF_ / 2,
                                          pw2_hi + (size_t)l * w2N, pw2_lo + (size_t)l * w2N,
                                          b2 + l * D_, ptmp, nullptr, D_, 0);
        add_ln_warp<<<NTOK / 8, 256>>>(ph, ptmp, ln2_g + l * D_, ln2_b + l * D_,
                                       nullptr, 0);
    }

    pool_cls_kernel<<<B_, 320>>>(ph, pool_W, pool_b, cW1, cb1, cW2, cb2,
                                 (float*)d_out);
}

// round 12
// speedup vs baseline: 2.8134x; 1.1125x over previous
#include <cuda_runtime.h>
#include <cuda_fp16.h>
#include <math.h>
#include <stdint.h>

#define B_    4096
#define S_    30
#define FIN_  80
#define D_    320
#define H_    5
#define DH_   64
#define L_    4
#define DFF_  1280
#define NTOK  (B_ * S_)

#define FLAG_RELU 1
#define FLAG_PE   2
#define FLAG_PACK 4

// ---------------- scratch (device globals; no allocations allowed) ----------
__device__ float g_h[NTOK * D_];
__device__ float g_tmp[NTOK * D_];
__device__ uint32_t g_ha[NTOK * D_ / 2];      // h packed fp16x2 (FFN1 A)
__device__ uint32_t g_hd[NTOK * D_ / 2];      // heads packed fp16x2 (Wo A)
__device__ uint32_t g_ff[NTOK * DFF_ / 2];    // ffn packed fp16x2 (FFN2 A)
__device__ uint32_t g_wo[L_ * D_ * D_ / 2];
__device__ uint32_t g_w1[L_ * D_ * DFF_ / 2];
__device__ uint32_t g_w2[L_ * DFF_ * D_ / 2];

// ---------------- helpers --------------------------------------------------
__device__ __forceinline__ uint32_t smem_u32(const void* p) {
    uint32_t a;
    asm("{ .reg .u64 t; cvta.to.shared.u64 t, %1; cvt.u32.u64 %0, t; }"
        : "=r"(a) : "l"(p));
    return a;
}

__device__ __forceinline__ uint32_t pack2h(float v0, float v1) {
    __half2 h = __floats2half2_rn(v0, v1);
    return *reinterpret_cast<uint32_t*>(&h);
}

__device__ __forceinline__ void mma_f16(float* c, const uint32_t* a, const uint32_t* b) {
    asm volatile(
        "mma.sync.aligned.m16n8k16.row.col.f32.f16.f16.f32 "
        "{%0,%1,%2,%3}, {%4,%5,%6,%7}, {%8,%9}, {%0,%1,%2,%3};\n"
        : "+f"(c[0]), "+f"(c[1]), "+f"(c[2]), "+f"(c[3])
        : "r"(a[0]), "r"(a[1]), "r"(a[2]), "r"(a[3]), "r"(b[0]), "r"(b[1]));
}

__device__ __forceinline__ void ldm_x4(uint32_t* r, uint32_t addr) {
    asm volatile("ldmatrix.sync.aligned.m8n8.x4.shared.b16 {%0,%1,%2,%3}, [%4];"
        : "=r"(r[0]), "=r"(r[1]), "=r"(r[2]), "=r"(r[3]) : "r"(addr));
}

__device__ __forceinline__ void cp16(uint32_t dst, const uint32_t* src) {
    asm volatile("cp.async.cg.shared.global [%0], [%1], 16;" :: "r"(dst), "l"(src));
}
#define CP_COMMIT() asm volatile("cp.async.commit_group;" ::: "memory")
#define CP_WAIT0()  asm volatile("cp.async.wait_group 0;" ::: "memory")
#define CP_WAIT1()  asm volatile("cp.async.wait_group 1;" ::: "memory")

// ---------------- weight conversion: W[K][N] -> fp16x2 [N][K/2] ------------
__global__ void convert_w(const float* __restrict__ W,
                          uint32_t* __restrict__ out, int K, int N)
{
    int idx = blockIdx.x * 256 + threadIdx.x;
    int K2 = K >> 1;
    if (idx >= N * K2) return;
    int n = idx / K2, k2 = idx % K2;
    float v0 = W[(size_t)(2 * k2) * N + n];
    float v1 = W[(size_t)(2 * k2 + 1) * N + n];
    out[idx] = pack2h(v0, v1);
}

// ======================================================================
// Pure fp16 GEMM: C = A @ B + bias [+relu] [packed out]
// A fp16x2 [M][K2]; B fp16x2 transposed [N][K2].
// BM=128, BK=32 (16 u32), 256 thr; single-sync 3-stage cp.async pipe.
//   BN=64:  8 warps 4x2, warp tile 32x32 (MT=2)
//   BN=128: 8 warps 2x4, warp tile 64x32 (MT=4)
// smem row stride 20 u32 (80B, 16B-aligned, ldmatrix conflict-free).
// Stage = 10240 + BN*80 bytes; 3 stages.
// ======================================================================
template<int BN, int MT>
__global__ __launch_bounds__(256) void gemm_ps(
    const uint32_t* __restrict__ Apk, int K2,
    const uint32_t* __restrict__ Bpk,
    const float* __restrict__ bias,
    float* __restrict__ C, uint32_t* __restrict__ Cpk,
    int N, int flags)
{
    constexpr int ST   = 20;
    constexpr int SA   = 0;
    constexpr int SB   = 128 * ST * 4;       // 10240
    constexpr int STAGE = SB + BN * ST * 4;

    extern __shared__ __align__(1024) char smem[];
    const uint32_t sbase = smem_u32(smem);
    const int tid = threadIdx.x;
    const int lane = tid & 31;
    const int w = tid >> 5;
    const int g = lane >> 2, t4 = lane & 3;
    const int wm = (BN == 64) ? (w >> 1) * 32 : (w >> 2) * 64;
    const int wn = (BN == 64) ? (w & 1) * 32 : (w & 3) * 32;

    const size_t rowBase = (size_t)blockIdx.y * 128;
    const int    colBase = blockIdx.x * BN;

    const uint32_t* A_g = Apk + rowBase * K2;
    const uint32_t* B_g = Bpk + (size_t)colBase * K2;

    float acc[MT][4][4];
#pragma unroll
    for (int mt = 0; mt < MT; mt++)
#pragma unroll
        for (int nt = 0; nt < 4; nt++)
#pragma unroll
            for (int i = 0; i < 4; i++) acc[mt][nt][i] = 0.f;

    auto stage = [&](int it, int slot) {
        uint32_t sb = sbase + slot * STAGE;
        int k2o = it * 16;
#pragma unroll
        for (int j = 0; j < 2; j++) {       // A: 128 rows x 4 chunks
            int idx = tid + j * 256;
            int row = idx >> 2, ch = (idx & 3) * 4;
            uint32_t so = (uint32_t)(row * ST + ch) * 4;
            cp16(sb + SA + so, A_g + (size_t)row * K2 + k2o + ch);
        }
#pragma unroll
        for (int j = 0; j < BN / 64; j++) { // B: BN rows x 4 chunks
            int idx = tid + j * 256;
            int row = idx >> 2, ch = (idx & 3) * 4;
            uint32_t so = (uint32_t)(row * ST + ch) * 4;
            cp16(sb + SB + so, B_g + (size_t)row * K2 + k2o + ch);
        }
    };

    auto compute = [&](int slot) {
        uint32_t sb = sbase + slot * STAGE;
#pragma unroll
        for (int s = 0; s < 2; s++) {
            const int s8 = s * 8;
            uint32_t ah[MT][4], bf[4][2];
#pragma unroll
            for (int mt = 0; mt < MT; mt++) {
                int row = wm + mt * 16 + (lane & 15);
                uint32_t off = (uint32_t)(row * ST + s8 + ((lane >> 4) << 2)) * 4;
                ldm_x4(ah[mt], sb + SA + off);
            }
#pragma unroll
            for (int h2 = 0; h2 < 2; h2++) {
                int row = wn + h2 * 16 + (lane & 7) + ((lane >> 4) << 3);
                uint32_t off = (uint32_t)(row * ST + s8 + ((lane & 8) >> 1)) * 4;
                uint32_t t[4];
                ldm_x4(t, sb + SB + off);
                bf[h2 * 2][0] = t[0]; bf[h2 * 2][1] = t[1];
                bf[h2 * 2 + 1][0] = t[2]; bf[h2 * 2 + 1][1] = t[3];
            }
#pragma unroll
            for (int mt = 0; mt < MT; mt++)
#pragma unroll
                for (int nt = 0; nt < 4; nt++)
                    mma_f16(acc[mt][nt], ah[mt], bf[nt]);
        }
    };

    const int nIter = K2 >> 4;   // K/32 (>= 10 always)
    stage(0, 0); CP_COMMIT();
    stage(1, 1); CP_COMMIT();
    for (int it = 0; it < nIter; it++) {
        if (it + 1 < nIter) { CP_WAIT1(); } else { CP_WAIT0(); }
        __syncthreads();
        compute(it % 3);
        if (it + 2 < nIter) {
            stage(it + 2, (it + 2) % 3);
            CP_COMMIT();
        }
    }

    // epilogue
#pragma unroll
    for (int mt = 0; mt < MT; mt++) {
        size_t r0 = rowBase + wm + mt * 16 + g;
#pragma unroll
        for (int nt = 0; nt < 4; nt++) {
            int col = colBase + wn + nt * 8 + t4 * 2;
            float2 bs = *(const float2*)&bias[col];
            float v0 = acc[mt][nt][0] + bs.x;
            float v1 = acc[mt][nt][1] + bs.y;
            float v2 = acc[mt][nt][2] + bs.x;
            float v3 = acc[mt][nt][3] + bs.y;
            if (flags & FLAG_RELU) {
                v0 = fmaxf(v0, 0.f); v1 = fmaxf(v1, 0.f);
                v2 = fmaxf(v2, 0.f); v3 = fmaxf(v3, 0.f);
            }
            if (flags & FLAG_PACK) {
                int N2 = N >> 1, c2 = col >> 1;
                Cpk[r0 * N2 + c2]       = pack2h(v0, v1);
                Cpk[(r0 + 8) * N2 + c2] = pack2h(v2, v3);
            } else {
                *(float2*)&C[r0 * N + col]       = make_float2(v0, v1);
                *(float2*)&C[(r0 + 8) * N + col] = make_float2(v2, v3);
            }
        }
    }
}

#define GPS_SMEM64  (3 * (10240 + 64 * 80))     // 46080
#define GPS_SMEM128 (3 * (10240 + 128 * 80))    // 61440

// ---------------- fp32 tiled SGEMM (input projection only; PE epilogue) ----
__global__ __launch_bounds__(256) void gemm64(
    const float* __restrict__ A, int lda,
    const float* __restrict__ Bw, int ldb,
    const float* __restrict__ bias,
    float* __restrict__ C, int ldc,
    int K, int flags)
{
    __shared__ __align__(16) float As[16][65];
    __shared__ __align__(16) float Bs[16][64];

    int tid = threadIdx.x;
    int ty = tid >> 4, tx = tid & 15;
    size_t rowBase = (size_t)blockIdx.y * 64;
    int colBase = blockIdx.x * 64;
    const float* Ab = A + rowBase * (size_t)lda;
    const float* Bb = Bw + colBase;

    float acc[4][4];
#pragma unroll
    for (int i = 0; i < 4; i++)
#pragma unroll
        for (int j = 0; j < 4; j++) acc[i][j] = 0.f;

    for (int k0 = 0; k0 < K; k0 += 16) {
#pragma unroll
        for (int i = 0; i < 4; i++) {
            int e = tid + i * 256;
            int r = e >> 4, c = e & 15;
            As[c][r] = Ab[(size_t)r * lda + (k0 + c)];
        }
#pragma unroll
        for (int i = 0; i < 4; i++) {
            int e = tid + i * 256;
            int r = e >> 6, c = e & 63;
            Bs[r][c] = Bb[(size_t)(k0 + r) * ldb + c];
        }
        __syncthreads();
#pragma unroll
        for (int k = 0; k < 16; k++) {
            float a0 = As[k][ty * 4 + 0];
            float a1 = As[k][ty * 4 + 1];
            float a2 = As[k][ty * 4 + 2];
            float a3 = As[k][ty * 4 + 3];
            float4 b = *(const float4*)&Bs[k][tx * 4];
            acc[0][0] += a0 * b.x; acc[0][1] += a0 * b.y; acc[0][2] += a0 * b.z; acc[0][3] += a0 * b.w;
            acc[1][0] += a1 * b.x; acc[1][1] += a1 * b.y; acc[1][2] += a1 * b.z; acc[1][3] += a1 * b.w;
            acc[2][0] += a2 * b.x; acc[2][1] += a2 * b.y; acc[2][2] += a2 * b.z; acc[2][3] += a2 * b.w;
            acc[3][0] += a3 * b.x; acc[3][1] += a3 * b.y; acc[3][2] += a3 * b.z; acc[3][3] += a3 * b.w;
        }
        __syncthreads();
    }

    int row0 = (int)rowBase + ty * 4;
    int col0 = colBase + tx * 4;
#pragma unroll
    for (int i = 0; i < 4; i++) {
        int row = row0 + i;
#pragma unroll
        for (int j = 0; j < 4; j++) {
            int col = col0 + j;
            float v = acc[i][j] + bias[col];
            if (flags & FLAG_PE) {
                int s = row % S_;
                int half = col >> 1;
                float div = expf((float)(2 * half) * (-9.210340371976184f / (float)D_));
                float arg = (float)s * div;
                v += (col & 1) ? cosf(arg) : sinf(arg);
            }
            if (flags & FLAG_RELU) v = fmaxf(v, 0.f);
            C[(size_t)row * ldc + col] = v;
        }
    }
}

// ---------------- fused QKV projection + attention: block per (b, h) -------
__global__ __launch_bounds__(256) void attn_fused(
    const float* __restrict__ hsrc,
    const float* __restrict__ Wq, const float* __restrict__ bq,
    const float* __restrict__ Wk, const float* __restrict__ bk,
    const float* __restrict__ Wv, const float* __restrict__ bv,
    int l, uint32_t* __restrict__ headsPk)
{
    __shared__ float sh[S_][DH_ + 1];
    __shared__ float sq[S_][DH_ + 1];
    __shared__ float sk[S_][DH_ + 1];
    __shared__ float sv[S_][DH_ + 1];
    __shared__ float sc[S_][S_ + 1];

    int bh = blockIdx.x;
    int b = bh / H_, h = bh % H_;
    size_t base = ((size_t)b * S_) * D_ + (size_t)h * DH_;
    int tid = threadIdx.x;

    for (int e = tid; e < S_ * DH_; e += 256) {
        int s = e >> 6, d = e & 63;
        sh[s][d] = hsrc[base + (size_t)s * D_ + d];
    }
    __syncthreads();

    size_t woff = ((size_t)l * H_ + h) * DH_ * DH_;
    size_t boff = ((size_t)l * H_ + h) * DH_;
    const float* Wqh = Wq + woff;
    const float* Wkh = Wk + woff;
    const float* Wvh = Wv + woff;

    {
        int e = tid & 63;
        for (int r = tid >> 6; r < 3 * S_; r += 4) {
            int m = r / S_, s = r % S_;
            const float* Wm = (m == 0) ? Wqh : (m == 1) ? Wkh : Wvh;
            const float* bm = (m == 0) ? (bq + boff) : (m == 1) ? (bk + boff) : (bv + boff);
            float acc = bm[e];
#pragma unroll 16
            for (int d = 0; d < DH_; d++) acc += sh[s][d] * Wm[d * DH_ + e];
            if (m == 0) sq[s][e] = acc;
            else if (m == 1) sk[s][e] = acc;
            else sv[s][e] = acc;
        }
    }
    __syncthreads();

    for (int e = tid; e < S_ * S_; e += 256) {
        int i = e / S_, j = e % S_;
        float acc = 0.f;
#pragma unroll
        for (int d = 0; d < DH_; d++) acc += sq[i][d] * sk[j][d];
        sc[i][j] = acc * 0.125f;
    }
    __syncthreads();

    if (tid < S_) {
        float m = -1e30f;
        for (int j = 0; j < S_; j++) m = fmaxf(m, sc[tid][j]);
        float sum = 0.f;
        for (int j = 0; j < S_; j++) {
            float e2 = expf(sc[tid][j] - m);
            sc[tid][j] = e2;
            sum += e2;
        }
        float inv = 1.f / sum;
        for (int j = 0; j < S_; j++) sc[tid][j] *= inv;
    }
    __syncthreads();

    // A @ V -> packed fp16 pairs
    size_t tokBase = (size_t)b * S_;
    for (int e = tid; e < S_ * 32; e += 256) {
        int s = e >> 5, p = e & 31;
        int d0 = p * 2;
        float a0 = 0.f, a1 = 0.f;
#pragma unroll
        for (int j = 0; j < S_; j++) {
            a0 += sc[s][j] * sv[j][d0];
            a1 += sc[s][j] * sv[j][d0 + 1];
        }
        headsPk[(tokBase + s) * (D_ / 2) + h * 32 + p] = pack2h(a0, a1);
    }
}

// ---------------- residual add + LayerNorm: warp per token -----------------
__global__ __launch_bounds__(256) void add_ln_warp(
    float* __restrict__ hb, const float* __restrict__ add,
    const float* __restrict__ gamma, const float* __restrict__ beta,
    uint32_t* __restrict__ outPk, int pack)
{
    int w = threadIdx.x >> 5, lane = threadIdx.x & 31;
    size_t tok = (size_t)blockIdx.x * 8 + w;
    size_t base = tok * D_;

    float2 v[5];
    float s = 0.f;
#pragma unroll
    for (int i = 0; i < 5; i++) {
        int d = lane * 2 + i * 64;
        float2 a = *(const float2*)&hb[base + d];
        float2 r = *(const float2*)&add[base + d];
        v[i].x = a.x + r.x;
        v[i].y = a.y + r.y;
        s += v[i].x + v[i].y;
    }
#pragma unroll
    for (int o = 16; o; o >>= 1) s += __shfl_xor_sync(0xffffffffu, s, o);
    float mean = s * (1.f / (float)D_);

    float s2 = 0.f;
#pragma unroll
    for (int i = 0; i < 5; i++) {
        float dx = v[i].x - mean, dy = v[i].y - mean;
        s2 += dx * dx + dy * dy;
    }
#pragma unroll
    for (int o = 16; o; o >>= 1) s2 += __shfl_xor_sync(0xffffffffu, s2, o);
    float rstd = rsqrtf(s2 * (1.f / (float)D_) + 1e-5f);

#pragma unroll
    for (int i = 0; i < 5; i++) {
        int d = lane * 2 + i * 64;
        float o0 = (v[i].x - mean) * rstd * gamma[d] + beta[d];
        float o1 = (v[i].y - mean) * rstd * gamma[d + 1] + beta[d + 1];
        *(float2*)&hb[base + d] = make_float2(o0, o1);
        if (pack)
            outPk[tok * (D_ / 2) + lane + i * 32] = pack2h(o0, o1);
    }
}

// ---------------- attention pooling + classifier (block per batch row) -----
__global__ __launch_bounds__(320) void pool_cls_kernel(
    const float* __restrict__ hb,
    const float* __restrict__ pool_W, const float* __restrict__ pool_b,
    const float* __restrict__ W1, const float* __restrict__ b1,
    const float* __restrict__ W2, const float* __restrict__ b2,
    float* __restrict__ out)
{
    __shared__ float sscore[S_];
    __shared__ float sz[D_];
    __shared__ float shid[D_ / 2];
    __shared__ float sred[10];

    int b = blockIdx.x;
    int t = threadIdx.x, warp = t >> 5, lane = t & 31;
    const float* hrow = hb + (size_t)b * S_ * D_;

    for (int s = warp; s < S_; s += 10) {
        float acc = 0.f;
        for (int d = lane; d < D_; d += 32) acc += hrow[s * D_ + d] * pool_W[d];
#pragma unroll
        for (int o = 16; o; o >>= 1) acc += __shfl_down_sync(0xffffffffu, acc, o);
        if (lane == 0) sscore[s] = acc + pool_b[0];
    }
    __syncthreads();

    if (t == 0) {
        float m = -1e30f;
        for (int s = 0; s < S_; s++) m = fmaxf(m, sscore[s]);
        float sum = 0.f;
        for (int s = 0; s < S_; s++) {
            float e = expf(sscore[s] - m);
            sscore[s] = e;
            sum += e;
        }
        float inv = 1.f / sum;
        for (int s = 0; s < S_; s++) sscore[s] *= inv;
    }
    __syncthreads();

    {
        float acc = 0.f;
        for (int s = 0; s < S_; s++) acc += sscore[s] * hrow[s * D_ + t];
        sz[t] = acc;
    }
    __syncthreads();

    if (t < D_ / 2) {
        float acc = b1[t];
        for (int d = 0; d < D_; d++) acc += sz[d] * W1[d * (D_ / 2) + t];
        shid[t] = fmaxf(acc, 0.f);
    }
    __syncthreads();

    float p = (t < D_ / 2) ? shid[t] * W2[t] : 0.f;
#pragma unroll
    for (int o = 16; o; o >>= 1) p += __shfl_down_sync(0xffffffffu, p, o);
    if (lane == 0) sred[warp] = p;
    __syncthreads();
    if (t == 0) {
        float tot = 0.f;
        for (int i = 0; i < 10; i++) tot += sred[i];
        float logit = tot + b2[0];
        out[b] = logit;
        out[B_ + b] = 1.f / (1.f + expf(-logit));
    }
}

// ---------------- host launcher -------------------------------------------
extern "C" void kernel_launch(void* const* d_in, const int* in_sizes, int n_in,
                              void* d_out, int out_size)
{
    const float* x      = (const float*)d_in[0];
    const float* in_W   = (const float*)d_in[1];
    const float* in_b   = (const float*)d_in[2];
    const float* Wq     = (const float*)d_in[3];
    const float* bq     = (const float*)d_in[4];
    const float* Wk     = (const float*)d_in[5];
    const float* bk     = (const float*)d_in[6];
    const float* Wv     = (const float*)d_in[7];
    const float* bv     = (const float*)d_in[8];
    const float* Wo     = (const float*)d_in[9];
    const float* bo     = (const float*)d_in[10];
    const float* ln1_g  = (const float*)d_in[11];
    const float* ln1_b  = (const float*)d_in[12];
    const float* W1     = (const float*)d_in[13];
    const float* b1     = (const float*)d_in[14];
    const float* W2     = (const float*)d_in[15];
    const float* b2     = (const float*)d_in[16];
    const float* ln2_g  = (const float*)d_in[17];
    const float* ln2_b  = (const float*)d_in[18];
    const float* pool_W = (const float*)d_in[19];
    const float* pool_b = (const float*)d_in[20];
    const float* cW1    = (const float*)d_in[21];
    const float* cb1    = (const float*)d_in[22];
    const float* cW2    = (const float*)d_in[23];
    const float* cb2    = (const float*)d_in[24];

    float *ph, *ptmp;
    uint32_t *pha, *phd, *pff, *pwo, *pw1, *pw2;
    cudaGetSymbolAddress((void**)&ph, g_h);
    cudaGetSymbolAddress((void**)&ptmp, g_tmp);
    cudaGetSymbolAddress((void**)&pha, g_ha);
    cudaGetSymbolAddress((void**)&phd, g_hd);
    cudaGetSymbolAddress((void**)&pff, g_ff);
    cudaGetSymbolAddress((void**)&pwo, g_wo);
    cudaGetSymbolAddress((void**)&pw1, g_w1);
    cudaGetSymbolAddress((void**)&pw2, g_w2);

    cudaFuncSetAttribute(gemm_ps<64, 2>,
                         cudaFuncAttributeMaxDynamicSharedMemorySize, GPS_SMEM64);
    cudaFuncSetAttribute(gemm_ps<128, 4>,
                         cudaFuncAttributeMaxDynamicSharedMemorySize, GPS_SMEM128);

    // weight conversion (per layer)
    const int woN = D_ * D_ / 2, w1N = D_ * DFF_ / 2, w2N = DFF_ * D_ / 2;
    for (int l = 0; l < L_; l++) {
        convert_w<<<(woN + 255) / 256, 256>>>(Wo + (size_t)l * D_ * D_,
                                              pwo + (size_t)l * woN, D_, D_);
        convert_w<<<(w1N + 255) / 256, 256>>>(W1 + (size_t)l * D_ * DFF_,
                                              pw1 + (size_t)l * w1N, D_, DFF_);
        convert_w<<<(w2N + 255) / 256, 256>>>(W2 + (size_t)l * DFF_ * D_,
                                              pw2 + (size_t)l * w2N, DFF_, D_);
    }

    const dim3 gridIn(D_ / 64, NTOK / 64);
    const dim3 gridD(D_ / 64, NTOK / 128);       // BN=64, N=320
    const dim3 gridF(DFF_ / 128, NTOK / 128);    // BN=128, N=1280

    // input projection + bias + positional encoding (fp32)
    gemm64<<<gridIn, 256>>>(x, FIN_, in_W, D_, in_b, ph, D_, FIN_, FLAG_PE);

    for (int l = 0; l < L_; l++) {
        attn_fused<<<B_ * H_, 256>>>(ph, Wq, bq, Wk, bk, Wv, bv, l, phd);
        // Wo: heads_packed @ Wo -> tmp fp32   (BN=64)
        gemm_ps<64, 2><<<gridD, 256, GPS_SMEM64>>>(phd, D_ / 2,
                                          pwo + (size_t)l * woN,
                                          bo + l * D_, ptmp, nullptr, D_, 0);
        add_ln_warp<<<NTOK / 8, 256>>>(ph, ptmp, ln1_g + l * D_, ln1_b + l * D_,
                                       pha, 1);
        // FFN1: h_packed @ W1 -> ffn packed (relu)   (BN=128)
        gemm_ps<128, 4><<<gridF, 256, GPS_SMEM128>>>(pha, D_ / 2,
                                          pw1 + (size_t)l * w1N,
                                          b1 + l * DFF_, nullptr, pff, DFF_,
                                          FLAG_RELU | FLAG_PACK);
        // FFN2: ffn_packed @ W2 -> tmp fp32   (BN=64)
        gemm_ps<64, 2><<<gridD, 256, GPS_SMEM64>>>(pff, DFF_ / 2,
                                          pw2 + (size_t)l * w2N,
                                          b2 + l * D_, ptmp, nullptr, D_, 0);
        add_ln_warp<<<NTOK / 8, 256>>>(ph, ptmp, ln2_g + l * D_, ln2_b + l * D_,
                                       nullptr, 0);
    }

    pool_cls_kernel<<<B_, 320>>>(ph, pool_W, pool_b, cW1, cb1, cW2, cb2,
                                 (float*)d_out);
}

// round 14
// speedup vs baseline: 2.8672x; 1.0192x over previous
#include <cuda_runtime.h>
#include <cuda_fp16.h>
#include <math.h>
#include <stdint.h>

#define B_    4096
#define S_    30
#define FIN_  80
#define D_    320
#define H_    5
#define DH_   64
#define L_    4
#define DFF_  1280
#define NTOK  (B_ * S_)

#define FLAG_RELU 1
#define FLAG_PE   2
#define FLAG_PACK 4

// ---------------- scratch (device globals; no allocations allowed) ----------
__device__ float g_h[NTOK * D_];
__device__ float g_tmp[NTOK * D_];
__device__ uint32_t g_ha[NTOK * D_ / 2];      // h packed fp16x2 (FFN1 A)
__device__ uint32_t g_hd[NTOK * D_ / 2];      // heads packed fp16x2 (Wo A)
__device__ uint32_t g_ff[NTOK * DFF_ / 2];    // ffn packed fp16x2 (FFN2 A)
__device__ uint32_t g_wo[L_ * D_ * D_ / 2];
__device__ uint32_t g_w1[L_ * D_ * DFF_ / 2];
__device__ uint32_t g_w2[L_ * DFF_ * D_ / 2];

// ---------------- helpers --------------------------------------------------
__device__ __forceinline__ uint32_t smem_u32(const void* p) {
    uint32_t a;
    asm("{ .reg .u64 t; cvta.to.shared.u64 t, %1; cvt.u32.u64 %0, t; }"
        : "=r"(a) : "l"(p));
    return a;
}

__device__ __forceinline__ uint32_t pack2h(float v0, float v1) {
    __half2 h = __floats2half2_rn(v0, v1);
    return *reinterpret_cast<uint32_t*>(&h);
}

__device__ __forceinline__ void mma_f16(float* c, const uint32_t* a, const uint32_t* b) {
    asm volatile(
        "mma.sync.aligned.m16n8k16.row.col.f32.f16.f16.f32 "
        "{%0,%1,%2,%3}, {%4,%5,%6,%7}, {%8,%9}, {%0,%1,%2,%3};\n"
        : "+f"(c[0]), "+f"(c[1]), "+f"(c[2]), "+f"(c[3])
        : "r"(a[0]), "r"(a[1]), "r"(a[2]), "r"(a[3]), "r"(b[0]), "r"(b[1]));
}

__device__ __forceinline__ void ldm_x4(uint32_t* r, uint32_t addr) {
    asm volatile("ldmatrix.sync.aligned.m8n8.x4.shared.b16 {%0,%1,%2,%3}, [%4];"
        : "=r"(r[0]), "=r"(r[1]), "=r"(r[2]), "=r"(r[3]) : "r"(addr));
}

__device__ __forceinline__ void cp16(uint32_t dst, const uint32_t* src) {
    asm volatile("cp.async.cg.shared.global [%0], [%1], 16;" :: "r"(dst), "l"(src));
}
#define CP_COMMIT() asm volatile("cp.async.commit_group;" ::: "memory")
#define CP_WAIT0()  asm volatile("cp.async.wait_group 0;" ::: "memory")
#define CP_WAIT1()  asm volatile("cp.async.wait_group 1;" ::: "memory")

// ---------------- weight conversion: W[K][N] -> fp16x2 [N][K/2] ------------
__global__ void convert_w(const float* __restrict__ W,
                          uint32_t* __restrict__ out, int K, int N)
{
    int idx = blockIdx.x * 256 + threadIdx.x;
    int K2 = K >> 1;
    if (idx >= N * K2) return;
    int n = idx / K2, k2 = idx % K2;
    float v0 = W[(size_t)(2 * k2) * N + n];
    float v1 = W[(size_t)(2 * k2 + 1) * N + n];
    out[idx] = pack2h(v0, v1);
}

// ======================================================================
// Pure fp16 GEMM: C = A @ B + bias [+relu] [packed out]
// A fp16x2 [M][K2]; B fp16x2 transposed [N][K2].
// BM=128, BK=64 (32 u32), 256 thr; single-sync 3-stage cp.async pipe.
//   BN=64:  8 warps 4x2, warp tile 32x32 (MT=2)
//   BN=128: 8 warps 2x4, warp tile 64x32 (MT=4)
// smem row stride 36 u32 (144B = 9x16: cp.async-aligned; ldmatrix rows
// land on banks 4r+c -> all 32 banks once per 8x8 matrix: conflict-free).
// Stage = (128+BN)*144 bytes; 3 stages.
// ======================================================================
template<int BN, int MT>
__global__ __launch_bounds__(256) void gemm_ps(
    const uint32_t* __restrict__ Apk, int K2,
    const uint32_t* __restrict__ Bpk,
    const float* __restrict__ bias,
    float* __restrict__ C, uint32_t* __restrict__ Cpk,
    int N, int flags)
{
    constexpr int ST   = 36;                 // u32 per smem row (32 data + 4 pad)
    constexpr int SA   = 0;
    constexpr int SB   = 128 * ST * 4;       // 18432
    constexpr int STAGE = SB + BN * ST * 4;

    extern __shared__ __align__(1024) char smem[];
    const uint32_t sbase = smem_u32(smem);
    const int tid = threadIdx.x;
    const int lane = tid & 31;
    const int w = tid >> 5;
    const int g = lane >> 2, t4 = lane & 3;
    const int wm = (BN == 64) ? (w >> 1) * 32 : (w >> 2) * 64;
    const int wn = (BN == 64) ? (w & 1) * 32 : (w & 3) * 32;

    const size_t rowBase = (size_t)blockIdx.y * 128;
    const int    colBase = blockIdx.x * BN;

    const uint32_t* A_g = Apk + rowBase * K2;
    const uint32_t* B_g = Bpk + (size_t)colBase * K2;

    float acc[MT][4][4];
#pragma unroll
    for (int mt = 0; mt < MT; mt++)
#pragma unroll
        for (int nt = 0; nt < 4; nt++)
#pragma unroll
            for (int i = 0; i < 4; i++) acc[mt][nt][i] = 0.f;

    auto stage = [&](int it, int slot) {
        uint32_t sb = sbase + slot * STAGE;
        int k2o = it * 32;
#pragma unroll
        for (int j = 0; j < 4; j++) {        // A: 128 rows x 8 chunks
            int idx = tid + j * 256;
            int row = idx >> 3, ch = (idx & 7) * 4;
            uint32_t so = (uint32_t)(row * ST + ch) * 4;
            cp16(sb + SA + so, A_g + (size_t)row * K2 + k2o + ch);
        }
#pragma unroll
        for (int j = 0; j < BN / 32; j++) {  // B: BN rows x 8 chunks
            int idx = tid + j * 256;
            int row = idx >> 3, ch = (idx & 7) * 4;
            uint32_t so = (uint32_t)(row * ST + ch) * 4;
            cp16(sb + SB + so, B_g + (size_t)row * K2 + k2o + ch);
        }
    };

    auto compute = [&](int slot) {
        uint32_t sb = sbase + slot * STAGE;
#pragma unroll
        for (int s = 0; s < 4; s++) {
            const int s8 = s * 8;
            uint32_t ah[MT][4], bf[4][2];
#pragma unroll
            for (int mt = 0; mt < MT; mt++) {
                int row = wm + mt * 16 + (lane & 15);
                uint32_t off = (uint32_t)(row * ST + s8 + ((lane >> 4) << 2)) * 4;
                ldm_x4(ah[mt], sb + SA + off);
            }
#pragma unroll
            for (int h2 = 0; h2 < 2; h2++) {
                int row = wn + h2 * 16 + (lane & 7) + ((lane >> 4) << 3);
                uint32_t off = (uint32_t)(row * ST + s8 + ((lane & 8) >> 1)) * 4;
                uint32_t t[4];
                ldm_x4(t, sb + SB + off);
                bf[h2 * 2][0] = t[0]; bf[h2 * 2][1] = t[1];
                bf[h2 * 2 + 1][0] = t[2]; bf[h2 * 2 + 1][1] = t[3];
            }
#pragma unroll
            for (int mt = 0; mt < MT; mt++)
#pragma unroll
                for (int nt = 0; nt < 4; nt++)
                    mma_f16(acc[mt][nt], ah[mt], bf[nt]);
        }
    };

    const int nIter = K2 >> 5;   // K/64 (>= 5 always)
    stage(0, 0); CP_COMMIT();
    stage(1, 1); CP_COMMIT();
    for (int it = 0; it < nIter; it++) {
        if (it + 1 < nIter) { CP_WAIT1(); } else { CP_WAIT0(); }
        __syncthreads();
        compute(it % 3);
        if (it + 2 < nIter) {
            stage(it + 2, (it + 2) % 3);
            CP_COMMIT();
        }
    }

    // epilogue
#pragma unroll
    for (int mt = 0; mt < MT; mt++) {
        size_t r0 = rowBase + wm + mt * 16 + g;
#pragma unroll
        for (int nt = 0; nt < 4; nt++) {
            int col = colBase + wn + nt * 8 + t4 * 2;
            float2 bs = *(const float2*)&bias[col];
            float v0 = acc[mt][nt][0] + bs.x;
            float v1 = acc[mt][nt][1] + bs.y;
            float v2 = acc[mt][nt][2] + bs.x;
            float v3 = acc[mt][nt][3] + bs.y;
            if (flags & FLAG_RELU) {
                v0 = fmaxf(v0, 0.f); v1 = fmaxf(v1, 0.f);
                v2 = fmaxf(v2, 0.f); v3 = fmaxf(v3, 0.f);
            }
            if (flags & FLAG_PACK) {
                int N2 = N >> 1, c2 = col >> 1;
                Cpk[r0 * N2 + c2]       = pack2h(v0, v1);
                Cpk[(r0 + 8) * N2 + c2] = pack2h(v2, v3);
            } else {
                *(float2*)&C[r0 * N + col]       = make_float2(v0, v1);
                *(float2*)&C[(r0 + 8) * N + col] = make_float2(v2, v3);
            }
        }
    }
}

#define GPS_SMEM64  (3 * ((128 + 64) * 144))    // 82944
#define GPS_SMEM128 (3 * ((128 + 128) * 144))   // 110592

// ---------------- fp32 tiled SGEMM (input projection only; PE epilogue) ----
__global__ __launch_bounds__(256) void gemm64(
    const float* __restrict__ A, int lda,
    const float* __restrict__ Bw, int ldb,
    const float* __restrict__ bias,
    float* __restrict__ C, int ldc,
    int K, int flags)
{
    __shared__ __align__(16) float As[16][65];
    __shared__ __align__(16) float Bs[16][64];

    int tid = threadIdx.x;
    int ty = tid >> 4, tx = tid & 15;
    size_t rowBase = (size_t)blockIdx.y * 64;
    int colBase = blockIdx.x * 64;
    const float* Ab = A + rowBase * (size_t)lda;
    const float* Bb = Bw + colBase;

    float acc[4][4];
#pragma unroll
    for (int i = 0; i < 4; i++)
#pragma unroll
        for (int j = 0; j < 4; j++) acc[i][j] = 0.f;

    for (int k0 = 0; k0 < K; k0 += 16) {
#pragma unroll
        for (int i = 0; i < 4; i++) {
            int e = tid + i * 256;
            int r = e >> 4, c = e & 15;
            As[c][r] = Ab[(size_t)r * lda + (k0 + c)];
        }
#pragma unroll
        for (int i = 0; i < 4; i++) {
            int e = tid + i * 256;
            int r = e >> 6, c = e & 63;
            Bs[r][c] = Bb[(size_t)(k0 + r) * ldb + c];
        }
        __syncthreads();
#pragma unroll
        for (int k = 0; k < 16; k++) {
            float a0 = As[k][ty * 4 + 0];
            float a1 = As[k][ty * 4 + 1];
            float a2 = As[k][ty * 4 + 2];
            float a3 = As[k][ty * 4 + 3];
            float4 b = *(const float4*)&Bs[k][tx * 4];
            acc[0][0] += a0 * b.x; acc[0][1] += a0 * b.y; acc[0][2] += a0 * b.z; acc[0][3] += a0 * b.w;
            acc[1][0] += a1 * b.x; acc[1][1] += a1 * b.y; acc[1][2] += a1 * b.z; acc[1][3] += a1 * b.w;
            acc[2][0] += a2 * b.x; acc[2][1] += a2 * b.y; acc[2][2] += a2 * b.z; acc[2][3] += a2 * b.w;
            acc[3][0] += a3 * b.x; acc[3][1] += a3 * b.y; acc[3][2] += a3 * b.z; acc[3][3] += a3 * b.w;
        }
        __syncthreads();
    }

    int row0 = (int)rowBase + ty * 4;
    int col0 = colBase + tx * 4;
#pragma unroll
    for (int i = 0; i < 4; i++) {
        int row = row0 + i;
#pragma unroll
        for (int j = 0; j < 4; j++) {
            int col = col0 + j;
            float v = acc[i][j] + bias[col];
            if (flags & FLAG_PE) {
                int s = row % S_;
                int half = col >> 1;
                float div = expf((float)(2 * half) * (-9.210340371976184f / (float)D_));
                float arg = (float)s * div;
                v += (col & 1) ? cosf(arg) : sinf(arg);
            }
            if (flags & FLAG_RELU) v = fmaxf(v, 0.f);
            C[(size_t)row * ldc + col] = v;
        }
    }
}

// ---------------- fused QKV projection + attention: block per (b, h) -------
__global__ __launch_bounds__(256) void attn_fused(
    const float* __restrict__ hsrc,
    const float* __restrict__ Wq, const float* __restrict__ bq,
    const float* __restrict__ Wk, const float* __restrict__ bk,
    const float* __restrict__ Wv, const float* __restrict__ bv,
    int l, uint32_t* __restrict__ headsPk)
{
    __shared__ float sh[S_][DH_ + 1];
    __shared__ float sq[S_][DH_ + 1];
    __shared__ float sk[S_][DH_ + 1];
    __shared__ float sv[S_][DH_ + 1];
    __shared__ float sc[S_][S_ + 1];

    int bh = blockIdx.x;
    int b = bh / H_, h = bh % H_;
    size_t base = ((size_t)b * S_) * D_ + (size_t)h * DH_;
    int tid = threadIdx.x;

    for (int e = tid; e < S_ * DH_; e += 256) {
        int s = e >> 6, d = e & 63;
        sh[s][d] = hsrc[base + (size_t)s * D_ + d];
    }
    __syncthreads();

    size_t woff = ((size_t)l * H_ + h) * DH_ * DH_;
    size_t boff = ((size_t)l * H_ + h) * DH_;
    const float* Wqh = Wq + woff;
    const float* Wkh = Wk + woff;
    const float* Wvh = Wv + woff;

    {
        int e = tid & 63;
        for (int r = tid >> 6; r < 3 * S_; r += 4) {
            int m = r / S_, s = r % S_;
            const float* Wm = (m == 0) ? Wqh : (m == 1) ? Wkh : Wvh;
            const float* bm = (m == 0) ? (bq + boff) : (m == 1) ? (bk + boff) : (bv + boff);
            float acc = bm[e];
#pragma unroll 16
            for (int d = 0; d < DH_; d++) acc += sh[s][d] * Wm[d * DH_ + e];
            if (m == 0) sq[s][e] = acc;
            else if (m == 1) sk[s][e] = acc;
            else sv[s][e] = acc;
        }
    }
    __syncthreads();

    for (int e = tid; e < S_ * S_; e += 256) {
        int i = e / S_, j = e % S_;
        float acc = 0.f;
#pragma unroll
        for (int d = 0; d < DH_; d++) acc += sq[i][d] * sk[j][d];
        sc[i][j] = acc * 0.125f;
    }
    __syncthreads();

    if (tid < S_) {
        float m = -1e30f;
        for (int j = 0; j < S_; j++) m = fmaxf(m, sc[tid][j]);
        float sum = 0.f;
        for (int j = 0; j < S_; j++) {
            float e2 = expf(sc[tid][j] - m);
            sc[tid][j] = e2;
            sum += e2;
        }
        float inv = 1.f / sum;
        for (int j = 0; j < S_; j++) sc[tid][j] *= inv;
    }
    __syncthreads();

    // A @ V -> packed fp16 pairs
    size_t tokBase = (size_t)b * S_;
    for (int e = tid; e < S_ * 32; e += 256) {
        int s = e >> 5, p = e & 31;
        int d0 = p * 2;
        float a0 = 0.f, a1 = 0.f;
#pragma unroll
        for (int j = 0; j < S_; j++) {
            a0 += sc[s][j] * sv[j][d0];
            a1 += sc[s][j] * sv[j][d0 + 1];
        }
        headsPk[(tokBase + s) * (D_ / 2) + h * 32 + p] = pack2h(a0, a1);
    }
}

// ---------------- residual add + LayerNorm: warp per token -----------------
__global__ __launch_bounds__(256) void add_ln_warp(
    float* __restrict__ hb, const float* __restrict__ add,
    const float* __restrict__ gamma, const float* __restrict__ beta,
    uint32_t* __restrict__ outPk, int pack)
{
    int w = threadIdx.x >> 5, lane = threadIdx.x & 31;
    size_t tok = (size_t)blockIdx.x * 8 + w;
    size_t base = tok * D_;

    float2 v[5];
    float s = 0.f;
#pragma unroll
    for (int i = 0; i < 5; i++) {
        int d = lane * 2 + i * 64;
        float2 a = *(const float2*)&hb[base + d];
        float2 r = *(const float2*)&add[base + d];
        v[i].x = a.x + r.x;
        v[i].y = a.y + r.y;
        s += v[i].x + v[i].y;
    }
#pragma unroll
    for (int o = 16; o; o >>= 1) s += __shfl_xor_sync(0xffffffffu, s, o);
    float mean = s * (1.f / (float)D_);

    float s2 = 0.f;
#pragma unroll
    for (int i = 0; i < 5; i++) {
        float dx = v[i].x - mean, dy = v[i].y - mean;
        s2 += dx * dx + dy * dy;
    }
#pragma unroll
    for (int o = 16; o; o >>= 1) s2 += __shfl_xor_sync(0xffffffffu, s2, o);
    float rstd = rsqrtf(s2 * (1.f / (float)D_) + 1e-5f);

#pragma unroll
    for (int i = 0; i < 5; i++) {
        int d = lane * 2 + i * 64;
        float o0 = (v[i].x - mean) * rstd * gamma[d] + beta[d];
        float o1 = (v[i].y - mean) * rstd * gamma[d + 1] + beta[d + 1];
        *(float2*)&hb[base + d] = make_float2(o0, o1);
        if (pack)
            outPk[tok * (D_ / 2) + lane + i * 32] = pack2h(o0, o1);
    }
}

// ---------------- attention pooling + classifier (block per batch row) -----
__global__ __launch_bounds__(320) void pool_cls_kernel(
    const float* __restrict__ hb,
    const float* __restrict__ pool_W, const float* __restrict__ pool_b,
    const float* __restrict__ W1, const float* __restrict__ b1,
    const float* __restrict__ W2, const float* __restrict__ b2,
    float* __restrict__ out)
{
    __shared__ float sscore[S_];
    __shared__ float sz[D_];
    __shared__ float shid[D_ / 2];
    __shared__ float sred[10];

    int b = blockIdx.x;
    int t = threadIdx.x, warp = t >> 5, lane = t & 31;
    const float* hrow = hb + (size_t)b * S_ * D_;

    for (int s = warp; s < S_; s += 10) {
        float acc = 0.f;
        for (int d = lane; d < D_; d += 32) acc += hrow[s * D_ + d] * pool_W[d];
#pragma unroll
        for (int o = 16; o; o >>= 1) acc += __shfl_down_sync(0xffffffffu, acc, o);
        if (lane == 0) sscore[s] = acc + pool_b[0];
    }
    __syncthreads();

    if (t == 0) {
        float m = -1e30f;
        for (int s = 0; s < S_; s++) m = fmaxf(m, sscore[s]);
        float sum = 0.f;
        for (int s = 0; s < S_; s++) {
            float e = expf(sscore[s] - m);
            sscore[s] = e;
            sum += e;
        }
        float inv = 1.f / sum;
        for (int s = 0; s < S_; s++) sscore[s] *= inv;
    }
    __syncthreads();

    {
        float acc = 0.f;
        for (int s = 0; s < S_; s++) acc += sscore[s] * hrow[s * D_ + t];
        sz[t] = acc;
    }
    __syncthreads();

    if (t < D_ / 2) {
        float acc = b1[t];
        for (int d = 0; d < D_; d++) acc += sz[d] * W1[d * (D_ / 2) + t];
        shid[t] = fmaxf(acc, 0.f);
    }
    __syncthreads();

    float p = (t < D_ / 2) ? shid[t] * W2[t] : 0.f;
#pragma unroll
    for (int o = 16; o; o >>= 1) p += __shfl_down_sync(0xffffffffu, p, o);
    if (lane == 0) sred[warp] = p;
    __syncthreads();
    if (t == 0) {
        float tot = 0.f;
        for (int i = 0; i < 10; i++) tot += sred[i];
        float logit = tot + b2[0];
        out[b] = logit;
        out[B_ + b] = 1.f / (1.f + expf(-logit));
    }
}

// ---------------- host launcher -------------------------------------------
extern "C" void kernel_launch(void* const* d_in, const int* in_sizes, int n_in,
                              void* d_out, int out_size)
{
    const float* x      = (const float*)d_in[0];
    const float* in_W   = (const float*)d_in[1];
    const float* in_b   = (const float*)d_in[2];
    const float* Wq     = (const float*)d_in[3];
    const float* bq     = (const float*)d_in[4];
    const float* Wk     = (const float*)d_in[5];
    const float* bk     = (const float*)d_in[6];
    const float* Wv     = (const float*)d_in[7];
    const float* bv     = (const float*)d_in[8];
    const float* Wo     = (const float*)d_in[9];
    const float* bo     = (const float*)d_in[10];
    const float* ln1_g  = (const float*)d_in[11];
    const float* ln1_b  = (const float*)d_in[12];
    const float* W1     = (const float*)d_in[13];
    const float* b1     = (const float*)d_in[14];
    const float* W2     = (const float*)d_in[15];
    const float* b2     = (const float*)d_in[16];
    const float* ln2_g  = (const float*)d_in[17];
    const float* ln2_b  = (const float*)d_in[18];
    const float* pool_W = (const float*)d_in[19];
    const float* pool_b = (const float*)d_in[20];
    const float* cW1    = (const float*)d_in[21];
    const float* cb1    = (const float*)d_in[22];
    const float* cW2    = (const float*)d_in[23];
    const float* cb2    = (const float*)d_in[24];

    float *ph, *ptmp;
    uint32_t *pha, *phd, *pff, *pwo, *pw1, *pw2;
    cudaGetSymbolAddress((void**)&ph, g_h);
    cudaGetSymbolAddress((void**)&ptmp, g_tmp);
    cudaGetSymbolAddress((void**)&pha, g_ha);
    cudaGetSymbolAddress((void**)&phd, g_hd);
    cudaGetSymbolAddress((void**)&pff, g_ff);
    cudaGetSymbolAddress((void**)&pwo, g_wo);
    cudaGetSymbolAddress((void**)&pw1, g_w1);
    cudaGetSymbolAddress((void**)&pw2, g_w2);

    cudaFuncSetAttribute(gemm_ps<64, 2>,
                         cudaFuncAttributeMaxDynamicSharedMemorySize, GPS_SMEM64);
    cudaFuncSetAttribute(gemm_ps<128, 4>,
                         cudaFuncAttributeMaxDynamicSharedMemorySize, GPS_SMEM128);

    // weight conversion (per layer)
    const int woN = D_ * D_ / 2, w1N = D_ * DFF_ / 2, w2N = DFF_ * D_ / 2;
    for (int l = 0; l < L_; l++) {
        convert_w<<<(woN + 255) / 256, 256>>>(Wo + (size_t)l * D_ * D_,
                                              pwo + (size_t)l * woN, D_, D_);
        convert_w<<<(w1N + 255) / 256, 256>>>(W1 + (size_t)l * D_ * DFF_,
                                              pw1 + (size_t)l * w1N, D_, DFF_);
        convert_w<<<(w2N + 255) / 256, 256>>>(W2 + (size_t)l * DFF_ * D_,
                                              pw2 + (size_t)l * w2N, DFF_, D_);
    }

    const dim3 gridIn(D_ / 64, NTOK / 64);
    const dim3 gridD(D_ / 64, NTOK / 128);       // BN=64, N=320
    const dim3 gridF(DFF_ / 128, NTOK / 128);    // BN=128, N=1280

    // input projection + bias + positional encoding (fp32)
    gemm64<<<gridIn, 256>>>(x, FIN_, in_W, D_, in_b, ph, D_, FIN_, FLAG_PE);

    for (int l = 0; l < L_; l++) {
        attn_fused<<<B_ * H_, 256>>>(ph, Wq, bq, Wk, bk, Wv, bv, l, phd);
        // Wo: heads_packed @ Wo -> tmp fp32   (BN=64)
        gemm_ps<64, 2><<<gridD, 256, GPS_SMEM64>>>(phd, D_ / 2,
                                          pwo + (size_t)l * woN,
                                          bo + l * D_, ptmp, nullptr, D_, 0);
        add_ln_warp<<<NTOK / 8, 256>>>(ph, ptmp, ln1_g + l * D_, ln1_b + l * D_,
                                       pha, 1);
        // FFN1: h_packed @ W1 -> ffn packed (relu)   (BN=128)
        gemm_ps<128, 4><<<gridF, 256, GPS_SMEM128>>>(pha, D_ / 2,
                                          pw1 + (size_t)l * w1N,
                                          b1 + l * DFF_, nullptr, pff, DFF_,
                                          FLAG_RELU | FLAG_PACK);
        // FFN2: ffn_packed @ W2 -> tmp fp32   (BN=64)
        gemm_ps<64, 2><<<gridD, 256, GPS_SMEM64>>>(pff, DFF_ / 2,
                                          pw2 + (size_t)l * w2N,
                                          b2 + l * D_, ptmp, nullptr, D_, 0);
        add_ln_warp<<<NTOK / 8, 256>>>(ph, ptmp, ln2_g + l * D_, ln2_b + l * D_,
                                       nullptr, 0);
    }

    pool_cls_kernel<<<B_, 320>>>(ph, pool_W, pool_b, cW1, cb1, cW2, cb2,
                                 (float*)d_out);
}

// round 15
// speedup vs baseline: 2.8866x; 1.0067x over previous
#include <cuda_runtime.h>
#include <cuda_fp16.h>
#include <math.h>
#include <stdint.h>

#define B_    4096
#define S_    30
#define FIN_  80
#define D_    320
#define H_    5
#define DH_   64
#define L_    4
#define DFF_  1280
#define NTOK  (B_ * S_)

#define FLAG_RELU 1
#define FLAG_PE   2
#define FLAG_PACK 4

// ---------------- scratch (device globals; no allocations allowed) ----------
__device__ float g_h[NTOK * D_];
__device__ uint32_t g_tmpk[NTOK * D_ / 2];    // GEMM out packed fp16x2 (pre-LN)
__device__ uint32_t g_ha[NTOK * D_ / 2];      // h packed fp16x2 (FFN1 A)
__device__ uint32_t g_hd[NTOK * D_ / 2];      // heads packed fp16x2 (Wo A)
__device__ uint32_t g_ff[NTOK * DFF_ / 2];    // ffn packed fp16x2 (FFN2 A)
__device__ uint32_t g_wo[L_ * D_ * D_ / 2];
__device__ uint32_t g_w1[L_ * D_ * DFF_ / 2];
__device__ uint32_t g_w2[L_ * DFF_ * D_ / 2];

// ---------------- helpers --------------------------------------------------
__device__ __forceinline__ uint32_t smem_u32(const void* p) {
    uint32_t a;
    asm("{ .reg .u64 t; cvta.to.shared.u64 t, %1; cvt.u32.u64 %0, t; }"
        : "=r"(a) : "l"(p));
    return a;
}

__device__ __forceinline__ uint32_t pack2h(float v0, float v1) {
    __half2 h = __floats2half2_rn(v0, v1);
    return *reinterpret_cast<uint32_t*>(&h);
}

__device__ __forceinline__ float2 unpack2h(uint32_t p) {
    return __half22float2(*reinterpret_cast<__half2*>(&p));
}

__device__ __forceinline__ void mma_f16(float* c, const uint32_t* a, const uint32_t* b) {
    asm volatile(
        "mma.sync.aligned.m16n8k16.row.col.f32.f16.f16.f32 "
        "{%0,%1,%2,%3}, {%4,%5,%6,%7}, {%8,%9}, {%0,%1,%2,%3};\n"
        : "+f"(c[0]), "+f"(c[1]), "+f"(c[2]), "+f"(c[3])
        : "r"(a[0]), "r"(a[1]), "r"(a[2]), "r"(a[3]), "r"(b[0]), "r"(b[1]));
}

__device__ __forceinline__ void ldm_x4(uint32_t* r, uint32_t addr) {
    asm volatile("ldmatrix.sync.aligned.m8n8.x4.shared.b16 {%0,%1,%2,%3}, [%4];"
        : "=r"(r[0]), "=r"(r[1]), "=r"(r[2]), "=r"(r[3]) : "r"(addr));
}

__device__ __forceinline__ void cp16(uint32_t dst, const uint32_t* src) {
    asm volatile("cp.async.cg.shared.global [%0], [%1], 16;" :: "r"(dst), "l"(src));
}
#define CP_COMMIT() asm volatile("cp.async.commit_group;" ::: "memory")
#define CP_WAIT0()  asm volatile("cp.async.wait_group 0;" ::: "memory")
#define CP_WAIT1()  asm volatile("cp.async.wait_group 1;" ::: "memory")

// ---------------- weight conversion (ALL layers/weights in ONE launch) -----
// W[K][N] -> fp16x2 transposed [N][K/2]
__global__ void convert_all(const float* __restrict__ Wo,
                            const float* __restrict__ W1,
                            const float* __restrict__ W2,
                            uint32_t* __restrict__ pwo,
                            uint32_t* __restrict__ pw1,
                            uint32_t* __restrict__ pw2)
{
    const int woN = D_ * D_ / 2;
    const int w1N = D_ * DFF_ / 2;
    const int w2N = DFF_ * D_ / 2;
    const int perL = woN + w1N + w2N;
    int idx = blockIdx.x * 256 + threadIdx.x;
    if (idx >= L_ * perL) return;
    int l = idx / perL, r = idx % perL;

    const float* W;
    uint32_t* out;
    int K, N, rr;
    if (r < woN)            { W = Wo + (size_t)l * D_ * D_;    out = pwo + (size_t)l * woN; K = D_;   N = D_;   rr = r; }
    else if (r < woN + w1N) { W = W1 + (size_t)l * D_ * DFF_;  out = pw1 + (size_t)l * w1N; K = D_;   N = DFF_; rr = r - woN; }
    else                    { W = W2 + (size_t)l * DFF_ * D_;  out = pw2 + (size_t)l * w2N; K = DFF_; N = D_;   rr = r - woN - w1N; }

    int K2 = K >> 1;
    int n = rr / K2, k2 = rr % K2;
    float v0 = W[(size_t)(2 * k2) * N + n];
    float v1 = W[(size_t)(2 * k2 + 1) * N + n];
    out[rr] = pack2h(v0, v1);
}

// ======================================================================
// Pure fp16 GEMM: C = A @ B + bias [+relu], output packed fp16x2.
// A fp16x2 [M][K2]; B fp16x2 transposed [N][K2].
// BM=128, BK=64 (32 u32), 256 thr; single-sync 3-stage cp.async pipe.
//   BN=64:  8 warps 4x2, warp tile 32x32 (MT=2)
//   BN=128: 8 warps 2x4, warp tile 64x32 (MT=4)
// smem row stride 36 u32 (144B = 9x16: cp.async-aligned; ldmatrix rows
// on banks 4r+c -> all 32 banks once per 8x8 matrix: conflict-free).
// Stage = (128+BN)*144 bytes; 3 stages.
// ======================================================================
template<int BN, int MT>
__global__ __launch_bounds__(256) void gemm_ps(
    const uint32_t* __restrict__ Apk, int K2,
    const uint32_t* __restrict__ Bpk,
    const float* __restrict__ bias,
    uint32_t* __restrict__ Cpk,
    int N, int flags)
{
    constexpr int ST   = 36;                 // u32 per smem row (32 data + 4 pad)
    constexpr int SA   = 0;
    constexpr int SB   = 128 * ST * 4;       // 18432
    constexpr int STAGE = SB + BN * ST * 4;

    extern __shared__ __align__(1024) char smem[];
    const uint32_t sbase = smem_u32(smem);
    const int tid = threadIdx.x;
    const int lane = tid & 31;
    const int w = tid >> 5;
    const int g = lane >> 2, t4 = lane & 3;
    const int wm = (BN == 64) ? (w >> 1) * 32 : (w >> 2) * 64;
    const int wn = (BN == 64) ? (w & 1) * 32 : (w & 3) * 32;

    const size_t rowBase = (size_t)blockIdx.y * 128;
    const int    colBase = blockIdx.x * BN;

    const uint32_t* A_g = Apk + rowBase * K2;
    const uint32_t* B_g = Bpk + (size_t)colBase * K2;

    float acc[MT][4][4];
#pragma unroll
    for (int mt = 0; mt < MT; mt++)
#pragma unroll
        for (int nt = 0; nt < 4; nt++)
#pragma unroll
            for (int i = 0; i < 4; i++) acc[mt][nt][i] = 0.f;

    auto stage = [&](int it, int slot) {
        uint32_t sb = sbase + slot * STAGE;
        int k2o = it * 32;
#pragma unroll
        for (int j = 0; j < 4; j++) {        // A: 128 rows x 8 chunks
            int idx = tid + j * 256;
            int row = idx >> 3, ch = (idx & 7) * 4;
            uint32_t so = (uint32_t)(row * ST + ch) * 4;
            cp16(sb + SA + so, A_g + (size_t)row * K2 + k2o + ch);
        }
#pragma unroll
        for (int j = 0; j < BN / 32; j++) {  // B: BN rows x 8 chunks
            int idx = tid + j * 256;
            int row = idx >> 3, ch = (idx & 7) * 4;
            uint32_t so = (uint32_t)(row * ST + ch) * 4;
            cp16(sb + SB + so, B_g + (size_t)row * K2 + k2o + ch);
        }
    };

    auto compute = [&](int slot) {
        uint32_t sb = sbase + slot * STAGE;
#pragma unroll
        for (int s = 0; s < 4; s++) {
            const int s8 = s * 8;
            uint32_t ah[MT][4], bf[4][2];
#pragma unroll
            for (int mt = 0; mt < MT; mt++) {
                int row = wm + mt * 16 + (lane & 15);
                uint32_t off = (uint32_t)(row * ST + s8 + ((lane >> 4) << 2)) * 4;
                ldm_x4(ah[mt], sb + SA + off);
            }
#pragma unroll
            for (int h2 = 0; h2 < 2; h2++) {
                int row = wn + h2 * 16 + (lane & 7) + ((lane >> 4) << 3);
                uint32_t off = (uint32_t)(row * ST + s8 + ((lane & 8) >> 1)) * 4;
                uint32_t t[4];
                ldm_x4(t, sb + SB + off);
                bf[h2 * 2][0] = t[0]; bf[h2 * 2][1] = t[1];
                bf[h2 * 2 + 1][0] = t[2]; bf[h2 * 2 + 1][1] = t[3];
            }
#pragma unroll
            for (int mt = 0; mt < MT; mt++)
#pragma unroll
                for (int nt = 0; nt < 4; nt++)
                    mma_f16(acc[mt][nt], ah[mt], bf[nt]);
        }
    };

    const int nIter = K2 >> 5;   // K/64 (>= 5 always)
    stage(0, 0); CP_COMMIT();
    stage(1, 1); CP_COMMIT();
    for (int it = 0; it < nIter; it++) {
        if (it + 1 < nIter) { CP_WAIT1(); } else { CP_WAIT0(); }
        __syncthreads();
        compute(it % 3);
        if (it + 2 < nIter) {
            stage(it + 2, (it + 2) % 3);
            CP_COMMIT();
        }
    }

    // epilogue: bias [+relu], packed fp16 output
    const int N2 = N >> 1;
#pragma unroll
    for (int mt = 0; mt < MT; mt++) {
        size_t r0 = rowBase + wm + mt * 16 + g;
#pragma unroll
        for (int nt = 0; nt < 4; nt++) {
            int col = colBase + wn + nt * 8 + t4 * 2;
            float2 bs = *(const float2*)&bias[col];
            float v0 = acc[mt][nt][0] + bs.x;
            float v1 = acc[mt][nt][1] + bs.y;
            float v2 = acc[mt][nt][2] + bs.x;
            float v3 = acc[mt][nt][3] + bs.y;
            if (flags & FLAG_RELU) {
                v0 = fmaxf(v0, 0.f); v1 = fmaxf(v1, 0.f);
                v2 = fmaxf(v2, 0.f); v3 = fmaxf(v3, 0.f);
            }
            int c2 = col >> 1;
            Cpk[r0 * N2 + c2]       = pack2h(v0, v1);
            Cpk[(r0 + 8) * N2 + c2] = pack2h(v2, v3);
        }
    }
}

#define GPS_SMEM64  (3 * ((128 + 64) * 144))    // 82944
#define GPS_SMEM128 (3 * ((128 + 128) * 144))   // 110592

// ---------------- fp32 tiled SGEMM (input projection only; PE epilogue) ----
__global__ __launch_bounds__(256) void gemm64(
    const float* __restrict__ A, int lda,
    const float* __restrict__ Bw, int ldb,
    const float* __restrict__ bias,
    float* __restrict__ C, int ldc,
    int K, int flags)
{
    __shared__ __align__(16) float As[16][65];
    __shared__ __align__(16) float Bs[16][64];

    int tid = threadIdx.x;
    int ty = tid >> 4, tx = tid & 15;
    size_t rowBase = (size_t)blockIdx.y * 64;
    int colBase = blockIdx.x * 64;
    const float* Ab = A + rowBase * (size_t)lda;
    const float* Bb = Bw + colBase;

    float acc[4][4];
#pragma unroll
    for (int i = 0; i < 4; i++)
#pragma unroll
        for (int j = 0; j < 4; j++) acc[i][j] = 0.f;

    for (int k0 = 0; k0 < K; k0 += 16) {
#pragma unroll
        for (int i = 0; i < 4; i++) {
            int e = tid + i * 256;
            int r = e >> 4, c = e & 15;
            As[c][r] = Ab[(size_t)r * lda + (k0 + c)];
        }
#pragma unroll
        for (int i = 0; i < 4; i++) {
            int e = tid + i * 256;
            int r = e >> 6, c = e & 63;
            Bs[r][c] = Bb[(size_t)(k0 + r) * ldb + c];
        }
        __syncthreads();
#pragma unroll
        for (int k = 0; k < 16; k++) {
            float a0 = As[k][ty * 4 + 0];
            float a1 = As[k][ty * 4 + 1];
            float a2 = As[k][ty * 4 + 2];
            float a3 = As[k][ty * 4 + 3];
            float4 b = *(const float4*)&Bs[k][tx * 4];
            acc[0][0] += a0 * b.x; acc[0][1] += a0 * b.y; acc[0][2] += a0 * b.z; acc[0][3] += a0 * b.w;
            acc[1][0] += a1 * b.x; acc[1][1] += a1 * b.y; acc[1][2] += a1 * b.z; acc[1][3] += a1 * b.w;
            acc[2][0] += a2 * b.x; acc[2][1] += a2 * b.y; acc[2][2] += a2 * b.z; acc[2][3] += a2 * b.w;
            acc[3][0] += a3 * b.x; acc[3][1] += a3 * b.y; acc[3][2] += a3 * b.z; acc[3][3] += a3 * b.w;
        }
        __syncthreads();
    }

    int row0 = (int)rowBase + ty * 4;
    int col0 = colBase + tx * 4;
#pragma unroll
    for (int i = 0; i < 4; i++) {
        int row = row0 + i;
#pragma unroll
        for (int j = 0; j < 4; j++) {
            int col = col0 + j;
            float v = acc[i][j] + bias[col];
            if (flags & FLAG_PE) {
                int s = row % S_;
                int half = col >> 1;
                float div = expf((float)(2 * half) * (-9.210340371976184f / (float)D_));
                float arg = (float)s * div;
                v += (col & 1) ? cosf(arg) : sinf(arg);
            }
            if (flags & FLAG_RELU) v = fmaxf(v, 0.f);
            C[(size_t)row * ldc + col] = v;
        }
    }
}

// ---------------- fused QKV projection + attention: block per (b, h) -------
__global__ __launch_bounds__(256) void attn_fused(
    const float* __restrict__ hsrc,
    const float* __restrict__ Wq, const float* __restrict__ bq,
    const float* __restrict__ Wk, const float* __restrict__ bk,
    const float* __restrict__ Wv, const float* __restrict__ bv,
    int l, uint32_t* __restrict__ headsPk)
{
    __shared__ float sh[S_][DH_ + 1];
    __shared__ float sq[S_][DH_ + 1];
    __shared__ float sk[S_][DH_ + 1];
    __shared__ float sv[S_][DH_ + 1];
    __shared__ float sc[S_][S_ + 1];

    int bh = blockIdx.x;
    int b = bh / H_, h = bh % H_;
    size_t base = ((size_t)b * S_) * D_ + (size_t)h * DH_;
    int tid = threadIdx.x;

    for (int e = tid; e < S_ * DH_; e += 256) {
        int s = e >> 6, d = e & 63;
        sh[s][d] = hsrc[base + (size_t)s * D_ + d];
    }
    __syncthreads();

    size_t woff = ((size_t)l * H_ + h) * DH_ * DH_;
    size_t boff = ((size_t)l * H_ + h) * DH_;
    const float* Wqh = Wq + woff;
    const float* Wkh = Wk + woff;
    const float* Wvh = Wv + woff;

    {
        int e = tid & 63;
        for (int r = tid >> 6; r < 3 * S_; r += 4) {
            int m = r / S_, s = r % S_;
            const float* Wm = (m == 0) ? Wqh : (m == 1) ? Wkh : Wvh;
            const float* bm = (m == 0) ? (bq + boff) : (m == 1) ? (bk + boff) : (bv + boff);
            float acc = bm[e];
#pragma unroll 16
            for (int d = 0; d < DH_; d++) acc += sh[s][d] * Wm[d * DH_ + e];
            if (m == 0) sq[s][e] = acc;
            else if (m == 1) sk[s][e] = acc;
            else sv[s][e] = acc;
        }
    }
    __syncthreads();

    for (int e = tid; e < S_ * S_; e += 256) {
        int i = e / S_, j = e % S_;
        float acc = 0.f;
#pragma unroll
        for (int d = 0; d < DH_; d++) acc += sq[i][d] * sk[j][d];
        sc[i][j] = acc * 0.125f;
    }
    __syncthreads();

    if (tid < S_) {
        float m = -1e30f;
        for (int j = 0; j < S_; j++) m = fmaxf(m, sc[tid][j]);
        float sum = 0.f;
        for (int j = 0; j < S_; j++) {
            float e2 = expf(sc[tid][j] - m);
            sc[tid][j] = e2;
            sum += e2;
        }
        float inv = 1.f / sum;
        for (int j = 0; j < S_; j++) sc[tid][j] *= inv;
    }
    __syncthreads();

    // A @ V -> packed fp16 pairs
    size_t tokBase = (size_t)b * S_;
    for (int e = tid; e < S_ * 32; e += 256) {
        int s = e >> 5, p = e & 31;
        int d0 = p * 2;
        float a0 = 0.f, a1 = 0.f;
#pragma unroll
        for (int j = 0; j < S_; j++) {
            a0 += sc[s][j] * sv[j][d0];
            a1 += sc[s][j] * sv[j][d0 + 1];
        }
        headsPk[(tokBase + s) * (D_ / 2) + h * 32 + p] = pack2h(a0, a1);
    }
}

// ---------------- residual add (packed fp16) + LayerNorm: warp per token ---
__global__ __launch_bounds__(256) void add_ln_warp(
    float* __restrict__ hb, const uint32_t* __restrict__ addPk,
    const float* __restrict__ gamma, const float* __restrict__ beta,
    uint32_t* __restrict__ outPk, int pack)
{
    int w = threadIdx.x >> 5, lane = threadIdx.x & 31;
    size_t tok = (size_t)blockIdx.x * 8 + w;
    size_t base = tok * D_;

    float2 v[5];
    float s = 0.f;
#pragma unroll
    for (int i = 0; i < 5; i++) {
        int d = lane * 2 + i * 64;
        float2 a = *(const float2*)&hb[base + d];
        float2 r = unpack2h(addPk[tok * (D_ / 2) + lane + i * 32]);
        v[i].x = a.x + r.x;
        v[i].y = a.y + r.y;
        s += v[i].x + v[i].y;
    }
#pragma unroll
    for (int o = 16; o; o >>= 1) s += __shfl_xor_sync(0xffffffffu, s, o);
    float mean = s * (1.f / (float)D_);

    float s2 = 0.f;
#pragma unroll
    for (int i = 0; i < 5; i++) {
        float dx = v[i].x - mean, dy = v[i].y - mean;
        s2 += dx * dx + dy * dy;
    }
#pragma unroll
    for (int o = 16; o; o >>= 1) s2 += __shfl_xor_sync(0xffffffffu, s2, o);
    float rstd = rsqrtf(s2 * (1.f / (float)D_) + 1e-5f);

#pragma unroll
    for (int i = 0; i < 5; i++) {
        int d = lane * 2 + i * 64;
        float o0 = (v[i].x - mean) * rstd * gamma[d] + beta[d];
        float o1 = (v[i].y - mean) * rstd * gamma[d + 1] + beta[d + 1];
        *(float2*)&hb[base + d] = make_float2(o0, o1);
        if (pack)
            outPk[tok * (D_ / 2) + lane + i * 32] = pack2h(o0, o1);
    }
}

// ---------------- attention pooling + classifier (block per batch row) -----
__global__ __launch_bounds__(320) void pool_cls_kernel(
    const float* __restrict__ hb,
    const float* __restrict__ pool_W, const float* __restrict__ pool_b,
    const float* __restrict__ W1, const float* __restrict__ b1,
    const float* __restrict__ W2, const float* __restrict__ b2,
    float* __restrict__ out)
{
    __shared__ float sscore[S_];
    __shared__ float sz[D_];
    __shared__ float shid[D_ / 2];
    __shared__ float sred[10];

    int b = blockIdx.x;
    int t = threadIdx.x, warp = t >> 5, lane = t & 31;
    const float* hrow = hb + (size_t)b * S_ * D_;

    for (int s = warp; s < S_; s += 10) {
        float acc = 0.f;
        for (int d = lane; d < D_; d += 32) acc += hrow[s * D_ + d] * pool_W[d];
#pragma unroll
        for (int o = 16; o; o >>= 1) acc += __shfl_down_sync(0xffffffffu, acc, o);
        if (lane == 0) sscore[s] = acc + pool_b[0];
    }
    __syncthreads();

    if (t == 0) {
        float m = -1e30f;
        for (int s = 0; s < S_; s++) m = fmaxf(m, sscore[s]);
        float sum = 0.f;
        for (int s = 0; s < S_; s++) {
            float e = expf(sscore[s] - m);
            sscore[s] = e;
            sum += e;
        }
        float inv = 1.f / sum;
        for (int s = 0; s < S_; s++) sscore[s] *= inv;
    }
    __syncthreads();

    {
        float acc = 0.f;
        for (int s = 0; s < S_; s++) acc += sscore[s] * hrow[s * D_ + t];
        sz[t] = acc;
    }
    __syncthreads();

    if (t < D_ / 2) {
        float acc = b1[t];
        for (int d = 0; d < D_; d++) acc += sz[d] * W1[d * (D_ / 2) + t];
        shid[t] = fmaxf(acc, 0.f);
    }
    __syncthreads();

    float p = (t < D_ / 2) ? shid[t] * W2[t] : 0.f;
#pragma unroll
    for (int o = 16; o; o >>= 1) p += __shfl_down_sync(0xffffffffu, p, o);
    if (lane == 0) sred[warp] = p;
    __syncthreads();
    if (t == 0) {
        float tot = 0.f;
        for (int i = 0; i < 10; i++) tot += sred[i];
        float logit = tot + b2[0];
        out[b] = logit;
        out[B_ + b] = 1.f / (1.f + expf(-logit));
    }
}

// ---------------- host launcher -------------------------------------------
extern "C" void kernel_launch(void* const* d_in, const int* in_sizes, int n_in,
                              void* d_out, int out_size)
{
    const float* x      = (const float*)d_in[0];
    const float* in_W   = (const float*)d_in[1];
    const float* in_b   = (const float*)d_in[2];
    const float* Wq     = (const float*)d_in[3];
    const float* bq     = (const float*)d_in[4];
    const float* Wk     = (const float*)d_in[5];
    const float* bk     = (const float*)d_in[6];
    const float* Wv     = (const float*)d_in[7];
    const float* bv     = (const float*)d_in[8];
    const float* Wo     = (const float*)d_in[9];
    const float* bo     = (const float*)d_in[10];
    const float* ln1_g  = (const float*)d_in[11];
    const float* ln1_b  = (const float*)d_in[12];
    const float* W1     = (const float*)d_in[13];
    const float* b1     = (const float*)d_in[14];
    const float* W2     = (const float*)d_in[15];
    const float* b2     = (const float*)d_in[16];
    const float* ln2_g  = (const float*)d_in[17];
    const float* ln2_b  = (const float*)d_in[18];
    const float* pool_W = (const float*)d_in[19];
    const float* pool_b = (const float*)d_in[20];
    const float* cW1    = (const float*)d_in[21];
    const float* cb1    = (const float*)d_in[22];
    const float* cW2    = (const float*)d_in[23];
    const float* cb2    = (const float*)d_in[24];

    float* ph;
    uint32_t *ptmpk, *pha, *phd, *pff, *pwo, *pw1, *pw2;
    cudaGetSymbolAddress((void**)&ph, g_h);
    cudaGetSymbolAddress((void**)&ptmpk, g_tmpk);
    cudaGetSymbolAddress((void**)&pha, g_ha);
    cudaGetSymbolAddress((void**)&phd, g_hd);
    cudaGetSymbolAddress((void**)&pff, g_ff);
    cudaGetSymbolAddress((void**)&pwo, g_wo);
    cudaGetSymbolAddress((void**)&pw1, g_w1);
    cudaGetSymbolAddress((void**)&pw2, g_w2);

    cudaFuncSetAttribute(gemm_ps<64, 2>,
                         cudaFuncAttributeMaxDynamicSharedMemorySize, GPS_SMEM64);
    cudaFuncSetAttribute(gemm_ps<128, 4>,
                         cudaFuncAttributeMaxDynamicSharedMemorySize, GPS_SMEM128);

    // launch 0: all weight conversions in one kernel
    const int woN = D_ * D_ / 2, w1N = D_ * DFF_ / 2, w2N = DFF_ * D_ / 2;
    const int totalConv = L_ * (woN + w1N + w2N);
    convert_all<<<(totalConv + 255) / 256, 256>>>(Wo, W1, W2, pwo, pw1, pw2);

    const dim3 gridIn(D_ / 64, NTOK / 64);
    const dim3 gridD(D_ / 64, NTOK / 128);       // BN=64, N=320
    const dim3 gridF(DFF_ / 128, NTOK / 128);    // BN=128, N=1280

    // launch 1: input projection + bias + positional encoding (fp32)
    gemm64<<<gridIn, 256>>>(x, FIN_, in_W, D_, in_b, ph, D_, FIN_, FLAG_PE);

    for (int l = 0; l < L_; l++) {
        // launch 2 (l=0): attention
        attn_fused<<<B_ * H_, 256>>>(ph, Wq, bq, Wk, bk, Wv, bv, l, phd);
        // launch 3: Wo GEMM -> packed tmp
        gemm_ps<64, 2><<<gridD, 256, GPS_SMEM64>>>(phd, D_ / 2,
                                          pwo + (size_t)l * woN,
                                          bo + l * D_, ptmpk, D_, 0);
        // launch 4: add+LN (packs h for FFN1)
        add_ln_warp<<<NTOK / 8, 256>>>(ph, ptmpk, ln1_g + l * D_, ln1_b + l * D_,
                                       pha, 1);
        // launch 5 (l=0): FFN1 GEMM (ncu profile target)
        gemm_ps<128, 4><<<gridF, 256, GPS_SMEM128>>>(pha, D_ / 2,
                                          pw1 + (size_t)l * w1N,
                                          b1 + l * DFF_, pff, DFF_,
                                          FLAG_RELU);
        // FFN2 GEMM -> packed tmp
        gemm_ps<64, 2><<<gridD, 256, GPS_SMEM64>>>(pff, DFF_ / 2,
                                          pw2 + (size_t)l * w2N,
                                          b2 + l * D_, ptmpk, D_, 0);
        add_ln_warp<<<NTOK / 8, 256>>>(ph, ptmpk, ln2_g + l * D_, ln2_b + l * D_,
                                       nullptr, 0);
    }

    pool_cls_kernel<<<B_, 320>>>(ph, pool_W, pool_b, cW1, cb1, cW2, cb2,
                                 (float*)d_out);
}

// round 16
// speedup vs baseline: 4.9919x; 1.7293x over previous
#include <cuda_runtime.h>
#include <cuda_fp16.h>
#include <math.h>
#include <stdint.h>

#define B_    4096
#define S_    30
#define FIN_  80
#define D_    320
#define H_    5
#define DH_   64
#define L_    4
#define DFF_  1280
#define NTOK  (B_ * S_)
#define NQKV  (3 * D_)        // 960

#define FLAG_RELU 1
#define FLAG_PE   2

// ---------------- scratch (device globals; no allocations allowed) ----------
__device__ float g_h[NTOK * D_];
__device__ uint32_t g_tmpk[NTOK * D_ / 2];     // GEMM out packed fp16x2 (pre-LN)
__device__ uint32_t g_ha[NTOK * D_ / 2];       // h packed fp16x2 (QKV + FFN1 A)
__device__ uint32_t g_hd[NTOK * D_ / 2];       // heads packed fp16x2 (Wo A)
__device__ uint32_t g_ff[NTOK * DFF_ / 2];     // ffn packed fp16x2 (FFN2 A)
__device__ uint32_t g_qkv[NTOK * NQKV / 2];    // qkv packed fp16x2
__device__ uint32_t g_wo[L_ * D_ * D_ / 2];
__device__ uint32_t g_w1[L_ * D_ * DFF_ / 2];
__device__ uint32_t g_w2[L_ * DFF_ * D_ / 2];
__device__ uint32_t g_wqkv[L_ * NQKV * D_ / 2];  // block-diagonal, transposed
__device__ float    g_bqkv[L_ * NQKV];

// ---------------- helpers --------------------------------------------------
__device__ __forceinline__ uint32_t smem_u32(const void* p) {
    uint32_t a;
    asm("{ .reg .u64 t; cvta.to.shared.u64 t, %1; cvt.u32.u64 %0, t; }"
        : "=r"(a) : "l"(p));
    return a;
}

__device__ __forceinline__ uint32_t pack2h(float v0, float v1) {
    __half2 h = __floats2half2_rn(v0, v1);
    return *reinterpret_cast<uint32_t*>(&h);
}

__device__ __forceinline__ float2 unpack2h(uint32_t p) {
    return __half22float2(*reinterpret_cast<__half2*>(&p));
}

__device__ __forceinline__ void mma_f16(float* c, const uint32_t* a, const uint32_t* b) {
    asm volatile(
        "mma.sync.aligned.m16n8k16.row.col.f32.f16.f16.f32 "
        "{%0,%1,%2,%3}, {%4,%5,%6,%7}, {%8,%9}, {%0,%1,%2,%3};\n"
        : "+f"(c[0]), "+f"(c[1]), "+f"(c[2]), "+f"(c[3])
        : "r"(a[0]), "r"(a[1]), "r"(a[2]), "r"(a[3]), "r"(b[0]), "r"(b[1]));
}

__device__ __forceinline__ void ldm_x4(uint32_t* r, uint32_t addr) {
    asm volatile("ldmatrix.sync.aligned.m8n8.x4.shared.b16 {%0,%1,%2,%3}, [%4];"
        : "=r"(r[0]), "=r"(r[1]), "=r"(r[2]), "=r"(r[3]) : "r"(addr));
}

__device__ __forceinline__ void cp16(uint32_t dst, const uint32_t* src) {
    asm volatile("cp.async.cg.shared.global [%0], [%1], 16;" :: "r"(dst), "l"(src));
}
#define CP_COMMIT() asm volatile("cp.async.commit_group;" ::: "memory")
#define CP_WAIT0()  asm volatile("cp.async.wait_group 0;" ::: "memory")
#define CP_WAIT1()  asm volatile("cp.async.wait_group 1;" ::: "memory")

// ---------------- weight conversion (ALL weights in ONE launch) -------------
// Dense W[K][N] -> fp16x2 transposed [N][K/2]; plus block-diagonal QKV
// weight [D_ -> NQKV] and fused QKV bias.
__global__ void convert_all(const float* __restrict__ Wo,
                            const float* __restrict__ W1,
                            const float* __restrict__ W2,
                            const float* __restrict__ Wq,
                            const float* __restrict__ Wk,
                            const float* __restrict__ Wv,
                            const float* __restrict__ bq,
                            const float* __restrict__ bk,
                            const float* __restrict__ bv,
                            uint32_t* __restrict__ pwo,
                            uint32_t* __restrict__ pw1,
                            uint32_t* __restrict__ pw2,
                            uint32_t* __restrict__ pwqkv,
                            float* __restrict__ pbqkv)
{
    const int woN = D_ * D_ / 2;
    const int w1N = D_ * DFF_ / 2;
    const int w2N = DFF_ * D_ / 2;
    const int qkN = NQKV * D_ / 2;
    const int qbN = NQKV;
    const int perL = woN + w1N + w2N + qkN + qbN;
    int idx = blockIdx.x * 256 + threadIdx.x;
    if (idx >= L_ * perL) return;
    int l = idx / perL, r = idx % perL;

    if (r < woN + w1N + w2N) {
        const float* W;
        uint32_t* out;
        int K, N, rr;
        if (r < woN)            { W = Wo + (size_t)l * D_ * D_;    out = pwo + (size_t)l * woN; K = D_;   N = D_;   rr = r; }
        else if (r < woN + w1N) { W = W1 + (size_t)l * D_ * DFF_;  out = pw1 + (size_t)l * w1N; K = D_;   N = DFF_; rr = r - woN; }
        else                    { W = W2 + (size_t)l * DFF_ * D_;  out = pw2 + (size_t)l * w2N; K = DFF_; N = D_;   rr = r - woN - w1N; }
        int K2 = K >> 1;
        int n = rr / K2, k2 = rr % K2;
        out[rr] = pack2h(W[(size_t)(2 * k2) * N + n], W[(size_t)(2 * k2 + 1) * N + n]);
    } else if (r < woN + w1N + w2N + qkN) {
        int rr = r - (woN + w1N + w2N);
        const int K2 = D_ / 2;            // 160
        int n = rr / K2, k2 = rr % K2;
        int m = n / D_, nl = n % D_;
        int h = nl >> 6, e = nl & 63;
        const float* Wm = (m == 0) ? Wq : (m == 1) ? Wk : Wv;
        int d0 = 2 * k2 - h * 64;
        float v0 = 0.f, v1 = 0.f;
        if (d0 >= 0 && d0 < 64) {
            size_t base = (size_t)(l * H_ + h) * 64 * 64;
            v0 = Wm[base + (size_t)d0 * 64 + e];
            v1 = Wm[base + (size_t)(d0 + 1) * 64 + e];
        }
        pwqkv[(size_t)l * qkN + rr] = pack2h(v0, v1);
    } else {
        int rr = r - (woN + w1N + w2N + qkN);
        int m = rr / D_, nl = rr % D_;
        const float* bm = (m == 0) ? bq : (m == 1) ? bk : bv;
        pbqkv[l * NQKV + rr] = bm[l * D_ + nl];
    }
}

// ======================================================================
// Pure fp16 GEMM: C = A @ B + bias [+relu], output packed fp16x2.
// A fp16x2 [M][K2]; B fp16x2 transposed [N][K2].
// BM=128, BK=64 (32 u32), 256 thr; single-sync 3-stage cp.async pipe.
//   BN=64:  8 warps 4x2, warp tile 32x32 (MT=2)
//   BN=128: 8 warps 2x4, warp tile 64x32 (MT=4)
// smem row stride 36 u32 (144B, cp.async-aligned; ldmatrix conflict-free).
// ======================================================================
template<int BN, int MT>
__global__ __launch_bounds__(256) void gemm_ps(
    const uint32_t* __restrict__ Apk, int K2,
    const uint32_t* __restrict__ Bpk,
    const float* __restrict__ bias,
    uint32_t* __restrict__ Cpk,
    int N, int flags)
{
    constexpr int ST   = 36;
    constexpr int SA   = 0;
    constexpr int SB   = 128 * ST * 4;       // 18432
    constexpr int STAGE = SB + BN * ST * 4;

    extern __shared__ __align__(1024) char smem[];
    const uint32_t sbase = smem_u32(smem);
    const int tid = threadIdx.x;
    const int lane = tid & 31;
    const int w = tid >> 5;
    const int g = lane >> 2, t4 = lane & 3;
    const int wm = (BN == 64) ? (w >> 1) * 32 : (w >> 2) * 64;
    const int wn = (BN == 64) ? (w & 1) * 32 : (w & 3) * 32;

    const size_t rowBase = (size_t)blockIdx.y * 128;
    const int    colBase = blockIdx.x * BN;

    const uint32_t* A_g = Apk + rowBase * K2;
    const uint32_t* B_g = Bpk + (size_t)colBase * K2;

    float acc[MT][4][4];
#pragma unroll
    for (int mt = 0; mt < MT; mt++)
#pragma unroll
        for (int nt = 0; nt < 4; nt++)
#pragma unroll
            for (int i = 0; i < 4; i++) acc[mt][nt][i] = 0.f;

    auto stage = [&](int it, int slot) {
        uint32_t sb = sbase + slot * STAGE;
        int k2o = it * 32;
#pragma unroll
        for (int j = 0; j < 4; j++) {
            int idx = tid + j * 256;
            int row = idx >> 3, ch = (idx & 7) * 4;
            uint32_t so = (uint32_t)(row * ST + ch) * 4;
            cp16(sb + SA + so, A_g + (size_t)row * K2 + k2o + ch);
        }
#pragma unroll
        for (int j = 0; j < BN / 32; j++) {
            int idx = tid + j * 256;
            int row = idx >> 3, ch = (idx & 7) * 4;
            uint32_t so = (uint32_t)(row * ST + ch) * 4;
            cp16(sb + SB + so, B_g + (size_t)row * K2 + k2o + ch);
        }
    };

    auto compute = [&](int slot) {
        uint32_t sb = sbase + slot * STAGE;
#pragma unroll
        for (int s = 0; s < 4; s++) {
            const int s8 = s * 8;
            uint32_t ah[MT][4], bf[4][2];
#pragma unroll
            for (int mt = 0; mt < MT; mt++) {
                int row = wm + mt * 16 + (lane & 15);
                uint32_t off = (uint32_t)(row * ST + s8 + ((lane >> 4) << 2)) * 4;
                ldm_x4(ah[mt], sb + SA + off);
            }
#pragma unroll
            for (int h2 = 0; h2 < 2; h2++) {
                int row = wn + h2 * 16 + (lane & 7) + ((lane >> 4) << 3);
                uint32_t off = (uint32_t)(row * ST + s8 + ((lane & 8) >> 1)) * 4;
                uint32_t t[4];
                ldm_x4(t, sb + SB + off);
                bf[h2 * 2][0] = t[0]; bf[h2 * 2][1] = t[1];
                bf[h2 * 2 + 1][0] = t[2]; bf[h2 * 2 + 1][1] = t[3];
            }
#pragma unroll
            for (int mt = 0; mt < MT; mt++)
#pragma unroll
                for (int nt = 0; nt < 4; nt++)
                    mma_f16(acc[mt][nt], ah[mt], bf[nt]);
        }
    };

    const int nIter = K2 >> 5;
    stage(0, 0); CP_COMMIT();
    stage(1, 1); CP_COMMIT();
    for (int it = 0; it < nIter; it++) {
        if (it + 1 < nIter) { CP_WAIT1(); } else { CP_WAIT0(); }
        __syncthreads();
        compute(it % 3);
        if (it + 2 < nIter) {
            stage(it + 2, (it + 2) % 3);
            CP_COMMIT();
        }
    }

    const int N2 = N >> 1;
#pragma unroll
    for (int mt = 0; mt < MT; mt++) {
        size_t r0 = rowBase + wm + mt * 16 + g;
#pragma unroll
        for (int nt = 0; nt < 4; nt++) {
            int col = colBase + wn + nt * 8 + t4 * 2;
            float2 bs = *(const float2*)&bias[col];
            float v0 = acc[mt][nt][0] + bs.x;
            float v1 = acc[mt][nt][1] + bs.y;
            float v2 = acc[mt][nt][2] + bs.x;
            float v3 = acc[mt][nt][3] + bs.y;
            if (flags & FLAG_RELU) {
                v0 = fmaxf(v0, 0.f); v1 = fmaxf(v1, 0.f);
                v2 = fmaxf(v2, 0.f); v3 = fmaxf(v3, 0.f);
            }
            int c2 = col >> 1;
            Cpk[r0 * N2 + c2]       = pack2h(v0, v1);
            Cpk[(r0 + 8) * N2 + c2] = pack2h(v2, v3);
        }
    }
}

#define GPS_SMEM64  (3 * ((128 + 64) * 144))    // 82944
#define GPS_SMEM128 (3 * ((128 + 128) * 144))   // 110592

// ---------------- fp32 SGEMM (input projection; PE epilogue; packs out) ----
__global__ __launch_bounds__(256) void gemm64(
    const float* __restrict__ A, int lda,
    const float* __restrict__ Bw, int ldb,
    const float* __restrict__ bias,
    float* __restrict__ C, uint32_t* __restrict__ Cpk, int ldc,
    int K, int flags)
{
    __shared__ __align__(16) float As[16][65];
    __shared__ __align__(16) float Bs[16][64];

    int tid = threadIdx.x;
    int ty = tid >> 4, tx = tid & 15;
    size_t rowBase = (size_t)blockIdx.y * 64;
    int colBase = blockIdx.x * 64;
    const float* Ab = A + rowBase * (size_t)lda;
    const float* Bb = Bw + colBase;

    float acc[4][4];
#pragma unroll
    for (int i = 0; i < 4; i++)
#pragma unroll
        for (int j = 0; j < 4; j++) acc[i][j] = 0.f;

    for (int k0 = 0; k0 < K; k0 += 16) {
#pragma unroll
        for (int i = 0; i < 4; i++) {
            int e = tid + i * 256;
            int r = e >> 4, c = e & 15;
            As[c][r] = Ab[(size_t)r * lda + (k0 + c)];
        }
#pragma unroll
        for (int i = 0; i < 4; i++) {
            int e = tid + i * 256;
            int r = e >> 6, c = e & 63;
            Bs[r][c] = Bb[(size_t)(k0 + r) * ldb + c];
        }
        __syncthreads();
#pragma unroll
        for (int k = 0; k < 16; k++) {
            float a0 = As[k][ty * 4 + 0];
            float a1 = As[k][ty * 4 + 1];
            float a2 = As[k][ty * 4 + 2];
            float a3 = As[k][ty * 4 + 3];
            float4 b = *(const float4*)&Bs[k][tx * 4];
            acc[0][0] += a0 * b.x; acc[0][1] += a0 * b.y; acc[0][2] += a0 * b.z; acc[0][3] += a0 * b.w;
            acc[1][0] += a1 * b.x; acc[1][1] += a1 * b.y; acc[1][2] += a1 * b.z; acc[1][3] += a1 * b.w;
            acc[2][0] += a2 * b.x; acc[2][1] += a2 * b.y; acc[2][2] += a2 * b.z; acc[2][3] += a2 * b.w;
            acc[3][0] += a3 * b.x; acc[3][1] += a3 * b.y; acc[3][2] += a3 * b.z; acc[3][3] += a3 * b.w;
        }
        __syncthreads();
    }

    int row0 = (int)rowBase + ty * 4;
    int col0 = colBase + tx * 4;
    const int N2 = ldc >> 1;
#pragma unroll
    for (int i = 0; i < 4; i++) {
        int row = row0 + i;
        float vv[4];
#pragma unroll
        for (int j = 0; j < 4; j++) {
            int col = col0 + j;
            float v = acc[i][j] + bias[col];
            if (flags & FLAG_PE) {
                int s = row % S_;
                int half = col >> 1;
                float div = expf((float)(2 * half) * (-9.210340371976184f / (float)D_));
                float arg = (float)s * div;
                v += (col & 1) ? cosf(arg) : sinf(arg);
            }
            if (flags & FLAG_RELU) v = fmaxf(v, 0.f);
            C[(size_t)row * ldc + col0 + j] = v;
            vv[j] = v;
        }
        Cpk[(size_t)row * N2 + (col0 >> 1)]     = pack2h(vv[0], vv[1]);
        Cpk[(size_t)row * N2 + (col0 >> 1) + 1] = pack2h(vv[2], vv[3]);
    }
}

// ---------------- attention core: scores/softmax/AV only -------------------
// Reads packed qkv [NTOK][480] u32: q cols [0,160), k [160,320), v [320,480);
// head slice h covers 32 u32 within each. Block per (b, h).
__global__ __launch_bounds__(256) void attn_core(
    const uint32_t* __restrict__ qkvPk, uint32_t* __restrict__ headsPk)
{
    __shared__ float sq[S_][DH_ + 1];
    __shared__ float sk[S_][DH_ + 1];
    __shared__ float sv[S_][DH_ + 1];
    __shared__ float sc[S_][S_ + 1];

    int bh = blockIdx.x;
    int b = bh / H_, h = bh % H_;
    int tid = threadIdx.x;
    size_t tokBase = (size_t)b * S_;
    const int Q2 = NQKV / 2;  // 480

    for (int e = tid; e < S_ * 32; e += 256) {
        int s = e >> 5, p = e & 31;
        size_t rowOff = (tokBase + s) * Q2 + h * 32 + p;
        float2 q2 = unpack2h(qkvPk[rowOff]);
        float2 k2 = unpack2h(qkvPk[rowOff + 160]);
        float2 v2 = unpack2h(qkvPk[rowOff + 320]);
        sq[s][2 * p] = q2.x; sq[s][2 * p + 1] = q2.y;
        sk[s][2 * p] = k2.x; sk[s][2 * p + 1] = k2.y;
        sv[s][2 * p] = v2.x; sv[s][2 * p + 1] = v2.y;
    }
    __syncthreads();

    for (int e = tid; e < S_ * S_; e += 256) {
        int i = e / S_, j = e % S_;
        float acc = 0.f;
#pragma unroll
        for (int d = 0; d < DH_; d++) acc += sq[i][d] * sk[j][d];
        sc[i][j] = acc * 0.125f;
    }
    __syncthreads();

    if (tid < S_) {
        float m = -1e30f;
        for (int j = 0; j < S_; j++) m = fmaxf(m, sc[tid][j]);
        float sum = 0.f;
        for (int j = 0; j < S_; j++) {
            float e2 = expf(sc[tid][j] - m);
            sc[tid][j] = e2;
            sum += e2;
        }
        float inv = 1.f / sum;
        for (int j = 0; j < S_; j++) sc[tid][j] *= inv;
    }
    __syncthreads();

    for (int e = tid; e < S_ * 32; e += 256) {
        int s = e >> 5, p = e & 31;
        int d0 = p * 2;
        float a0 = 0.f, a1 = 0.f;
#pragma unroll
        for (int j = 0; j < S_; j++) {
            a0 += sc[s][j] * sv[j][d0];
            a1 += sc[s][j] * sv[j][d0 + 1];
        }
        headsPk[(tokBase + s) * (D_ / 2) + h * 32 + p] = pack2h(a0, a1);
    }
}

// ---------------- residual add (packed fp16) + LayerNorm: warp per token ---
__global__ __launch_bounds__(256) void add_ln_warp(
    float* __restrict__ hb, const uint32_t* __restrict__ addPk,
    const float* __restrict__ gamma, const float* __restrict__ beta,
    uint32_t* __restrict__ outPk)
{
    int w = threadIdx.x >> 5, lane = threadIdx.x & 31;
    size_t tok = (size_t)blockIdx.x * 8 + w;
    size_t base = tok * D_;

    float2 v[5];
    float s = 0.f;
#pragma unroll
    for (int i = 0; i < 5; i++) {
        int d = lane * 2 + i * 64;
        float2 a = *(const float2*)&hb[base + d];
        float2 r = unpack2h(addPk[tok * (D_ / 2) + lane + i * 32]);
        v[i].x = a.x + r.x;
        v[i].y = a.y + r.y;
        s += v[i].x + v[i].y;
    }
#pragma unroll
    for (int o = 16; o; o >>= 1) s += __shfl_xor_sync(0xffffffffu, s, o);
    float mean = s * (1.f / (float)D_);

    float s2 = 0.f;
#pragma unroll
    for (int i = 0; i < 5; i++) {
        float dx = v[i].x - mean, dy = v[i].y - mean;
        s2 += dx * dx + dy * dy;
    }
#pragma unroll
    for (int o = 16; o; o >>= 1) s2 += __shfl_xor_sync(0xffffffffu, s2, o);
    float rstd = rsqrtf(s2 * (1.f / (float)D_) + 1e-5f);

#pragma unroll
    for (int i = 0; i < 5; i++) {
        int d = lane * 2 + i * 64;
        float o0 = (v[i].x - mean) * rstd * gamma[d] + beta[d];
        float o1 = (v[i].y - mean) * rstd * gamma[d + 1] + beta[d + 1];
        *(float2*)&hb[base + d] = make_float2(o0, o1);
        outPk[tok * (D_ / 2) + lane + i * 32] = pack2h(o0, o1);
    }
}

// ---------------- attention pooling + classifier (block per batch row) -----
__global__ __launch_bounds__(320) void pool_cls_kernel(
    const float* __restrict__ hb,
    const float* __restrict__ pool_W, const float* __restrict__ pool_b,
    const float* __restrict__ W1, const float* __restrict__ b1,
    const float* __restrict__ W2, const float* __restrict__ b2,
    float* __restrict__ out)
{
    __shared__ float sscore[S_];
    __shared__ float sz[D_];
    __shared__ float shid[D_ / 2];
    __shared__ float sred[10];

    int b = blockIdx.x;
    int t = threadIdx.x, warp = t >> 5, lane = t & 31;
    const float* hrow = hb + (size_t)b * S_ * D_;

    for (int s = warp; s < S_; s += 10) {
        float acc = 0.f;
        for (int d = lane; d < D_; d += 32) acc += hrow[s * D_ + d] * pool_W[d];
#pragma unroll
        for (int o = 16; o; o >>= 1) acc += __shfl_down_sync(0xffffffffu, acc, o);
        if (lane == 0) sscore[s] = acc + pool_b[0];
    }
    __syncthreads();

    if (t == 0) {
        float m = -1e30f;
        for (int s = 0; s < S_; s++) m = fmaxf(m, sscore[s]);
        float sum = 0.f;
        for (int s = 0; s < S_; s++) {
            float e = expf(sscore[s] - m);
            sscore[s] = e;
            sum += e;
        }
        float inv = 1.f / sum;
        for (int s = 0; s < S_; s++) sscore[s] *= inv;
    }
    __syncthreads();

    {
        float acc = 0.f;
        for (int s = 0; s < S_; s++) acc += sscore[s] * hrow[s * D_ + t];
        sz[t] = acc;
    }
    __syncthreads();

    if (t < D_ / 2) {
        float acc = b1[t];
        for (int d = 0; d < D_; d++) acc += sz[d] * W1[d * (D_ / 2) + t];
        shid[t] = fmaxf(acc, 0.f);
    }
    __syncthreads();

    float p = (t < D_ / 2) ? shid[t] * W2[t] : 0.f;
#pragma unroll
    for (int o = 16; o; o >>= 1) p += __shfl_down_sync(0xffffffffu, p, o);
    if (lane == 0) sred[warp] = p;
    __syncthreads();
    if (t == 0) {
        float tot = 0.f;
        for (int i = 0; i < 10; i++) tot += sred[i];
        float logit = tot + b2[0];
        out[b] = logit;
        out[B_ + b] = 1.f / (1.f + expf(-logit));
    }
}

// ---------------- host launcher -------------------------------------------
extern "C" void kernel_launch(void* const* d_in, const int* in_sizes, int n_in,
                              void* d_out, int out_size)
{
    const float* x      = (const float*)d_in[0];
    const float* in_W   = (const float*)d_in[1];
    const float* in_b   = (const float*)d_in[2];
    const float* Wq     = (const float*)d_in[3];
    const float* bq     = (const float*)d_in[4];
    const float* Wk     = (const float*)d_in[5];
    const float* bk     = (const float*)d_in[6];
    const float* Wv     = (const float*)d_in[7];
    const float* bv     = (const float*)d_in[8];
    const float* Wo     = (const float*)d_in[9];
    const float* bo     = (const float*)d_in[10];
    const float* ln1_g  = (const float*)d_in[11];
    const float* ln1_b  = (const float*)d_in[12];
    const float* W1     = (const float*)d_in[13];
    const float* b1     = (const float*)d_in[14];
    const float* W2     = (const float*)d_in[15];
    const float* b2     = (const float*)d_in[16];
    const float* ln2_g  = (const float*)d_in[17];
    const float* ln2_b  = (const float*)d_in[18];
    const float* pool_W = (const float*)d_in[19];
    const float* pool_b = (const float*)d_in[20];
    const float* cW1    = (const float*)d_in[21];
    const float* cb1    = (const float*)d_in[22];
    const float* cW2    = (const float*)d_in[23];
    const float* cb2    = (const float*)d_in[24];

    float *ph, *pbqkv;
    uint32_t *ptmpk, *pha, *phd, *pff, *pqkv, *pwo, *pw1, *pw2, *pwqkv;
    cudaGetSymbolAddress((void**)&ph, g_h);
    cudaGetSymbolAddress((void**)&ptmpk, g_tmpk);
    cudaGetSymbolAddress((void**)&pha, g_ha);
    cudaGetSymbolAddress((void**)&phd, g_hd);
    cudaGetSymbolAddress((void**)&pff, g_ff);
    cudaGetSymbolAddress((void**)&pqkv, g_qkv);
    cudaGetSymbolAddress((void**)&pwo, g_wo);
    cudaGetSymbolAddress((void**)&pw1, g_w1);
    cudaGetSymbolAddress((void**)&pw2, g_w2);
    cudaGetSymbolAddress((void**)&pwqkv, g_wqkv);
    cudaGetSymbolAddress((void**)&pbqkv, g_bqkv);

    cudaFuncSetAttribute(gemm_ps<64, 2>,
                         cudaFuncAttributeMaxDynamicSharedMemorySize, GPS_SMEM64);
    cudaFuncSetAttribute(gemm_ps<128, 4>,
                         cudaFuncAttributeMaxDynamicSharedMemorySize, GPS_SMEM128);

    const int woN = D_ * D_ / 2, w1N = D_ * DFF_ / 2, w2N = DFF_ * D_ / 2;
    const int qkN = NQKV * D_ / 2;
    const int totalConv = L_ * (woN + w1N + w2N + qkN + NQKV);
    convert_all<<<(totalConv + 255) / 256, 256>>>(Wo, W1, W2, Wq, Wk, Wv,
                                                  bq, bk, bv,
                                                  pwo, pw1, pw2, pwqkv, pbqkv);

    const dim3 gridIn(D_ / 64, NTOK / 64);
    const dim3 gridD(D_ / 64, NTOK / 128);       // BN=64, N=320
    const dim3 gridQ(NQKV / 64, NTOK / 128);     // BN=64, N=960
    const dim3 gridF(DFF_ / 128, NTOK / 128);    // BN=128, N=1280

    // input projection + bias + PE (fp32 + packed out)
    gemm64<<<gridIn, 256>>>(x, FIN_, in_W, D_, in_b, ph, pha, D_, FIN_, FLAG_PE);

    for (int l = 0; l < L_; l++) {
        // QKV via block-diagonal fp16 GEMM
        gemm_ps<64, 2><<<gridQ, 256, GPS_SMEM64>>>(pha, D_ / 2,
                                          pwqkv + (size_t)l * qkN,
                                          pbqkv + l * NQKV, pqkv, NQKV, 0);
        // attention core (scores/softmax/AV)
        attn_core<<<B_ * H_, 256>>>(pqkv, phd);
        // Wo
        gemm_ps<64, 2><<<gridD, 256, GPS_SMEM64>>>(phd, D_ / 2,
                                          pwo + (size_t)l * woN,
                                          bo + l * D_, ptmpk, D_, 0);
        add_ln_warp<<<NTOK / 8, 256>>>(ph, ptmpk, ln1_g + l * D_, ln1_b + l * D_,
                                       pha);
        // FFN1
        gemm_ps<128, 4><<<gridF, 256, GPS_SMEM128>>>(pha, D_ / 2,
                                          pw1 + (size_t)l * w1N,
                                          b1 + l * DFF_, pff, DFF_,
                                          FLAG_RELU);
        // FFN2
        gemm_ps<64, 2><<<gridD, 256, GPS_SMEM64>>>(pff, DFF_ / 2,
                                          pw2 + (size_t)l * w2N,
                                          b2 + l * D_, ptmpk, D_, 0);
        add_ln_warp<<<NTOK / 8, 256>>>(ph, ptmpk, ln2_g + l * D_, ln2_b + l * D_,
                                       pha);
    }

    pool_cls_kernel<<<B_, 320>>>(ph, pool_W, pool_b, cW1, cb1, cW2, cb2,
                                 (float*)d_out);
}